// round 1
// baseline (speedup 1.0000x reference)
#include <cuda_runtime.h>
#include <math.h>

// Problem constants
#define BB    2
#define NN    2048
#define DIM   256
#define HH    8
#define HD    32
#define HD2   64
#define ROWS  (BB*NN)          // 4096
#define SCALE 0.17677669529663689f  // 32^-0.5
#define LAMBDA_INIT 0.1f
#define EPS   1e-5f

// ---------------- scratch (static device globals; no runtime allocation) ----
__device__ float g_x  [ROWS*DIM];      // LN1 output
__device__ float g_Q  [ROWS*2*DIM];    // Q proj (4096x512)
__device__ float g_K  [ROWS*2*DIM];    // K proj
__device__ float g_V  [ROWS*DIM];      // V proj
__device__ float g_att[ROWS*DIM];      // attention output
__device__ float g_y  [ROWS*DIM];      // LN2 output
__device__ float g_h  [ROWS*4*DIM];    // MLP hidden (4096x1024)

// ---------------- LayerNorm: 1 warp per row of 256 ------------------------
__global__ void __launch_bounds__(256) ln_kernel(const float* __restrict__ in,
                                                 float* __restrict__ out,
                                                 const float* __restrict__ gamma,
                                                 const float* __restrict__ beta)
{
    int wid  = threadIdx.x >> 5;
    int lane = threadIdx.x & 31;
    int row  = blockIdx.x * 8 + wid;
    const float4* p = (const float4*)(in + (size_t)row * DIM);
    float4 v0 = p[lane*2], v1 = p[lane*2+1];

    float s = v0.x+v0.y+v0.z+v0.w + v1.x+v1.y+v1.z+v1.w;
    #pragma unroll
    for (int o = 16; o; o >>= 1) s += __shfl_xor_sync(0xffffffffu, s, o);
    float mu = s * (1.0f/DIM);

    float d0x=v0.x-mu,d0y=v0.y-mu,d0z=v0.z-mu,d0w=v0.w-mu;
    float d1x=v1.x-mu,d1y=v1.y-mu,d1z=v1.z-mu,d1w=v1.w-mu;
    float q = d0x*d0x+d0y*d0y+d0z*d0z+d0w*d0w + d1x*d1x+d1y*d1y+d1z*d1z+d1w*d1w;
    #pragma unroll
    for (int o = 16; o; o >>= 1) q += __shfl_xor_sync(0xffffffffu, q, o);
    float rstd = rsqrtf(q * (1.0f/DIM) + EPS);

    const float4* gp = (const float4*)(gamma);
    const float4* bp = (const float4*)(beta);
    float4 g0 = gp[lane*2], g1 = gp[lane*2+1];
    float4 b0 = bp[lane*2], b1 = bp[lane*2+1];

    float4 o0, o1;
    o0.x = d0x*rstd*g0.x + b0.x;  o0.y = d0y*rstd*g0.y + b0.y;
    o0.z = d0z*rstd*g0.z + b0.z;  o0.w = d0w*rstd*g0.w + b0.w;
    o1.x = d1x*rstd*g1.x + b1.x;  o1.y = d1y*rstd*g1.y + b1.y;
    o1.z = d1z*rstd*g1.z + b1.z;  o1.w = d1w*rstd*g1.w + b1.w;

    float4* q4 = (float4*)(out + (size_t)row * DIM);
    q4[lane*2]   = o0;
    q4[lane*2+1] = o1;
}

// ---------------- GEMM NT: C[M,N] = A[M,K] * B[N,K]^T  (+ epilogue) -------
// EPI: 0 = none, 1 = +res, 2 = gelu(.+bias), 3 = +bias+res
template<int EPI>
__global__ void __launch_bounds__(256) gemm_nt(const float* __restrict__ A,
                                               const float* __restrict__ Bm,
                                               const float* __restrict__ bias,
                                               const float* __restrict__ res,
                                               float* __restrict__ C,
                                               int M, int N, int K)
{
    __shared__ float As[64][17];
    __shared__ float Bs[64][17];

    int tid = threadIdx.x;
    int m0 = blockIdx.y * 64, n0 = blockIdx.x * 64;
    int lr = tid >> 2, lc = tid & 3;     // global-load row, float4 slot
    int ty = tid >> 4, tx = tid & 15;    // compute tile coords

    float c[4][4];
    #pragma unroll
    for (int i=0;i<4;i++)
        #pragma unroll
        for (int j=0;j<4;j++) c[i][j]=0.f;

    for (int k0 = 0; k0 < K; k0 += 16) {
        float4 av = *(const float4*)&A [(size_t)(m0+lr)*K + k0 + lc*4];
        float4 bv = *(const float4*)&Bm[(size_t)(n0+lr)*K + k0 + lc*4];
        __syncthreads();
        As[lr][lc*4+0]=av.x; As[lr][lc*4+1]=av.y; As[lr][lc*4+2]=av.z; As[lr][lc*4+3]=av.w;
        Bs[lr][lc*4+0]=bv.x; Bs[lr][lc*4+1]=bv.y; Bs[lr][lc*4+2]=bv.z; Bs[lr][lc*4+3]=bv.w;
        __syncthreads();
        #pragma unroll
        for (int kk = 0; kk < 16; kk++) {
            float a[4], b[4];
            #pragma unroll
            for (int i=0;i<4;i++) a[i] = As[ty*4+i][kk];
            #pragma unroll
            for (int j=0;j<4;j++) b[j] = Bs[tx*4+j][kk];
            #pragma unroll
            for (int i=0;i<4;i++)
                #pragma unroll
                for (int j=0;j<4;j++) c[i][j] = fmaf(a[i], b[j], c[i][j]);
        }
    }

    int col = n0 + tx*4;
    float4 bi = make_float4(0,0,0,0);
    if (EPI == 2 || EPI == 3) bi = *(const float4*)&bias[col];

    #pragma unroll
    for (int i = 0; i < 4; i++) {
        int row = m0 + ty*4 + i;
        float4 v = make_float4(c[i][0], c[i][1], c[i][2], c[i][3]);
        if (EPI == 2) {
            v.x += bi.x; v.y += bi.y; v.z += bi.z; v.w += bi.w;
            v.x = 0.5f*v.x*(1.0f + erff(v.x*0.7071067811865475f));
            v.y = 0.5f*v.y*(1.0f + erff(v.y*0.7071067811865475f));
            v.z = 0.5f*v.z*(1.0f + erff(v.z*0.7071067811865475f));
            v.w = 0.5f*v.w*(1.0f + erff(v.w*0.7071067811865475f));
        }
        if (EPI == 3) { v.x += bi.x; v.y += bi.y; v.z += bi.z; v.w += bi.w; }
        if (EPI == 1 || EPI == 3) {
            float4 r = *(const float4*)&res[(size_t)row*N + col];
            v.x += r.x; v.y += r.y; v.z += r.z; v.w += r.w;
        }
        *(float4*)&C[(size_t)row*N + col] = v;
    }
}

// ---------------- Differential flash attention -----------------------------
// grid: (NN/64, H, B); block 128: threads 0-63 = half0 of queries 0-63,
// threads 64-127 = half1. Each thread owns one (query, half): q[32] + acc[32].
#define BNK 64
__global__ void __launch_bounds__(128) attn_kernel(const float* __restrict__ Q,
                                                   const float* __restrict__ Kg,
                                                   const float* __restrict__ Vg,
                                                   const float* __restrict__ lq1,
                                                   const float* __restrict__ lk1,
                                                   const float* __restrict__ lq2,
                                                   const float* __restrict__ lk2,
                                                   float* __restrict__ O)
{
    __shared__ float Ks[BNK][64];
    __shared__ float Vs[BNK][32];
    __shared__ float comb[64][36];   // padded: lam*acc2/l2 handoff

    int b = blockIdx.z, h = blockIdx.y;
    int half = threadIdx.x >> 6;
    int ql   = threadIdx.x & 63;
    int qg   = blockIdx.x * 64 + ql;

    const float4* qp = (const float4*)(Q + ((size_t)(b*NN + qg))*(2*DIM) + h*HD2 + half*HD);
    float4 q4[8];
    #pragma unroll
    for (int i=0;i<8;i++) q4[i] = qp[i];

    float4 acc[8];
    #pragma unroll
    for (int i=0;i<8;i++) acc[i] = make_float4(0,0,0,0);
    float m = -1e30f, l = 0.f;

    for (int k0 = 0; k0 < NN; k0 += BNK) {
        __syncthreads();
        // load K tile: 64 keys x 64 floats (both halves)
        for (int i = threadIdx.x; i < BNK*16; i += 128) {
            int kk = i >> 4, cc = i & 15;
            ((float4*)Ks[kk])[cc] =
                *(const float4*)&Kg[((size_t)(b*NN + k0 + kk))*(2*DIM) + h*HD2 + cc*4];
        }
        // load V tile: 64 keys x 32 floats
        for (int i = threadIdx.x; i < BNK*8; i += 128) {
            int kk = i >> 3, cc = i & 7;
            ((float4*)Vs[kk])[cc] =
                *(const float4*)&Vg[((size_t)(b*NN + k0 + kk))*DIM + h*HD + cc*4];
        }
        __syncthreads();

        #pragma unroll 2
        for (int kk = 0; kk < BNK; kk++) {
            const float4* kp = (const float4*)&Ks[kk][half*HD];
            float s = 0.f;
            #pragma unroll
            for (int i=0;i<8;i++) {
                float4 kv = kp[i];
                s = fmaf(q4[i].x, kv.x, s);
                s = fmaf(q4[i].y, kv.y, s);
                s = fmaf(q4[i].z, kv.z, s);
                s = fmaf(q4[i].w, kv.w, s);
            }
            s *= SCALE;
            float mold = m;
            m = fmaxf(m, s);
            if (m != mold) {
                float corr = __expf(mold - m);
                l *= corr;
                #pragma unroll
                for (int i=0;i<8;i++) {
                    acc[i].x *= corr; acc[i].y *= corr;
                    acc[i].z *= corr; acc[i].w *= corr;
                }
            }
            float p = __expf(s - m);
            l += p;
            const float4* vp = (const float4*)Vs[kk];
            #pragma unroll
            for (int i=0;i<8;i++) {
                float4 vv = vp[i];
                acc[i].x = fmaf(p, vv.x, acc[i].x);
                acc[i].y = fmaf(p, vv.y, acc[i].y);
                acc[i].z = fmaf(p, vv.z, acc[i].z);
                acc[i].w = fmaf(p, vv.w, acc[i].w);
            }
        }
    }

    // lambda for this head
    float d1 = 0.f, d2 = 0.f;
    {
        const float* a1 = lq1 + h*HD; const float* c1 = lk1 + h*HD;
        const float* a2 = lq2 + h*HD; const float* c2 = lk2 + h*HD;
        #pragma unroll
        for (int i=0;i<HD;i++) { d1 = fmaf(a1[i], c1[i], d1); d2 = fmaf(a2[i], c2[i], d2); }
    }
    float lam = expf(d1) - expf(d2) + LAMBDA_INIT;

    __syncthreads();
    if (half == 1) {
        float sc = lam / l;
        #pragma unroll
        for (int i=0;i<8;i++) {
            float4 v = make_float4(acc[i].x*sc, acc[i].y*sc, acc[i].z*sc, acc[i].w*sc);
            *(float4*)&comb[ql][i*4] = v;
        }
    }
    __syncthreads();
    if (half == 0) {
        float inv = 1.f / l;
        float* op = O + ((size_t)(b*NN + qg))*DIM + h*HD;
        #pragma unroll
        for (int i=0;i<8;i++) {
            float4 c2 = *(const float4*)&comb[ql][i*4];
            float4 v;
            v.x = acc[i].x*inv - c2.x;
            v.y = acc[i].y*inv - c2.y;
            v.z = acc[i].z*inv - c2.z;
            v.w = acc[i].w*inv - c2.w;
            *(float4*)&op[i*4] = v;
        }
    }
}

// ---------------- launch ----------------------------------------------------
static float* symp(const void* sym) {
    void* p = nullptr;
    cudaGetSymbolAddress(&p, sym);
    return (float*)p;
}

extern "C" void kernel_launch(void* const* d_in, const int* in_sizes, int n_in,
                              void* d_out, int out_size)
{
    const float* drift = (const float*)d_in[0];
    const float* ocean = (const float*)d_in[1];
    const float* Wq    = (const float*)d_in[2];
    const float* Wk    = (const float*)d_in[3];
    const float* Wv    = (const float*)d_in[4];
    const float* Wo    = (const float*)d_in[5];
    const float* lq1   = (const float*)d_in[6];
    const float* lk1   = (const float*)d_in[7];
    const float* lq2   = (const float*)d_in[8];
    const float* lk2   = (const float*)d_in[9];
    const float* gamma = (const float*)d_in[10];
    const float* beta  = (const float*)d_in[11];
    const float* fc1w  = (const float*)d_in[12];
    const float* fc1b  = (const float*)d_in[13];
    const float* fc2w  = (const float*)d_in[14];
    const float* fc2b  = (const float*)d_in[15];
    float* out = (float*)d_out;

    float* x   = symp(g_x);
    float* Qb  = symp(g_Q);
    float* Kb  = symp(g_K);
    float* Vb  = symp(g_V);
    float* att = symp(g_att);
    float* y   = symp(g_y);
    float* hb  = symp(g_h);

    // 1) x = LN(drift)
    ln_kernel<<<ROWS/8, 256>>>(drift, x, gamma, beta);
    // 2) Q = x @ Wq^T   (4096 x 512)
    gemm_nt<0><<<dim3(512/64, ROWS/64), 256>>>(x, Wq, nullptr, nullptr, Qb, ROWS, 512, 256);
    // 3) K = ocean @ Wk^T
    gemm_nt<0><<<dim3(512/64, ROWS/64), 256>>>(ocean, Wk, nullptr, nullptr, Kb, ROWS, 512, 256);
    // 4) V = ocean @ Wv^T
    gemm_nt<0><<<dim3(256/64, ROWS/64), 256>>>(ocean, Wv, nullptr, nullptr, Vb, ROWS, 256, 256);
    // 5) differential attention
    attn_kernel<<<dim3(NN/64, HH, BB), 128>>>(Qb, Kb, Vb, lq1, lk1, lq2, lk2, att);
    // 6) drift2 = drift + att @ Wo^T  -> d_out (drift section)
    gemm_nt<1><<<dim3(256/64, ROWS/64), 256>>>(att, Wo, nullptr, drift, out, ROWS, 256, 256);
    // 7) y = LN(drift2)
    ln_kernel<<<ROWS/8, 256>>>(out, y, gamma, beta);
    // 8) h = gelu(y @ fc1^T + b1)   (4096 x 1024)
    gemm_nt<2><<<dim3(1024/64, ROWS/64), 256>>>(y, fc1w, fc1b, nullptr, hb, ROWS, 1024, 256);
    // 9) drift_out = drift2 + h @ fc2^T + b2   (in-place on d_out)
    gemm_nt<3><<<dim3(256/64, ROWS/64), 256>>>(hb, fc2w, fc2b, out, out, ROWS, 256, 1024);
    // 10) ocean pass-through
    if (out_size >= 2 * ROWS * DIM) {
        cudaMemcpyAsync(out + (size_t)ROWS*DIM, ocean,
                        (size_t)ROWS*DIM*sizeof(float), cudaMemcpyDeviceToDevice);
    }
}

// round 2
// speedup vs baseline: 1.9059x; 1.9059x over previous
#include <cuda_runtime.h>
#include <math.h>
#include <stdint.h>

// Problem constants
#define BB    2
#define NN    2048
#define DIM   256
#define HH    8
#define HD    32
#define HD2   64
#define ROWS  (BB*NN)          // 4096
#define SCALE 0.17677669529663689f  // 32^-0.5
#define LAMBDA_INIT 0.1f
#define EPS   1e-5f

// ---------------- scratch (static device globals; no runtime allocation) ----
__device__ float g_x  [ROWS*DIM];      // LN1 output
__device__ float g_Q  [ROWS*2*DIM];    // Q proj (4096x512)
__device__ float g_K  [ROWS*2*DIM];    // K proj
__device__ float g_V  [ROWS*DIM];      // V proj
__device__ float g_att[ROWS*DIM];      // attention output
__device__ float g_y  [ROWS*DIM];      // LN2 output
__device__ float g_h  [ROWS*4*DIM];    // MLP hidden (4096x1024)

// ---------------- LayerNorm: 1 warp per row of 256 ------------------------
__global__ void __launch_bounds__(256) ln_kernel(const float* __restrict__ in,
                                                 float* __restrict__ out,
                                                 const float* __restrict__ gamma,
                                                 const float* __restrict__ beta)
{
    int wid  = threadIdx.x >> 5;
    int lane = threadIdx.x & 31;
    int row  = blockIdx.x * 8 + wid;
    const float4* p = (const float4*)(in + (size_t)row * DIM);
    float4 v0 = p[lane*2], v1 = p[lane*2+1];

    float s = v0.x+v0.y+v0.z+v0.w + v1.x+v1.y+v1.z+v1.w;
    #pragma unroll
    for (int o = 16; o; o >>= 1) s += __shfl_xor_sync(0xffffffffu, s, o);
    float mu = s * (1.0f/DIM);

    float d0x=v0.x-mu,d0y=v0.y-mu,d0z=v0.z-mu,d0w=v0.w-mu;
    float d1x=v1.x-mu,d1y=v1.y-mu,d1z=v1.z-mu,d1w=v1.w-mu;
    float q = d0x*d0x+d0y*d0y+d0z*d0z+d0w*d0w + d1x*d1x+d1y*d1y+d1z*d1z+d1w*d1w;
    #pragma unroll
    for (int o = 16; o; o >>= 1) q += __shfl_xor_sync(0xffffffffu, q, o);
    float rstd = rsqrtf(q * (1.0f/DIM) + EPS);

    const float4* gp = (const float4*)(gamma);
    const float4* bp = (const float4*)(beta);
    float4 g0 = gp[lane*2], g1 = gp[lane*2+1];
    float4 b0 = bp[lane*2], b1 = bp[lane*2+1];

    float4 o0, o1;
    o0.x = d0x*rstd*g0.x + b0.x;  o0.y = d0y*rstd*g0.y + b0.y;
    o0.z = d0z*rstd*g0.z + b0.z;  o0.w = d0w*rstd*g0.w + b0.w;
    o1.x = d1x*rstd*g1.x + b1.x;  o1.y = d1y*rstd*g1.y + b1.y;
    o1.z = d1z*rstd*g1.z + b1.z;  o1.w = d1w*rstd*g1.w + b1.w;

    float4* q4 = (float4*)(out + (size_t)row * DIM);
    q4[lane*2]   = o0;
    q4[lane*2+1] = o1;
}

// ---------------- GEMM NT: C[M,N] = A[M,K] * B[N,K]^T  (+ epilogue) -------
// EPI: 0 = none, 1 = +res, 2 = gelu(.+bias), 3 = +bias+res
template<int EPI>
__global__ void __launch_bounds__(256) gemm_nt(const float* __restrict__ A,
                                               const float* __restrict__ Bm,
                                               const float* __restrict__ bias,
                                               const float* __restrict__ res,
                                               float* __restrict__ C,
                                               int M, int N, int K)
{
    __shared__ float As[64][17];
    __shared__ float Bs[64][17];

    int tid = threadIdx.x;
    int m0 = blockIdx.y * 64, n0 = blockIdx.x * 64;
    int lr = tid >> 2, lc = tid & 3;     // global-load row, float4 slot
    int ty = tid >> 4, tx = tid & 15;    // compute tile coords

    float c[4][4];
    #pragma unroll
    for (int i=0;i<4;i++)
        #pragma unroll
        for (int j=0;j<4;j++) c[i][j]=0.f;

    for (int k0 = 0; k0 < K; k0 += 16) {
        float4 av = *(const float4*)&A [(size_t)(m0+lr)*K + k0 + lc*4];
        float4 bv = *(const float4*)&Bm[(size_t)(n0+lr)*K + k0 + lc*4];
        __syncthreads();
        As[lr][lc*4+0]=av.x; As[lr][lc*4+1]=av.y; As[lr][lc*4+2]=av.z; As[lr][lc*4+3]=av.w;
        Bs[lr][lc*4+0]=bv.x; Bs[lr][lc*4+1]=bv.y; Bs[lr][lc*4+2]=bv.z; Bs[lr][lc*4+3]=bv.w;
        __syncthreads();
        #pragma unroll
        for (int kk = 0; kk < 16; kk++) {
            float a[4], b[4];
            #pragma unroll
            for (int i=0;i<4;i++) a[i] = As[ty*4+i][kk];
            #pragma unroll
            for (int j=0;j<4;j++) b[j] = Bs[tx*4+j][kk];
            #pragma unroll
            for (int i=0;i<4;i++)
                #pragma unroll
                for (int j=0;j<4;j++) c[i][j] = fmaf(a[i], b[j], c[i][j]);
        }
    }

    int col = n0 + tx*4;
    float4 bi = make_float4(0,0,0,0);
    if (EPI == 2 || EPI == 3) bi = *(const float4*)&bias[col];

    #pragma unroll
    for (int i = 0; i < 4; i++) {
        int row = m0 + ty*4 + i;
        float4 v = make_float4(c[i][0], c[i][1], c[i][2], c[i][3]);
        if (EPI == 2) {
            v.x += bi.x; v.y += bi.y; v.z += bi.z; v.w += bi.w;
            v.x = 0.5f*v.x*(1.0f + erff(v.x*0.7071067811865475f));
            v.y = 0.5f*v.y*(1.0f + erff(v.y*0.7071067811865475f));
            v.z = 0.5f*v.z*(1.0f + erff(v.z*0.7071067811865475f));
            v.w = 0.5f*v.w*(1.0f + erff(v.w*0.7071067811865475f));
        }
        if (EPI == 3) { v.x += bi.x; v.y += bi.y; v.z += bi.z; v.w += bi.w; }
        if (EPI == 1 || EPI == 3) {
            float4 r = *(const float4*)&res[(size_t)row*N + col];
            v.x += r.x; v.y += r.y; v.z += r.z; v.w += r.w;
        }
        *(float4*)&C[(size_t)row*N + col] = v;
    }
}

// ---------------- tf32 helpers ---------------------------------------------
__device__ __forceinline__ uint32_t f2tf(float x) {
    uint32_t u;
    asm("cvt.rna.tf32.f32 %0, %1;" : "=r"(u) : "f"(x));
    return u;
}
__device__ __forceinline__ float f2tff(float x) {
    return __uint_as_float(f2tf(x));
}
__device__ __forceinline__ void mma_tf32(float* d, const uint32_t* a, const uint32_t* b) {
    asm volatile("mma.sync.aligned.m16n8k8.row.col.f32.tf32.tf32.f32 "
                 "{%0,%1,%2,%3},{%4,%5,%6,%7},{%8,%9},{%0,%1,%2,%3};"
                 : "+f"(d[0]), "+f"(d[1]), "+f"(d[2]), "+f"(d[3])
                 : "r"(a[0]), "r"(a[1]), "r"(a[2]), "r"(a[3]),
                   "r"(b[0]), "r"(b[1]));
}

// ---------------- Differential attention via tf32 tensor cores ------------
// grid (NN/64, H, B), 128 threads (4 warps x 16 query rows).
// No online-max: scores are O(0.1) std, exp cannot overflow -> plain
// exp-accumulate, normalize once at the end.
#define KSTRIDE 68
#define VSTRIDE 40
__global__ void __launch_bounds__(128) attn_tc(const float* __restrict__ Q,
                                               const float* __restrict__ Kg,
                                               const float* __restrict__ Vg,
                                               const float* __restrict__ lq1,
                                               const float* __restrict__ lk1,
                                               const float* __restrict__ lq2,
                                               const float* __restrict__ lk2,
                                               float* __restrict__ O)
{
    __shared__ float Ks[64][KSTRIDE];  // 64 keys x 64 dims (both halves), tf32
    __shared__ float Vs[64][VSTRIDE];  // 64 keys x 32 dims, tf32
    __shared__ float Ps[64][KSTRIDE];  // P staging, per-warp 16-row regions

    const int b    = blockIdx.z;
    const int h    = blockIdx.y;
    const int warp = threadIdx.x >> 5;
    const int lane = threadIdx.x & 31;
    const int gr   = lane >> 2;   // group row 0..7
    const int gc   = lane & 3;    // thread-in-group 0..3
    const int qw   = blockIdx.x * 64 + warp * 16;   // warp's query base

    // lambda for this head (all threads compute; tiny)
    float d1 = 0.f, d2 = 0.f;
    #pragma unroll
    for (int i = 0; i < HD; i++) {
        d1 = fmaf(lq1[h*HD+i], lk1[h*HD+i], d1);
        d2 = fmaf(lq2[h*HD+i], lk2[h*HD+i], d2);
    }
    const float lam = expf(d1) - expf(d2) + LAMBDA_INIT;

    // Q fragments (SCALE folded in), tf32
    uint32_t qf[2][4][4];
    {
        const size_t rstride = 2*DIM;  // 512
        const float* qb = Q + ((size_t)(b*NN + qw + gr))*rstride + h*HD2;
        #pragma unroll
        for (int half = 0; half < 2; half++) {
            #pragma unroll
            for (int ks = 0; ks < 4; ks++) {
                const float* p = qb + half*HD + ks*8 + gc;
                qf[half][ks][0] = f2tf(p[0]          * SCALE);
                qf[half][ks][1] = f2tf(p[8*rstride]  * SCALE);
                qf[half][ks][2] = f2tf(p[4]          * SCALE);
                qf[half][ks][3] = f2tf(p[8*rstride+4]* SCALE);
            }
        }
    }

    float o[2][4][4];
    #pragma unroll
    for (int hf=0; hf<2; hf++)
        #pragma unroll
        for (int n=0; n<4; n++)
            #pragma unroll
            for (int i=0; i<4; i++) o[hf][n][i] = 0.f;
    float lsum[2][2] = {{0.f,0.f},{0.f,0.f}};  // [half][row r / r+8]

    for (int k0 = 0; k0 < NN; k0 += 64) {
        __syncthreads();
        // K tile (both halves) -> tf32 in SMEM
        #pragma unroll
        for (int it = 0; it < 8; it++) {
            int i = threadIdx.x + it*128;
            int row = i >> 4, c4 = i & 15;
            float4 v = *(const float4*)&Kg[((size_t)(b*NN + k0 + row))*(2*DIM) + h*HD2 + c4*4];
            float4 w = make_float4(f2tff(v.x), f2tff(v.y), f2tff(v.z), f2tff(v.w));
            *(float4*)&Ks[row][c4*4] = w;
        }
        // V tile -> tf32 in SMEM
        #pragma unroll
        for (int it = 0; it < 4; it++) {
            int i = threadIdx.x + it*128;
            int row = i >> 3, c4 = i & 7;
            float4 v = *(const float4*)&Vg[((size_t)(b*NN + k0 + row))*DIM + h*HD + c4*4];
            float4 w = make_float4(f2tff(v.x), f2tff(v.y), f2tff(v.z), f2tff(v.w));
            *(float4*)&Vs[row][c4*4] = w;
        }
        __syncthreads();

        #pragma unroll
        for (int half = 0; half < 2; half++) {
            // S = Q_half @ K_half^T for this warp's 16 rows x 64 keys
            float s[8][4];
            #pragma unroll
            for (int n=0;n<8;n++)
                #pragma unroll
                for (int i=0;i<4;i++) s[n][i] = 0.f;

            #pragma unroll
            for (int n = 0; n < 8; n++) {
                int key = n*8 + gr;
                #pragma unroll
                for (int ks = 0; ks < 4; ks++) {
                    uint32_t bb[2];
                    int d = half*HD + ks*8 + gc;
                    bb[0] = __float_as_uint(Ks[key][d]);
                    bb[1] = __float_as_uint(Ks[key][d+4]);
                    mma_tf32(s[n], qf[half][ks], bb);
                }
            }
            // P = exp(S), row sums, stage to SMEM (tf32)
            #pragma unroll
            for (int n = 0; n < 8; n++) {
                float p0 = __expf(s[n][0]);
                float p1 = __expf(s[n][1]);
                float p2 = __expf(s[n][2]);
                float p3 = __expf(s[n][3]);
                lsum[half][0] += p0 + p1;
                lsum[half][1] += p2 + p3;
                float2 lo = make_float2(f2tff(p0), f2tff(p1));
                float2 hi = make_float2(f2tff(p2), f2tff(p3));
                *(float2*)&Ps[warp*16 + gr    ][n*8 + 2*gc] = lo;
                *(float2*)&Ps[warp*16 + gr + 8][n*8 + 2*gc] = hi;
            }
            __syncwarp();
            // O_half += P @ V
            #pragma unroll
            for (int ks = 0; ks < 8; ks++) {
                uint32_t af[4];
                af[0] = __float_as_uint(Ps[warp*16 + gr    ][ks*8 + gc    ]);
                af[1] = __float_as_uint(Ps[warp*16 + gr + 8][ks*8 + gc    ]);
                af[2] = __float_as_uint(Ps[warp*16 + gr    ][ks*8 + gc + 4]);
                af[3] = __float_as_uint(Ps[warp*16 + gr + 8][ks*8 + gc + 4]);
                #pragma unroll
                for (int n = 0; n < 4; n++) {
                    uint32_t bb[2];
                    bb[0] = __float_as_uint(Vs[ks*8 + gc    ][n*8 + gr]);
                    bb[1] = __float_as_uint(Vs[ks*8 + gc + 4][n*8 + gr]);
                    mma_tf32(o[half][n], af, bb);
                }
            }
            __syncwarp();   // before next half overwrites Ps
        }
    }

    // reduce row sums within each 4-thread group (all 4 get the total)
    #pragma unroll
    for (int hf = 0; hf < 2; hf++) {
        #pragma unroll
        for (int r2 = 0; r2 < 2; r2++) {
            float v = lsum[hf][r2];
            v += __shfl_xor_sync(0xffffffffu, v, 1);
            v += __shfl_xor_sync(0xffffffffu, v, 2);
            lsum[hf][r2] = v;
        }
    }
    const float i1A = 1.f / lsum[0][0];
    const float i1B = 1.f / lsum[0][1];
    const float s2A = lam / lsum[1][0];
    const float s2B = lam / lsum[1][1];

    float* outA = O + ((size_t)(b*NN + qw + gr    ))*DIM + h*HD;
    float* outB = O + ((size_t)(b*NN + qw + gr + 8))*DIM + h*HD;
    #pragma unroll
    for (int n = 0; n < 4; n++) {
        float2 vA = make_float2(o[0][n][0]*i1A - o[1][n][0]*s2A,
                                o[0][n][1]*i1A - o[1][n][1]*s2A);
        float2 vB = make_float2(o[0][n][2]*i1B - o[1][n][2]*s2B,
                                o[0][n][3]*i1B - o[1][n][3]*s2B);
        *(float2*)&outA[n*8 + 2*gc] = vA;
        *(float2*)&outB[n*8 + 2*gc] = vB;
    }
}

// ---------------- launch ----------------------------------------------------
static float* symp(const void* sym) {
    void* p = nullptr;
    cudaGetSymbolAddress(&p, sym);
    return (float*)p;
}

extern "C" void kernel_launch(void* const* d_in, const int* in_sizes, int n_in,
                              void* d_out, int out_size)
{
    const float* drift = (const float*)d_in[0];
    const float* ocean = (const float*)d_in[1];
    const float* Wq    = (const float*)d_in[2];
    const float* Wk    = (const float*)d_in[3];
    const float* Wv    = (const float*)d_in[4];
    const float* Wo    = (const float*)d_in[5];
    const float* lq1   = (const float*)d_in[6];
    const float* lk1   = (const float*)d_in[7];
    const float* lq2   = (const float*)d_in[8];
    const float* lk2   = (const float*)d_in[9];
    const float* gamma = (const float*)d_in[10];
    const float* beta  = (const float*)d_in[11];
    const float* fc1w  = (const float*)d_in[12];
    const float* fc1b  = (const float*)d_in[13];
    const float* fc2w  = (const float*)d_in[14];
    const float* fc2b  = (const float*)d_in[15];
    float* out = (float*)d_out;

    float* x   = symp(g_x);
    float* Qb  = symp(g_Q);
    float* Kb  = symp(g_K);
    float* Vb  = symp(g_V);
    float* att = symp(g_att);
    float* y   = symp(g_y);
    float* hb  = symp(g_h);

    // 1) x = LN(drift)
    ln_kernel<<<ROWS/8, 256>>>(drift, x, gamma, beta);
    // 2) Q = x @ Wq^T   (4096 x 512)
    gemm_nt<0><<<dim3(512/64, ROWS/64), 256>>>(x, Wq, nullptr, nullptr, Qb, ROWS, 512, 256);
    // 3) K = ocean @ Wk^T
    gemm_nt<0><<<dim3(512/64, ROWS/64), 256>>>(ocean, Wk, nullptr, nullptr, Kb, ROWS, 512, 256);
    // 4) V = ocean @ Wv^T
    gemm_nt<0><<<dim3(256/64, ROWS/64), 256>>>(ocean, Wv, nullptr, nullptr, Vb, ROWS, 256, 256);
    // 5) differential attention (tf32 tensor cores)
    attn_tc<<<dim3(NN/64, HH, BB), 128>>>(Qb, Kb, Vb, lq1, lk1, lq2, lk2, att);
    // 6) drift2 = drift + att @ Wo^T  -> d_out (drift section)
    gemm_nt<1><<<dim3(256/64, ROWS/64), 256>>>(att, Wo, nullptr, drift, out, ROWS, 256, 256);
    // 7) y = LN(drift2)
    ln_kernel<<<ROWS/8, 256>>>(out, y, gamma, beta);
    // 8) h = gelu(y @ fc1^T + b1)   (4096 x 1024)
    gemm_nt<2><<<dim3(1024/64, ROWS/64), 256>>>(y, fc1w, fc1b, nullptr, hb, ROWS, 1024, 256);
    // 9) drift_out = drift2 + h @ fc2^T + b2   (in-place on d_out)
    gemm_nt<3><<<dim3(256/64, ROWS/64), 256>>>(hb, fc2w, fc2b, out, out, ROWS, 256, 1024);
    // 10) ocean pass-through
    if (out_size >= 2 * ROWS * DIM) {
        cudaMemcpyAsync(out + (size_t)ROWS*DIM, ocean,
                        (size_t)ROWS*DIM*sizeof(float), cudaMemcpyDeviceToDevice);
    }
}

// round 3
// speedup vs baseline: 2.6675x; 1.3996x over previous
#include <cuda_runtime.h>
#include <math.h>
#include <stdint.h>

// Problem constants
#define BB    2
#define NN    2048
#define DIM   256
#define HH    8
#define HD    32
#define HD2   64
#define ROWS  (BB*NN)          // 4096
#define SCALE 0.17677669529663689f  // 32^-0.5
#define LAMBDA_INIT 0.1f
#define EPS   1e-5f

// ---------------- scratch (static device globals; no runtime allocation) ----
__device__ float g_x  [ROWS*DIM];      // LN1 output
__device__ float g_Q  [ROWS*2*DIM];    // Q proj (4096x512)
__device__ float g_K  [ROWS*2*DIM];    // K proj
__device__ float g_V  [ROWS*DIM];      // V proj
__device__ float g_att[ROWS*DIM];      // attention output
__device__ float g_y  [ROWS*DIM];      // LN2 output
__device__ float g_h  [ROWS*4*DIM];    // MLP hidden (4096x1024)

// ---------------- tf32 helpers ---------------------------------------------
__device__ __forceinline__ uint32_t f2tf(float x) {
    uint32_t u;
    asm("cvt.rna.tf32.f32 %0, %1;" : "=r"(u) : "f"(x));
    return u;
}
__device__ __forceinline__ float f2tff(float x) {
    return __uint_as_float(f2tf(x));
}
__device__ __forceinline__ void mma_tf32(float* d, const uint32_t* a, const uint32_t* b) {
    asm volatile("mma.sync.aligned.m16n8k8.row.col.f32.tf32.tf32.f32 "
                 "{%0,%1,%2,%3},{%4,%5,%6,%7},{%8,%9},{%0,%1,%2,%3};"
                 : "+f"(d[0]), "+f"(d[1]), "+f"(d[2]), "+f"(d[3])
                 : "r"(a[0]), "r"(a[1]), "r"(a[2]), "r"(a[3]),
                   "r"(b[0]), "r"(b[1]));
}

// ---------------- LayerNorm: 1 warp per row of 256 ------------------------
__global__ void __launch_bounds__(256) ln_kernel(const float* __restrict__ in,
                                                 float* __restrict__ out,
                                                 const float* __restrict__ gamma,
                                                 const float* __restrict__ beta)
{
    int wid  = threadIdx.x >> 5;
    int lane = threadIdx.x & 31;
    int row  = blockIdx.x * 8 + wid;
    const float4* p = (const float4*)(in + (size_t)row * DIM);
    float4 v0 = p[lane*2], v1 = p[lane*2+1];

    float s = v0.x+v0.y+v0.z+v0.w + v1.x+v1.y+v1.z+v1.w;
    #pragma unroll
    for (int o = 16; o; o >>= 1) s += __shfl_xor_sync(0xffffffffu, s, o);
    float mu = s * (1.0f/DIM);

    float d0x=v0.x-mu,d0y=v0.y-mu,d0z=v0.z-mu,d0w=v0.w-mu;
    float d1x=v1.x-mu,d1y=v1.y-mu,d1z=v1.z-mu,d1w=v1.w-mu;
    float q = d0x*d0x+d0y*d0y+d0z*d0z+d0w*d0w + d1x*d1x+d1y*d1y+d1z*d1z+d1w*d1w;
    #pragma unroll
    for (int o = 16; o; o >>= 1) q += __shfl_xor_sync(0xffffffffu, q, o);
    float rstd = rsqrtf(q * (1.0f/DIM) + EPS);

    const float4* gp = (const float4*)(gamma);
    const float4* bp = (const float4*)(beta);
    float4 g0 = gp[lane*2], g1 = gp[lane*2+1];
    float4 b0 = bp[lane*2], b1 = bp[lane*2+1];

    float4 o0, o1;
    o0.x = d0x*rstd*g0.x + b0.x;  o0.y = d0y*rstd*g0.y + b0.y;
    o0.z = d0z*rstd*g0.z + b0.z;  o0.w = d0w*rstd*g0.w + b0.w;
    o1.x = d1x*rstd*g1.x + b1.x;  o1.y = d1y*rstd*g1.y + b1.y;
    o1.z = d1z*rstd*g1.z + b1.z;  o1.w = d1w*rstd*g1.w + b1.w;

    float4* q4 = (float4*)(out + (size_t)row * DIM);
    q4[lane*2]   = o0;
    q4[lane*2+1] = o1;
}

// ---------------- tf32 tensor-core GEMM NT ---------------------------------
// C[M,N] = A[M,K] * B[N,K]^T (+ epilogue). Tile 128x64, K-step 32.
// 256 threads = 8 warps as 4(M) x 2(N); each warp 32x32 (2x4 m16n8k8 tiles).
// EPI: 0 = none, 1 = +res, 2 = gelu(.+bias), 3 = +bias+res
template<int EPI>
__global__ void __launch_bounds__(256) gemm_tc(const float* __restrict__ A,
                                               const float* __restrict__ Bm,
                                               const float* __restrict__ bias,
                                               const float* __restrict__ res,
                                               float* __restrict__ C,
                                               int M, int N, int K)
{
    __shared__ float As[128][36];   // stride ≡ 4 mod 32 -> conflict-free frags
    __shared__ float Bs[64][36];

    const int tid  = threadIdx.x;
    const int m0   = blockIdx.y * 128;
    const int n0   = blockIdx.x * 64;
    const int lane = tid & 31;
    const int warp = tid >> 5;
    const int gr   = lane >> 2;      // 0..7
    const int gc   = lane & 3;       // 0..3
    const int wm   = warp >> 1;      // 0..3
    const int wn   = warp & 1;       // 0..1

    float c[2][4][4];
    #pragma unroll
    for (int mi=0; mi<2; mi++)
        #pragma unroll
        for (int ni=0; ni<4; ni++)
            #pragma unroll
            for (int i=0; i<4; i++) c[mi][ni][i] = 0.f;

    for (int k0 = 0; k0 < K; k0 += 32) {
        // stage global loads in regs before sync
        float4 a4[4], b4[2];
        #pragma unroll
        for (int it = 0; it < 4; it++) {
            int s = tid + it*256;                 // 0..1023
            a4[it] = *(const float4*)&A[(size_t)(m0 + (s>>3))*K + k0 + (s&7)*4];
        }
        #pragma unroll
        for (int it = 0; it < 2; it++) {
            int s = tid + it*256;                 // 0..511
            b4[it] = *(const float4*)&Bm[(size_t)(n0 + (s>>3))*K + k0 + (s&7)*4];
        }
        __syncthreads();
        #pragma unroll
        for (int it = 0; it < 4; it++) {
            int s = tid + it*256;
            float* p = &As[s>>3][(s&7)*4];
            p[0]=f2tff(a4[it].x); p[1]=f2tff(a4[it].y);
            p[2]=f2tff(a4[it].z); p[3]=f2tff(a4[it].w);
        }
        #pragma unroll
        for (int it = 0; it < 2; it++) {
            int s = tid + it*256;
            float* p = &Bs[s>>3][(s&7)*4];
            p[0]=f2tff(b4[it].x); p[1]=f2tff(b4[it].y);
            p[2]=f2tff(b4[it].z); p[3]=f2tff(b4[it].w);
        }
        __syncthreads();

        #pragma unroll
        for (int ks = 0; ks < 4; ks++) {
            const int k = ks*8;
            uint32_t af[2][4], bf[4][2];
            #pragma unroll
            for (int mi = 0; mi < 2; mi++) {
                int r = wm*32 + mi*16 + gr;
                af[mi][0] = __float_as_uint(As[r  ][k+gc  ]);
                af[mi][1] = __float_as_uint(As[r+8][k+gc  ]);
                af[mi][2] = __float_as_uint(As[r  ][k+gc+4]);
                af[mi][3] = __float_as_uint(As[r+8][k+gc+4]);
            }
            #pragma unroll
            for (int ni = 0; ni < 4; ni++) {
                int r = wn*32 + ni*8 + gr;
                bf[ni][0] = __float_as_uint(Bs[r][k+gc  ]);
                bf[ni][1] = __float_as_uint(Bs[r][k+gc+4]);
            }
            #pragma unroll
            for (int mi = 0; mi < 2; mi++)
                #pragma unroll
                for (int ni = 0; ni < 4; ni++)
                    mma_tf32(c[mi][ni], af[mi], bf[ni]);
        }
    }

    // epilogue
    #pragma unroll
    for (int ni = 0; ni < 4; ni++) {
        const int col = n0 + wn*32 + ni*8 + 2*gc;
        float2 bi = make_float2(0.f, 0.f);
        if (EPI == 2 || EPI == 3) bi = *(const float2*)&bias[col];
        #pragma unroll
        for (int mi = 0; mi < 2; mi++) {
            const int row0 = m0 + wm*32 + mi*16 + gr;
            #pragma unroll
            for (int half = 0; half < 2; half++) {
                const int row = row0 + half*8;
                float2 v = make_float2(c[mi][ni][half*2], c[mi][ni][half*2+1]);
                if (EPI == 2) {
                    v.x += bi.x; v.y += bi.y;
                    v.x = 0.5f*v.x*(1.0f + erff(v.x*0.7071067811865475f));
                    v.y = 0.5f*v.y*(1.0f + erff(v.y*0.7071067811865475f));
                }
                if (EPI == 3) { v.x += bi.x; v.y += bi.y; }
                if (EPI == 1 || EPI == 3) {
                    float2 r = *(const float2*)&res[(size_t)row*N + col];
                    v.x += r.x; v.y += r.y;
                }
                *(float2*)&C[(size_t)row*N + col] = v;
            }
        }
    }
}

// ---------------- Differential attention via tf32 tensor cores ------------
#define KSTRIDE 68
#define VSTRIDE 40
__global__ void __launch_bounds__(128) attn_tc(const float* __restrict__ Q,
                                               const float* __restrict__ Kg,
                                               const float* __restrict__ Vg,
                                               const float* __restrict__ lq1,
                                               const float* __restrict__ lk1,
                                               const float* __restrict__ lq2,
                                               const float* __restrict__ lk2,
                                               float* __restrict__ O)
{
    __shared__ float Ks[64][KSTRIDE];  // 64 keys x 64 dims (both halves), tf32
    __shared__ float Vs[64][VSTRIDE];  // 64 keys x 32 dims, tf32
    __shared__ float Ps[64][KSTRIDE];  // P staging, per-warp 16-row regions

    const int b    = blockIdx.z;
    const int h    = blockIdx.y;
    const int warp = threadIdx.x >> 5;
    const int lane = threadIdx.x & 31;
    const int gr   = lane >> 2;
    const int gc   = lane & 3;
    const int qw   = blockIdx.x * 64 + warp * 16;

    float d1 = 0.f, d2 = 0.f;
    #pragma unroll
    for (int i = 0; i < HD; i++) {
        d1 = fmaf(lq1[h*HD+i], lk1[h*HD+i], d1);
        d2 = fmaf(lq2[h*HD+i], lk2[h*HD+i], d2);
    }
    const float lam = expf(d1) - expf(d2) + LAMBDA_INIT;

    uint32_t qf[2][4][4];
    {
        const size_t rstride = 2*DIM;
        const float* qb = Q + ((size_t)(b*NN + qw + gr))*rstride + h*HD2;
        #pragma unroll
        for (int half = 0; half < 2; half++) {
            #pragma unroll
            for (int ks = 0; ks < 4; ks++) {
                const float* p = qb + half*HD + ks*8 + gc;
                qf[half][ks][0] = f2tf(p[0]          * SCALE);
                qf[half][ks][1] = f2tf(p[8*rstride]  * SCALE);
                qf[half][ks][2] = f2tf(p[4]          * SCALE);
                qf[half][ks][3] = f2tf(p[8*rstride+4]* SCALE);
            }
        }
    }

    float o[2][4][4];
    #pragma unroll
    for (int hf=0; hf<2; hf++)
        #pragma unroll
        for (int n=0; n<4; n++)
            #pragma unroll
            for (int i=0; i<4; i++) o[hf][n][i] = 0.f;
    float lsum[2][2] = {{0.f,0.f},{0.f,0.f}};

    for (int k0 = 0; k0 < NN; k0 += 64) {
        __syncthreads();
        #pragma unroll
        for (int it = 0; it < 8; it++) {
            int i = threadIdx.x + it*128;
            int row = i >> 4, c4 = i & 15;
            float4 v = *(const float4*)&Kg[((size_t)(b*NN + k0 + row))*(2*DIM) + h*HD2 + c4*4];
            float4 w = make_float4(f2tff(v.x), f2tff(v.y), f2tff(v.z), f2tff(v.w));
            *(float4*)&Ks[row][c4*4] = w;
        }
        #pragma unroll
        for (int it = 0; it < 4; it++) {
            int i = threadIdx.x + it*128;
            int row = i >> 3, c4 = i & 7;
            float4 v = *(const float4*)&Vg[((size_t)(b*NN + k0 + row))*DIM + h*HD + c4*4];
            float4 w = make_float4(f2tff(v.x), f2tff(v.y), f2tff(v.z), f2tff(v.w));
            *(float4*)&Vs[row][c4*4] = w;
        }
        __syncthreads();

        #pragma unroll
        for (int half = 0; half < 2; half++) {
            float s[8][4];
            #pragma unroll
            for (int n=0;n<8;n++)
                #pragma unroll
                for (int i=0;i<4;i++) s[n][i] = 0.f;

            #pragma unroll
            for (int n = 0; n < 8; n++) {
                int key = n*8 + gr;
                #pragma unroll
                for (int ks = 0; ks < 4; ks++) {
                    uint32_t bb[2];
                    int d = half*HD + ks*8 + gc;
                    bb[0] = __float_as_uint(Ks[key][d]);
                    bb[1] = __float_as_uint(Ks[key][d+4]);
                    mma_tf32(s[n], qf[half][ks], bb);
                }
            }
            #pragma unroll
            for (int n = 0; n < 8; n++) {
                float p0 = __expf(s[n][0]);
                float p1 = __expf(s[n][1]);
                float p2 = __expf(s[n][2]);
                float p3 = __expf(s[n][3]);
                lsum[half][0] += p0 + p1;
                lsum[half][1] += p2 + p3;
                float2 lo = make_float2(f2tff(p0), f2tff(p1));
                float2 hi = make_float2(f2tff(p2), f2tff(p3));
                *(float2*)&Ps[warp*16 + gr    ][n*8 + 2*gc] = lo;
                *(float2*)&Ps[warp*16 + gr + 8][n*8 + 2*gc] = hi;
            }
            __syncwarp();
            #pragma unroll
            for (int ks = 0; ks < 8; ks++) {
                uint32_t af[4];
                af[0] = __float_as_uint(Ps[warp*16 + gr    ][ks*8 + gc    ]);
                af[1] = __float_as_uint(Ps[warp*16 + gr + 8][ks*8 + gc    ]);
                af[2] = __float_as_uint(Ps[warp*16 + gr    ][ks*8 + gc + 4]);
                af[3] = __float_as_uint(Ps[warp*16 + gr + 8][ks*8 + gc + 4]);
                #pragma unroll
                for (int n = 0; n < 4; n++) {
                    uint32_t bb[2];
                    bb[0] = __float_as_uint(Vs[ks*8 + gc    ][n*8 + gr]);
                    bb[1] = __float_as_uint(Vs[ks*8 + gc + 4][n*8 + gr]);
                    mma_tf32(o[half][n], af, bb);
                }
            }
            __syncwarp();
        }
    }

    #pragma unroll
    for (int hf = 0; hf < 2; hf++) {
        #pragma unroll
        for (int r2 = 0; r2 < 2; r2++) {
            float v = lsum[hf][r2];
            v += __shfl_xor_sync(0xffffffffu, v, 1);
            v += __shfl_xor_sync(0xffffffffu, v, 2);
            lsum[hf][r2] = v;
        }
    }
    const float i1A = 1.f / lsum[0][0];
    const float i1B = 1.f / lsum[0][1];
    const float s2A = lam / lsum[1][0];
    const float s2B = lam / lsum[1][1];

    float* outA = O + ((size_t)(b*NN + qw + gr    ))*DIM + h*HD;
    float* outB = O + ((size_t)(b*NN + qw + gr + 8))*DIM + h*HD;
    #pragma unroll
    for (int n = 0; n < 4; n++) {
        float2 vA = make_float2(o[0][n][0]*i1A - o[1][n][0]*s2A,
                                o[0][n][1]*i1A - o[1][n][1]*s2A);
        float2 vB = make_float2(o[0][n][2]*i1B - o[1][n][2]*s2B,
                                o[0][n][3]*i1B - o[1][n][3]*s2B);
        *(float2*)&outA[n*8 + 2*gc] = vA;
        *(float2*)&outB[n*8 + 2*gc] = vB;
    }
}

// ---------------- launch ----------------------------------------------------
static float* symp(const void* sym) {
    void* p = nullptr;
    cudaGetSymbolAddress(&p, sym);
    return (float*)p;
}

extern "C" void kernel_launch(void* const* d_in, const int* in_sizes, int n_in,
                              void* d_out, int out_size)
{
    const float* drift = (const float*)d_in[0];
    const float* ocean = (const float*)d_in[1];
    const float* Wq    = (const float*)d_in[2];
    const float* Wk    = (const float*)d_in[3];
    const float* Wv    = (const float*)d_in[4];
    const float* Wo    = (const float*)d_in[5];
    const float* lq1   = (const float*)d_in[6];
    const float* lk1   = (const float*)d_in[7];
    const float* lq2   = (const float*)d_in[8];
    const float* lk2   = (const float*)d_in[9];
    const float* gamma = (const float*)d_in[10];
    const float* beta  = (const float*)d_in[11];
    const float* fc1w  = (const float*)d_in[12];
    const float* fc1b  = (const float*)d_in[13];
    const float* fc2w  = (const float*)d_in[14];
    const float* fc2b  = (const float*)d_in[15];
    float* out = (float*)d_out;

    float* x   = symp(g_x);
    float* Qb  = symp(g_Q);
    float* Kb  = symp(g_K);
    float* Vb  = symp(g_V);
    float* att = symp(g_att);
    float* y   = symp(g_y);
    float* hb  = symp(g_h);

    // 1) x = LN(drift)
    ln_kernel<<<ROWS/8, 256>>>(drift, x, gamma, beta);
    // 2) Q = x @ Wq^T   (4096 x 512)
    gemm_tc<0><<<dim3(512/64, ROWS/128), 256>>>(x, Wq, nullptr, nullptr, Qb, ROWS, 512, 256);
    // 3) K = ocean @ Wk^T
    gemm_tc<0><<<dim3(512/64, ROWS/128), 256>>>(ocean, Wk, nullptr, nullptr, Kb, ROWS, 512, 256);
    // 4) V = ocean @ Wv^T
    gemm_tc<0><<<dim3(256/64, ROWS/128), 256>>>(ocean, Wv, nullptr, nullptr, Vb, ROWS, 256, 256);
    // 5) differential attention (tf32 tensor cores)
    attn_tc<<<dim3(NN/64, HH, BB), 128>>>(Qb, Kb, Vb, lq1, lk1, lq2, lk2, att);
    // 6) drift2 = drift + att @ Wo^T  -> d_out (drift section)
    gemm_tc<1><<<dim3(256/64, ROWS/128), 256>>>(att, Wo, nullptr, drift, out, ROWS, 256, 256);
    // 7) y = LN(drift2)
    ln_kernel<<<ROWS/8, 256>>>(out, y, gamma, beta);
    // 8) h = gelu(y @ fc1^T + b1)   (4096 x 1024)
    gemm_tc<2><<<dim3(1024/64, ROWS/128), 256>>>(y, fc1w, fc1b, nullptr, hb, ROWS, 1024, 256);
    // 9) drift_out = drift2 + h @ fc2^T + b2   (in-place on d_out)
    gemm_tc<3><<<dim3(256/64, ROWS/128), 256>>>(hb, fc2w, fc2b, out, out, ROWS, 256, 1024);
    // 10) ocean pass-through
    if (out_size >= 2 * ROWS * DIM) {
        cudaMemcpyAsync(out + (size_t)ROWS*DIM, ocean,
                        (size_t)ROWS*DIM*sizeof(float), cudaMemcpyDeviceToDevice);
    }
}

// round 4
// speedup vs baseline: 3.2141x; 1.2049x over previous
#include <cuda_runtime.h>
#include <math.h>
#include <stdint.h>

// Problem constants
#define BB    2
#define NN    2048
#define DIM   256
#define HH    8
#define HD    32
#define HD2   64
#define ROWS  (BB*NN)          // 4096
#define SCALE 0.17677669529663689f  // 32^-0.5
#define LAMBDA_INIT 0.1f
#define EPS   1e-5f

// ---------------- scratch (static device globals; no runtime allocation) ----
__device__ float g_x  [ROWS*DIM];      // LN1 output
__device__ float g_Q  [ROWS*2*DIM];    // Q proj (4096x512)
__device__ float g_K  [ROWS*2*DIM];    // K proj
__device__ float g_V  [ROWS*DIM];      // V proj
__device__ float g_att[ROWS*DIM];      // attention output
__device__ float g_y  [ROWS*DIM];      // LN2 output
__device__ float g_h  [ROWS*4*DIM];    // MLP hidden (4096x1024)

// ---------------- tf32 helpers ---------------------------------------------
__device__ __forceinline__ uint32_t f2tf(float x) {
    uint32_t u;
    asm("cvt.rna.tf32.f32 %0, %1;" : "=r"(u) : "f"(x));
    return u;
}
__device__ __forceinline__ float f2tff(float x) {
    return __uint_as_float(f2tf(x));
}
__device__ __forceinline__ void mma_tf32(float* d, const uint32_t* a, const uint32_t* b) {
    asm volatile("mma.sync.aligned.m16n8k8.row.col.f32.tf32.tf32.f32 "
                 "{%0,%1,%2,%3},{%4,%5,%6,%7},{%8,%9},{%0,%1,%2,%3};"
                 : "+f"(d[0]), "+f"(d[1]), "+f"(d[2]), "+f"(d[3])
                 : "r"(a[0]), "r"(a[1]), "r"(a[2]), "r"(a[3]),
                   "r"(b[0]), "r"(b[1]));
}

// ---------------- LayerNorm: 1 warp per row of 256 ------------------------
__global__ void __launch_bounds__(256) ln_kernel(const float* __restrict__ in,
                                                 float* __restrict__ out,
                                                 const float* __restrict__ gamma,
                                                 const float* __restrict__ beta)
{
    int wid  = threadIdx.x >> 5;
    int lane = threadIdx.x & 31;
    int row  = blockIdx.x * 8 + wid;
    const float4* p = (const float4*)(in + (size_t)row * DIM);
    float4 v0 = p[lane*2], v1 = p[lane*2+1];

    float s = v0.x+v0.y+v0.z+v0.w + v1.x+v1.y+v1.z+v1.w;
    #pragma unroll
    for (int o = 16; o; o >>= 1) s += __shfl_xor_sync(0xffffffffu, s, o);
    float mu = s * (1.0f/DIM);

    float d0x=v0.x-mu,d0y=v0.y-mu,d0z=v0.z-mu,d0w=v0.w-mu;
    float d1x=v1.x-mu,d1y=v1.y-mu,d1z=v1.z-mu,d1w=v1.w-mu;
    float q = d0x*d0x+d0y*d0y+d0z*d0z+d0w*d0w + d1x*d1x+d1y*d1y+d1z*d1z+d1w*d1w;
    #pragma unroll
    for (int o = 16; o; o >>= 1) q += __shfl_xor_sync(0xffffffffu, q, o);
    float rstd = rsqrtf(q * (1.0f/DIM) + EPS);

    const float4* gp = (const float4*)(gamma);
    const float4* bp = (const float4*)(beta);
    float4 g0 = gp[lane*2], g1 = gp[lane*2+1];
    float4 b0 = bp[lane*2], b1 = bp[lane*2+1];

    float4 o0, o1;
    o0.x = d0x*rstd*g0.x + b0.x;  o0.y = d0y*rstd*g0.y + b0.y;
    o0.z = d0z*rstd*g0.z + b0.z;  o0.w = d0w*rstd*g0.w + b0.w;
    o1.x = d1x*rstd*g1.x + b1.x;  o1.y = d1y*rstd*g1.y + b1.y;
    o1.z = d1z*rstd*g1.z + b1.z;  o1.w = d1w*rstd*g1.w + b1.w;

    float4* q4 = (float4*)(out + (size_t)row * DIM);
    q4[lane*2]   = o0;
    q4[lane*2+1] = o1;
}

// ---------------- tf32 tensor-core GEMM NT, 2-stage pipelined ---------------
// C[M,N] = A[M,K] * B[N,K]^T (+ epilogue). Tile 128x64, K-step 32.
// 256 threads = 8 warps as 4(M) x 2(N); double-buffered SMEM, 1 sync/iter.
// EPI: 0 = none, 1 = +res, 2 = gelu(.+bias), 3 = +bias+res
#define GA_STRIDE 36
#define GEMM_SMEM_BYTES ((2*128*36 + 2*64*36)*4)
template<int EPI>
__global__ void __launch_bounds__(256) gemm_tc(const float* __restrict__ A,
                                               const float* __restrict__ Bm,
                                               const float* __restrict__ bias,
                                               const float* __restrict__ res,
                                               float* __restrict__ C,
                                               int M, int N, int K)
{
    extern __shared__ float sm[];
    float* sA = sm;                // [2][128][36]
    float* sB = sm + 2*128*36;     // [2][64][36]

    const int tid  = threadIdx.x;
    const int m0   = blockIdx.y * 128;
    const int n0   = blockIdx.x * 64;
    const int lane = tid & 31;
    const int warp = tid >> 5;
    const int gr   = lane >> 2;
    const int gc   = lane & 3;
    const int wm   = warp >> 1;
    const int wn   = warp & 1;

    float c[2][4][4];
    #pragma unroll
    for (int mi=0; mi<2; mi++)
        #pragma unroll
        for (int ni=0; ni<4; ni++)
            #pragma unroll
            for (int i=0; i<4; i++) c[mi][ni][i] = 0.f;

    float4 a4[4], b4[2];

    auto loadRegs = [&](int k0) {
        #pragma unroll
        for (int it = 0; it < 4; it++) {
            int s = tid + it*256;
            a4[it] = *(const float4*)&A[(size_t)(m0 + (s>>3))*K + k0 + (s&7)*4];
        }
        #pragma unroll
        for (int it = 0; it < 2; it++) {
            int s = tid + it*256;
            b4[it] = *(const float4*)&Bm[(size_t)(n0 + (s>>3))*K + k0 + (s&7)*4];
        }
    };
    auto stsBuf = [&](int buf) {
        #pragma unroll
        for (int it = 0; it < 4; it++) {
            int s = tid + it*256;
            float* p = &sA[(buf*128 + (s>>3))*GA_STRIDE + (s&7)*4];
            p[0]=f2tff(a4[it].x); p[1]=f2tff(a4[it].y);
            p[2]=f2tff(a4[it].z); p[3]=f2tff(a4[it].w);
        }
        #pragma unroll
        for (int it = 0; it < 2; it++) {
            int s = tid + it*256;
            float* p = &sB[(buf*64 + (s>>3))*GA_STRIDE + (s&7)*4];
            p[0]=f2tff(b4[it].x); p[1]=f2tff(b4[it].y);
            p[2]=f2tff(b4[it].z); p[3]=f2tff(b4[it].w);
        }
    };
    auto compute = [&](int buf) {
        #pragma unroll
        for (int ks = 0; ks < 4; ks++) {
            const int k = ks*8;
            uint32_t af[2][4], bf[4][2];
            #pragma unroll
            for (int mi = 0; mi < 2; mi++) {
                int r = buf*128 + wm*32 + mi*16 + gr;
                af[mi][0] = __float_as_uint(sA[ r   *GA_STRIDE + k+gc  ]);
                af[mi][1] = __float_as_uint(sA[(r+8)*GA_STRIDE + k+gc  ]);
                af[mi][2] = __float_as_uint(sA[ r   *GA_STRIDE + k+gc+4]);
                af[mi][3] = __float_as_uint(sA[(r+8)*GA_STRIDE + k+gc+4]);
            }
            #pragma unroll
            for (int ni = 0; ni < 4; ni++) {
                int r = buf*64 + wn*32 + ni*8 + gr;
                bf[ni][0] = __float_as_uint(sB[r*GA_STRIDE + k+gc  ]);
                bf[ni][1] = __float_as_uint(sB[r*GA_STRIDE + k+gc+4]);
            }
            #pragma unroll
            for (int mi = 0; mi < 2; mi++)
                #pragma unroll
                for (int ni = 0; ni < 4; ni++)
                    mma_tf32(c[mi][ni], af[mi], bf[ni]);
        }
    };

    const int nIter = K >> 5;
    loadRegs(0);
    stsBuf(0);
    if (nIter > 1) loadRegs(32);
    __syncthreads();
    for (int it = 0; it < nIter; it++) {
        if (it+1 < nIter) stsBuf((it+1)&1);
        if (it+2 < nIter) loadRegs((it+2)*32);
        compute(it&1);
        __syncthreads();
    }

    // epilogue
    #pragma unroll
    for (int ni = 0; ni < 4; ni++) {
        const int col = n0 + wn*32 + ni*8 + 2*gc;
        float2 bi = make_float2(0.f, 0.f);
        if (EPI == 2 || EPI == 3) bi = *(const float2*)&bias[col];
        #pragma unroll
        for (int mi = 0; mi < 2; mi++) {
            const int row0 = m0 + wm*32 + mi*16 + gr;
            #pragma unroll
            for (int half = 0; half < 2; half++) {
                const int row = row0 + half*8;
                float2 v = make_float2(c[mi][ni][half*2], c[mi][ni][half*2+1]);
                if (EPI == 2) {
                    v.x += bi.x; v.y += bi.y;
                    v.x = 0.5f*v.x*(1.0f + erff(v.x*0.7071067811865475f));
                    v.y = 0.5f*v.y*(1.0f + erff(v.y*0.7071067811865475f));
                }
                if (EPI == 3) { v.x += bi.x; v.y += bi.y; }
                if (EPI == 1 || EPI == 3) {
                    float2 r = *(const float2*)&res[(size_t)row*N + col];
                    v.x += r.x; v.y += r.y;
                }
                *(float2*)&C[(size_t)row*N + col] = v;
            }
        }
    }
}

// ---------------- Differential attention via tf32 tensor cores ------------
// 128 queries/block, 256 threads (8 warps x 16 query rows).
#define KS_STRIDE 68
#define VS_STRIDE 40
#define PS_STRIDE 68
#define ATT_KS_OFF 0
#define ATT_VS_OFF (64*KS_STRIDE)
#define ATT_PS_OFF (ATT_VS_OFF + 64*VS_STRIDE)
#define ATT_SMEM_FLOATS (ATT_PS_OFF + 128*PS_STRIDE)
#define ATT_SMEM_BYTES (ATT_SMEM_FLOATS*4)
__global__ void __launch_bounds__(256) attn_tc(const float* __restrict__ Q,
                                               const float* __restrict__ Kg,
                                               const float* __restrict__ Vg,
                                               const float* __restrict__ lq1,
                                               const float* __restrict__ lk1,
                                               const float* __restrict__ lq2,
                                               const float* __restrict__ lk2,
                                               float* __restrict__ O)
{
    extern __shared__ float sm[];
    float* Ks = sm + ATT_KS_OFF;   // [64][68]
    float* Vs = sm + ATT_VS_OFF;   // [64][40]
    float* Ps = sm + ATT_PS_OFF;   // [128][68]

    const int b    = blockIdx.z;
    const int h    = blockIdx.y;
    const int warp = threadIdx.x >> 5;
    const int lane = threadIdx.x & 31;
    const int gr   = lane >> 2;
    const int gc   = lane & 3;
    const int qw   = blockIdx.x * 128 + warp * 16;

    float d1 = 0.f, d2 = 0.f;
    #pragma unroll
    for (int i = 0; i < HD; i++) {
        d1 = fmaf(lq1[h*HD+i], lk1[h*HD+i], d1);
        d2 = fmaf(lq2[h*HD+i], lk2[h*HD+i], d2);
    }
    const float lam = expf(d1) - expf(d2) + LAMBDA_INIT;

    uint32_t qf[2][4][4];
    {
        const size_t rstride = 2*DIM;
        const float* qb = Q + ((size_t)(b*NN + qw + gr))*rstride + h*HD2;
        #pragma unroll
        for (int half = 0; half < 2; half++) {
            #pragma unroll
            for (int ks = 0; ks < 4; ks++) {
                const float* p = qb + half*HD + ks*8 + gc;
                qf[half][ks][0] = f2tf(p[0]          * SCALE);
                qf[half][ks][1] = f2tf(p[8*rstride]  * SCALE);
                qf[half][ks][2] = f2tf(p[4]          * SCALE);
                qf[half][ks][3] = f2tf(p[8*rstride+4]* SCALE);
            }
        }
    }

    float o[2][4][4];
    #pragma unroll
    for (int hf=0; hf<2; hf++)
        #pragma unroll
        for (int n=0; n<4; n++)
            #pragma unroll
            for (int i=0; i<4; i++) o[hf][n][i] = 0.f;
    float lsum[2][2] = {{0.f,0.f},{0.f,0.f}};

    for (int k0 = 0; k0 < NN; k0 += 64) {
        __syncthreads();
        // K tile: 64 keys x 64 dims -> 1024 float4, 256 threads x 4
        #pragma unroll
        for (int it = 0; it < 4; it++) {
            int i = threadIdx.x + it*256;
            int row = i >> 4, c4 = i & 15;
            float4 v = *(const float4*)&Kg[((size_t)(b*NN + k0 + row))*(2*DIM) + h*HD2 + c4*4];
            float4 w = make_float4(f2tff(v.x), f2tff(v.y), f2tff(v.z), f2tff(v.w));
            *(float4*)&Ks[row*KS_STRIDE + c4*4] = w;
        }
        // V tile: 64 keys x 32 dims -> 512 float4, 256 threads x 2
        #pragma unroll
        for (int it = 0; it < 2; it++) {
            int i = threadIdx.x + it*256;
            int row = i >> 3, c4 = i & 7;
            float4 v = *(const float4*)&Vg[((size_t)(b*NN + k0 + row))*DIM + h*HD + c4*4];
            float4 w = make_float4(f2tff(v.x), f2tff(v.y), f2tff(v.z), f2tff(v.w));
            *(float4*)&Vs[row*VS_STRIDE + c4*4] = w;
        }
        __syncthreads();

        #pragma unroll
        for (int half = 0; half < 2; half++) {
            float s[8][4];
            #pragma unroll
            for (int n=0;n<8;n++)
                #pragma unroll
                for (int i=0;i<4;i++) s[n][i] = 0.f;

            #pragma unroll
            for (int n = 0; n < 8; n++) {
                int key = n*8 + gr;
                #pragma unroll
                for (int ks = 0; ks < 4; ks++) {
                    uint32_t bb[2];
                    int d = half*HD + ks*8 + gc;
                    bb[0] = __float_as_uint(Ks[key*KS_STRIDE + d]);
                    bb[1] = __float_as_uint(Ks[key*KS_STRIDE + d+4]);
                    mma_tf32(s[n], qf[half][ks], bb);
                }
            }
            #pragma unroll
            for (int n = 0; n < 8; n++) {
                float p0 = __expf(s[n][0]);
                float p1 = __expf(s[n][1]);
                float p2 = __expf(s[n][2]);
                float p3 = __expf(s[n][3]);
                lsum[half][0] += p0 + p1;
                lsum[half][1] += p2 + p3;
                float2 lo = make_float2(f2tff(p0), f2tff(p1));
                float2 hi = make_float2(f2tff(p2), f2tff(p3));
                *(float2*)&Ps[(warp*16 + gr    )*PS_STRIDE + n*8 + 2*gc] = lo;
                *(float2*)&Ps[(warp*16 + gr + 8)*PS_STRIDE + n*8 + 2*gc] = hi;
            }
            __syncwarp();
            #pragma unroll
            for (int ks = 0; ks < 8; ks++) {
                uint32_t af[4];
                af[0] = __float_as_uint(Ps[(warp*16 + gr    )*PS_STRIDE + ks*8 + gc    ]);
                af[1] = __float_as_uint(Ps[(warp*16 + gr + 8)*PS_STRIDE + ks*8 + gc    ]);
                af[2] = __float_as_uint(Ps[(warp*16 + gr    )*PS_STRIDE + ks*8 + gc + 4]);
                af[3] = __float_as_uint(Ps[(warp*16 + gr + 8)*PS_STRIDE + ks*8 + gc + 4]);
                #pragma unroll
                for (int n = 0; n < 4; n++) {
                    uint32_t bb[2];
                    bb[0] = __float_as_uint(Vs[(ks*8 + gc    )*VS_STRIDE + n*8 + gr]);
                    bb[1] = __float_as_uint(Vs[(ks*8 + gc + 4)*VS_STRIDE + n*8 + gr]);
                    mma_tf32(o[half][n], af, bb);
                }
            }
            __syncwarp();
        }
    }

    #pragma unroll
    for (int hf = 0; hf < 2; hf++) {
        #pragma unroll
        for (int r2 = 0; r2 < 2; r2++) {
            float v = lsum[hf][r2];
            v += __shfl_xor_sync(0xffffffffu, v, 1);
            v += __shfl_xor_sync(0xffffffffu, v, 2);
            lsum[hf][r2] = v;
        }
    }
    const float i1A = 1.f / lsum[0][0];
    const float i1B = 1.f / lsum[0][1];
    const float s2A = lam / lsum[1][0];
    const float s2B = lam / lsum[1][1];

    float* outA = O + ((size_t)(b*NN + qw + gr    ))*DIM + h*HD;
    float* outB = O + ((size_t)(b*NN + qw + gr + 8))*DIM + h*HD;
    #pragma unroll
    for (int n = 0; n < 4; n++) {
        float2 vA = make_float2(o[0][n][0]*i1A - o[1][n][0]*s2A,
                                o[0][n][1]*i1A - o[1][n][1]*s2A);
        float2 vB = make_float2(o[0][n][2]*i1B - o[1][n][2]*s2B,
                                o[0][n][3]*i1B - o[1][n][3]*s2B);
        *(float2*)&outA[n*8 + 2*gc] = vA;
        *(float2*)&outB[n*8 + 2*gc] = vB;
    }
}

// ---------------- launch ----------------------------------------------------
static float* symp(const void* sym) {
    void* p = nullptr;
    cudaGetSymbolAddress(&p, sym);
    return (float*)p;
}

extern "C" void kernel_launch(void* const* d_in, const int* in_sizes, int n_in,
                              void* d_out, int out_size)
{
    const float* drift = (const float*)d_in[0];
    const float* ocean = (const float*)d_in[1];
    const float* Wq    = (const float*)d_in[2];
    const float* Wk    = (const float*)d_in[3];
    const float* Wv    = (const float*)d_in[4];
    const float* Wo    = (const float*)d_in[5];
    const float* lq1   = (const float*)d_in[6];
    const float* lk1   = (const float*)d_in[7];
    const float* lq2   = (const float*)d_in[8];
    const float* lk2   = (const float*)d_in[9];
    const float* gamma = (const float*)d_in[10];
    const float* beta  = (const float*)d_in[11];
    const float* fc1w  = (const float*)d_in[12];
    const float* fc1b  = (const float*)d_in[13];
    const float* fc2w  = (const float*)d_in[14];
    const float* fc2b  = (const float*)d_in[15];
    float* out = (float*)d_out;

    float* x   = symp(g_x);
    float* Qb  = symp(g_Q);
    float* Kb  = symp(g_K);
    float* Vb  = symp(g_V);
    float* att = symp(g_att);
    float* y   = symp(g_y);
    float* hb  = symp(g_h);

    // raise dynamic smem limits (host-side, idempotent, capture-safe)
    cudaFuncSetAttribute(gemm_tc<0>, cudaFuncAttributeMaxDynamicSharedMemorySize, GEMM_SMEM_BYTES);
    cudaFuncSetAttribute(gemm_tc<1>, cudaFuncAttributeMaxDynamicSharedMemorySize, GEMM_SMEM_BYTES);
    cudaFuncSetAttribute(gemm_tc<2>, cudaFuncAttributeMaxDynamicSharedMemorySize, GEMM_SMEM_BYTES);
    cudaFuncSetAttribute(gemm_tc<3>, cudaFuncAttributeMaxDynamicSharedMemorySize, GEMM_SMEM_BYTES);
    cudaFuncSetAttribute(attn_tc,    cudaFuncAttributeMaxDynamicSharedMemorySize, ATT_SMEM_BYTES);

    // 1) x = LN(drift)
    ln_kernel<<<ROWS/8, 256>>>(drift, x, gamma, beta);
    // 2) Q = x @ Wq^T   (4096 x 512)
    gemm_tc<0><<<dim3(512/64, ROWS/128), 256, GEMM_SMEM_BYTES>>>(x, Wq, nullptr, nullptr, Qb, ROWS, 512, 256);
    // 3) K = ocean @ Wk^T
    gemm_tc<0><<<dim3(512/64, ROWS/128), 256, GEMM_SMEM_BYTES>>>(ocean, Wk, nullptr, nullptr, Kb, ROWS, 512, 256);
    // 4) V = ocean @ Wv^T
    gemm_tc<0><<<dim3(256/64, ROWS/128), 256, GEMM_SMEM_BYTES>>>(ocean, Wv, nullptr, nullptr, Vb, ROWS, 256, 256);
    // 5) differential attention (tf32 tensor cores, 128 q/block)
    attn_tc<<<dim3(NN/128, HH, BB), 256, ATT_SMEM_BYTES>>>(Qb, Kb, Vb, lq1, lk1, lq2, lk2, att);
    // 6) drift2 = drift + att @ Wo^T  -> d_out (drift section)
    gemm_tc<1><<<dim3(256/64, ROWS/128), 256, GEMM_SMEM_BYTES>>>(att, Wo, nullptr, drift, out, ROWS, 256, 256);
    // 7) y = LN(drift2)
    ln_kernel<<<ROWS/8, 256>>>(out, y, gamma, beta);
    // 8) h = gelu(y @ fc1^T + b1)   (4096 x 1024)
    gemm_tc<2><<<dim3(1024/64, ROWS/128), 256, GEMM_SMEM_BYTES>>>(y, fc1w, fc1b, nullptr, hb, ROWS, 1024, 256);
    // 9) drift_out = drift2 + h @ fc2^T + b2   (in-place on d_out)
    gemm_tc<3><<<dim3(256/64, ROWS/128), 256, GEMM_SMEM_BYTES>>>(hb, fc2w, fc2b, out, out, ROWS, 256, 1024);
    // 10) ocean pass-through
    if (out_size >= 2 * ROWS * DIM) {
        cudaMemcpyAsync(out + (size_t)ROWS*DIM, ocean,
                        (size_t)ROWS*DIM*sizeof(float), cudaMemcpyDeviceToDevice);
    }
}

// round 5
// speedup vs baseline: 3.9405x; 1.2260x over previous
#include <cuda_runtime.h>
#include <cuda_fp16.h>
#include <math.h>
#include <stdint.h>

// Problem constants
#define BB    2
#define NN    2048
#define DIM   256
#define HH    8
#define HD    32
#define HD2   64
#define ROWS  (BB*NN)          // 4096
#define SCALE 0.17677669529663689f  // 32^-0.5
#define LAMBDA_INIT 0.1f
#define EPS   1e-5f

// ---------------- scratch (static device globals; no runtime allocation) ----
__device__ float g_x  [ROWS*DIM];      // LN1 output
__device__ float g_Q  [ROWS*2*DIM];    // Q proj (4096x512)
__device__ float g_K  [ROWS*2*DIM];    // K proj
__device__ float g_V  [ROWS*DIM];      // V proj
__device__ float g_att[ROWS*DIM];      // attention output
__device__ float g_y  [ROWS*DIM];      // LN2 output
__device__ float g_h  [ROWS*4*DIM];    // MLP hidden (4096x1024)

// ---------------- tf32 helpers ---------------------------------------------
__device__ __forceinline__ uint32_t f2tf(float x) {
    uint32_t u;
    asm("cvt.rna.tf32.f32 %0, %1;" : "=r"(u) : "f"(x));
    return u;
}
__device__ __forceinline__ float f2tff(float x) {
    return __uint_as_float(f2tf(x));
}
__device__ __forceinline__ void mma_tf32(float* d, const uint32_t* a, const uint32_t* b) {
    asm volatile("mma.sync.aligned.m16n8k8.row.col.f32.tf32.tf32.f32 "
                 "{%0,%1,%2,%3},{%4,%5,%6,%7},{%8,%9},{%0,%1,%2,%3};"
                 : "+f"(d[0]), "+f"(d[1]), "+f"(d[2]), "+f"(d[3])
                 : "r"(a[0]), "r"(a[1]), "r"(a[2]), "r"(a[3]),
                   "r"(b[0]), "r"(b[1]));
}
// ---------------- fp16 mma helper ------------------------------------------
__device__ __forceinline__ void mma_f16(float* d, const uint32_t* a,
                                        uint32_t b0, uint32_t b1) {
    asm volatile("mma.sync.aligned.m16n8k16.row.col.f32.f16.f16.f32 "
                 "{%0,%1,%2,%3},{%4,%5,%6,%7},{%8,%9},{%0,%1,%2,%3};"
                 : "+f"(d[0]), "+f"(d[1]), "+f"(d[2]), "+f"(d[3])
                 : "r"(a[0]), "r"(a[1]), "r"(a[2]), "r"(a[3]),
                   "r"(b0), "r"(b1));
}
__device__ __forceinline__ uint32_t packh2(float x, float y) {
    __half2 h = __floats2half2_rn(x, y);
    return *reinterpret_cast<uint32_t*>(&h);
}

// ---------------- LayerNorm: 1 warp per row of 256 ------------------------
__global__ void __launch_bounds__(256) ln_kernel(const float* __restrict__ in,
                                                 float* __restrict__ out,
                                                 const float* __restrict__ gamma,
                                                 const float* __restrict__ beta)
{
    int wid  = threadIdx.x >> 5;
    int lane = threadIdx.x & 31;
    int row  = blockIdx.x * 8 + wid;
    const float4* p = (const float4*)(in + (size_t)row * DIM);
    float4 v0 = p[lane*2], v1 = p[lane*2+1];

    float s = v0.x+v0.y+v0.z+v0.w + v1.x+v1.y+v1.z+v1.w;
    #pragma unroll
    for (int o = 16; o; o >>= 1) s += __shfl_xor_sync(0xffffffffu, s, o);
    float mu = s * (1.0f/DIM);

    float d0x=v0.x-mu,d0y=v0.y-mu,d0z=v0.z-mu,d0w=v0.w-mu;
    float d1x=v1.x-mu,d1y=v1.y-mu,d1z=v1.z-mu,d1w=v1.w-mu;
    float q = d0x*d0x+d0y*d0y+d0z*d0z+d0w*d0w + d1x*d1x+d1y*d1y+d1z*d1z+d1w*d1w;
    #pragma unroll
    for (int o = 16; o; o >>= 1) q += __shfl_xor_sync(0xffffffffu, q, o);
    float rstd = rsqrtf(q * (1.0f/DIM) + EPS);

    const float4* gp = (const float4*)(gamma);
    const float4* bp = (const float4*)(beta);
    float4 g0 = gp[lane*2], g1 = gp[lane*2+1];
    float4 b0 = bp[lane*2], b1 = bp[lane*2+1];

    float4 o0, o1;
    o0.x = d0x*rstd*g0.x + b0.x;  o0.y = d0y*rstd*g0.y + b0.y;
    o0.z = d0z*rstd*g0.z + b0.z;  o0.w = d0w*rstd*g0.w + b0.w;
    o1.x = d1x*rstd*g1.x + b1.x;  o1.y = d1y*rstd*g1.y + b1.y;
    o1.z = d1z*rstd*g1.z + b1.z;  o1.w = d1w*rstd*g1.w + b1.w;

    float4* q4 = (float4*)(out + (size_t)row * DIM);
    q4[lane*2]   = o0;
    q4[lane*2+1] = o1;
}

// ---------------- tf32 tensor-core GEMM NT, 2-stage pipelined ---------------
#define GA_STRIDE 36
#define GEMM_SMEM_BYTES ((2*128*36 + 2*64*36)*4)
template<int EPI>
__global__ void __launch_bounds__(256) gemm_tc(const float* __restrict__ A,
                                               const float* __restrict__ Bm,
                                               const float* __restrict__ bias,
                                               const float* __restrict__ res,
                                               float* __restrict__ C,
                                               int M, int N, int K)
{
    extern __shared__ float sm[];
    float* sA = sm;                // [2][128][36]
    float* sB = sm + 2*128*36;     // [2][64][36]

    const int tid  = threadIdx.x;
    const int m0   = blockIdx.y * 128;
    const int n0   = blockIdx.x * 64;
    const int lane = tid & 31;
    const int warp = tid >> 5;
    const int gr   = lane >> 2;
    const int gc   = lane & 3;
    const int wm   = warp >> 1;
    const int wn   = warp & 1;

    float c[2][4][4];
    #pragma unroll
    for (int mi=0; mi<2; mi++)
        #pragma unroll
        for (int ni=0; ni<4; ni++)
            #pragma unroll
            for (int i=0; i<4; i++) c[mi][ni][i] = 0.f;

    float4 a4[4], b4[2];

    auto loadRegs = [&](int k0) {
        #pragma unroll
        for (int it = 0; it < 4; it++) {
            int s = tid + it*256;
            a4[it] = *(const float4*)&A[(size_t)(m0 + (s>>3))*K + k0 + (s&7)*4];
        }
        #pragma unroll
        for (int it = 0; it < 2; it++) {
            int s = tid + it*256;
            b4[it] = *(const float4*)&Bm[(size_t)(n0 + (s>>3))*K + k0 + (s&7)*4];
        }
    };
    auto stsBuf = [&](int buf) {
        #pragma unroll
        for (int it = 0; it < 4; it++) {
            int s = tid + it*256;
            float* p = &sA[(buf*128 + (s>>3))*GA_STRIDE + (s&7)*4];
            p[0]=f2tff(a4[it].x); p[1]=f2tff(a4[it].y);
            p[2]=f2tff(a4[it].z); p[3]=f2tff(a4[it].w);
        }
        #pragma unroll
        for (int it = 0; it < 2; it++) {
            int s = tid + it*256;
            float* p = &sB[(buf*64 + (s>>3))*GA_STRIDE + (s&7)*4];
            p[0]=f2tff(b4[it].x); p[1]=f2tff(b4[it].y);
            p[2]=f2tff(b4[it].z); p[3]=f2tff(b4[it].w);
        }
    };
    auto compute = [&](int buf) {
        #pragma unroll
        for (int ks = 0; ks < 4; ks++) {
            const int k = ks*8;
            uint32_t af[2][4], bf[4][2];
            #pragma unroll
            for (int mi = 0; mi < 2; mi++) {
                int r = buf*128 + wm*32 + mi*16 + gr;
                af[mi][0] = __float_as_uint(sA[ r   *GA_STRIDE + k+gc  ]);
                af[mi][1] = __float_as_uint(sA[(r+8)*GA_STRIDE + k+gc  ]);
                af[mi][2] = __float_as_uint(sA[ r   *GA_STRIDE + k+gc+4]);
                af[mi][3] = __float_as_uint(sA[(r+8)*GA_STRIDE + k+gc+4]);
            }
            #pragma unroll
            for (int ni = 0; ni < 4; ni++) {
                int r = buf*64 + wn*32 + ni*8 + gr;
                bf[ni][0] = __float_as_uint(sB[r*GA_STRIDE + k+gc  ]);
                bf[ni][1] = __float_as_uint(sB[r*GA_STRIDE + k+gc+4]);
            }
            #pragma unroll
            for (int mi = 0; mi < 2; mi++)
                #pragma unroll
                for (int ni = 0; ni < 4; ni++)
                    mma_tf32(c[mi][ni], af[mi], bf[ni]);
        }
    };

    const int nIter = K >> 5;
    loadRegs(0);
    stsBuf(0);
    if (nIter > 1) loadRegs(32);
    __syncthreads();
    for (int it = 0; it < nIter; it++) {
        if (it+1 < nIter) stsBuf((it+1)&1);
        if (it+2 < nIter) loadRegs((it+2)*32);
        compute(it&1);
        __syncthreads();
    }

    // epilogue
    #pragma unroll
    for (int ni = 0; ni < 4; ni++) {
        const int col = n0 + wn*32 + ni*8 + 2*gc;
        float2 bi = make_float2(0.f, 0.f);
        if (EPI == 2 || EPI == 3) bi = *(const float2*)&bias[col];
        #pragma unroll
        for (int mi = 0; mi < 2; mi++) {
            const int row0 = m0 + wm*32 + mi*16 + gr;
            #pragma unroll
            for (int half = 0; half < 2; half++) {
                const int row = row0 + half*8;
                float2 v = make_float2(c[mi][ni][half*2], c[mi][ni][half*2+1]);
                if (EPI == 2) {
                    v.x += bi.x; v.y += bi.y;
                    v.x = 0.5f*v.x*(1.0f + erff(v.x*0.7071067811865475f));
                    v.y = 0.5f*v.y*(1.0f + erff(v.y*0.7071067811865475f));
                }
                if (EPI == 3) { v.x += bi.x; v.y += bi.y; }
                if (EPI == 1 || EPI == 3) {
                    float2 r = *(const float2*)&res[(size_t)row*N + col];
                    v.x += r.x; v.y += r.y;
                }
                *(float2*)&C[(size_t)row*N + col] = v;
            }
        }
    }
}

// ---------------- Differential attention: fp16 m16n8k16 tensor cores -------
// 128 queries/block, 256 threads (8 warps x 16 query rows).
// K in SMEM as half2 along dim; V transposed to half2 along key.
// P stays in registers: S-mma C fragment packs directly into PV A fragment.
#define KH_STRIDE 36   // half2 stride per key row (32 used + pad)
#define VT_STRIDE 36   // half2 stride per hd row (32 used + pad)
__global__ void __launch_bounds__(256) attn_tc(const float* __restrict__ Q,
                                               const float* __restrict__ Kg,
                                               const float* __restrict__ Vg,
                                               const float* __restrict__ lq1,
                                               const float* __restrict__ lk1,
                                               const float* __restrict__ lq2,
                                               const float* __restrict__ lk2,
                                               float* __restrict__ O)
{
    __shared__ uint32_t Kh[64*KH_STRIDE];  // 64 keys x 32 half2 (both halves)
    __shared__ uint32_t Vt[32*VT_STRIDE];  // 32 hd x 32 half2 (keys)

    const int b    = blockIdx.z;
    const int h    = blockIdx.y;
    const int warp = threadIdx.x >> 5;
    const int lane = threadIdx.x & 31;
    const int gr   = lane >> 2;
    const int gc   = lane & 3;
    const int qw   = blockIdx.x * 128 + warp * 16;

    float d1 = 0.f, d2 = 0.f;
    #pragma unroll
    for (int i = 0; i < HD; i++) {
        d1 = fmaf(lq1[h*HD+i], lk1[h*HD+i], d1);
        d2 = fmaf(lq2[h*HD+i], lk2[h*HD+i], d2);
    }
    const float lam = expf(d1) - expf(d2) + LAMBDA_INIT;

    // Q fragments (SCALE folded), fp16 packed. qh[half][kc][4]
    uint32_t qh[2][2][4];
    {
        const size_t rs = 2*DIM;  // 512
        const float* q0 = Q + ((size_t)(b*NN + qw + gr))*rs + h*HD2;
        const float* q8 = q0 + 8*rs;
        #pragma unroll
        for (int half = 0; half < 2; half++) {
            #pragma unroll
            for (int kc = 0; kc < 2; kc++) {
                int off = half*HD + kc*16 + 2*gc;
                qh[half][kc][0] = packh2(q0[off  ]*SCALE, q0[off+1]*SCALE);
                qh[half][kc][1] = packh2(q8[off  ]*SCALE, q8[off+1]*SCALE);
                qh[half][kc][2] = packh2(q0[off+8]*SCALE, q0[off+9]*SCALE);
                qh[half][kc][3] = packh2(q8[off+8]*SCALE, q8[off+9]*SCALE);
            }
        }
    }

    float o[2][4][4];
    #pragma unroll
    for (int hf=0; hf<2; hf++)
        #pragma unroll
        for (int n=0; n<4; n++)
            #pragma unroll
            for (int i=0; i<4; i++) o[hf][n][i] = 0.f;
    float lsum[2][2] = {{0.f,0.f},{0.f,0.f}};

    for (int k0 = 0; k0 < NN; k0 += 64) {
        __syncthreads();
        // K tile: 64 keys x 64 dims -> half2
        #pragma unroll
        for (int it = 0; it < 4; it++) {
            int i = threadIdx.x + it*256;
            int key = i >> 4, c4 = i & 15;
            float4 v = *(const float4*)&Kg[((size_t)(b*NN + k0 + key))*(2*DIM) + h*HD2 + c4*4];
            Kh[key*KH_STRIDE + c4*2    ] = packh2(v.x, v.y);
            Kh[key*KH_STRIDE + c4*2 + 1] = packh2(v.z, v.w);
        }
        // V tile: 64 keys x 32 dims -> transposed half scalar stores
        {
            __half* Vh = (__half*)Vt;
            #pragma unroll
            for (int it = 0; it < 2; it++) {
                int i = threadIdx.x + it*256;
                int key = i >> 3, c4 = i & 7;
                float4 v = *(const float4*)&Vg[((size_t)(b*NN + k0 + key))*DIM + h*HD + c4*4];
                Vh[(c4*4+0)*(2*VT_STRIDE) + key] = __float2half_rn(v.x);
                Vh[(c4*4+1)*(2*VT_STRIDE) + key] = __float2half_rn(v.y);
                Vh[(c4*4+2)*(2*VT_STRIDE) + key] = __float2half_rn(v.z);
                Vh[(c4*4+3)*(2*VT_STRIDE) + key] = __float2half_rn(v.w);
            }
        }
        __syncthreads();

        // S phase per half -> exp -> pack P into PV A-fragments (registers)
        uint32_t ph[2][4][4];
        #pragma unroll
        for (int half = 0; half < 2; half++) {
            float s[8][4];
            #pragma unroll
            for (int n=0;n<8;n++)
                #pragma unroll
                for (int i=0;i<4;i++) s[n][i] = 0.f;

            #pragma unroll
            for (int n = 0; n < 8; n++) {
                const uint32_t* krow = &Kh[(n*8 + gr)*KH_STRIDE + half*16];
                #pragma unroll
                for (int kc = 0; kc < 2; kc++) {
                    uint32_t b0 = krow[kc*8 + gc];
                    uint32_t b1 = krow[kc*8 + gc + 4];
                    mma_f16(s[n], qh[half][kc], b0, b1);
                }
            }
            #pragma unroll
            for (int n = 0; n < 8; n++) {
                float p0 = __expf(s[n][0]);
                float p1 = __expf(s[n][1]);
                float p2 = __expf(s[n][2]);
                float p3 = __expf(s[n][3]);
                lsum[half][0] += p0 + p1;
                lsum[half][1] += p2 + p3;
                int ks = n >> 1, hi = (n & 1) * 2;
                ph[half][ks][hi    ] = packh2(p0, p1);
                ph[half][ks][hi + 1] = packh2(p2, p3);
            }
        }

        // PV: shared V fragments feed both halves
        #pragma unroll
        for (int ks = 0; ks < 4; ks++) {
            #pragma unroll
            for (int n = 0; n < 4; n++) {
                uint32_t b0 = Vt[(n*8 + gr)*VT_STRIDE + ks*8 + gc    ];
                uint32_t b1 = Vt[(n*8 + gr)*VT_STRIDE + ks*8 + gc + 4];
                mma_f16(o[0][n], ph[0][ks], b0, b1);
                mma_f16(o[1][n], ph[1][ks], b0, b1);
            }
        }
    }

    #pragma unroll
    for (int hf = 0; hf < 2; hf++) {
        #pragma unroll
        for (int r2 = 0; r2 < 2; r2++) {
            float v = lsum[hf][r2];
            v += __shfl_xor_sync(0xffffffffu, v, 1);
            v += __shfl_xor_sync(0xffffffffu, v, 2);
            lsum[hf][r2] = v;
        }
    }
    const float i1A = 1.f / lsum[0][0];
    const float i1B = 1.f / lsum[0][1];
    const float s2A = lam / lsum[1][0];
    const float s2B = lam / lsum[1][1];

    float* outA = O + ((size_t)(b*NN + qw + gr    ))*DIM + h*HD;
    float* outB = O + ((size_t)(b*NN + qw + gr + 8))*DIM + h*HD;
    #pragma unroll
    for (int n = 0; n < 4; n++) {
        float2 vA = make_float2(o[0][n][0]*i1A - o[1][n][0]*s2A,
                                o[0][n][1]*i1A - o[1][n][1]*s2A);
        float2 vB = make_float2(o[0][n][2]*i1B - o[1][n][2]*s2B,
                                o[0][n][3]*i1B - o[1][n][3]*s2B);
        *(float2*)&outA[n*8 + 2*gc] = vA;
        *(float2*)&outB[n*8 + 2*gc] = vB;
    }
}

// ---------------- launch ----------------------------------------------------
static float* symp(const void* sym) {
    void* p = nullptr;
    cudaGetSymbolAddress(&p, sym);
    return (float*)p;
}

extern "C" void kernel_launch(void* const* d_in, const int* in_sizes, int n_in,
                              void* d_out, int out_size)
{
    const float* drift = (const float*)d_in[0];
    const float* ocean = (const float*)d_in[1];
    const float* Wq    = (const float*)d_in[2];
    const float* Wk    = (const float*)d_in[3];
    const float* Wv    = (const float*)d_in[4];
    const float* Wo    = (const float*)d_in[5];
    const float* lq1   = (const float*)d_in[6];
    const float* lk1   = (const float*)d_in[7];
    const float* lq2   = (const float*)d_in[8];
    const float* lk2   = (const float*)d_in[9];
    const float* gamma = (const float*)d_in[10];
    const float* beta  = (const float*)d_in[11];
    const float* fc1w  = (const float*)d_in[12];
    const float* fc1b  = (const float*)d_in[13];
    const float* fc2w  = (const float*)d_in[14];
    const float* fc2b  = (const float*)d_in[15];
    float* out = (float*)d_out;

    float* x   = symp(g_x);
    float* Qb  = symp(g_Q);
    float* Kb  = symp(g_K);
    float* Vb  = symp(g_V);
    float* att = symp(g_att);
    float* y   = symp(g_y);
    float* hb  = symp(g_h);

    cudaFuncSetAttribute(gemm_tc<0>, cudaFuncAttributeMaxDynamicSharedMemorySize, GEMM_SMEM_BYTES);
    cudaFuncSetAttribute(gemm_tc<1>, cudaFuncAttributeMaxDynamicSharedMemorySize, GEMM_SMEM_BYTES);
    cudaFuncSetAttribute(gemm_tc<2>, cudaFuncAttributeMaxDynamicSharedMemorySize, GEMM_SMEM_BYTES);
    cudaFuncSetAttribute(gemm_tc<3>, cudaFuncAttributeMaxDynamicSharedMemorySize, GEMM_SMEM_BYTES);

    // 1) x = LN(drift)
    ln_kernel<<<ROWS/8, 256>>>(drift, x, gamma, beta);
    // 2) Q = x @ Wq^T   (4096 x 512)
    gemm_tc<0><<<dim3(512/64, ROWS/128), 256, GEMM_SMEM_BYTES>>>(x, Wq, nullptr, nullptr, Qb, ROWS, 512, 256);
    // 3) K = ocean @ Wk^T
    gemm_tc<0><<<dim3(512/64, ROWS/128), 256, GEMM_SMEM_BYTES>>>(ocean, Wk, nullptr, nullptr, Kb, ROWS, 512, 256);
    // 4) V = ocean @ Wv^T
    gemm_tc<0><<<dim3(256/64, ROWS/128), 256, GEMM_SMEM_BYTES>>>(ocean, Wv, nullptr, nullptr, Vb, ROWS, 256, 256);
    // 5) differential attention (fp16 tensor cores)
    attn_tc<<<dim3(NN/128, HH, BB), 256>>>(Qb, Kb, Vb, lq1, lk1, lq2, lk2, att);
    // 6) drift2 = drift + att @ Wo^T  -> d_out (drift section)
    gemm_tc<1><<<dim3(256/64, ROWS/128), 256, GEMM_SMEM_BYTES>>>(att, Wo, nullptr, drift, out, ROWS, 256, 256);
    // 7) y = LN(drift2)
    ln_kernel<<<ROWS/8, 256>>>(out, y, gamma, beta);
    // 8) h = gelu(y @ fc1^T + b1)   (4096 x 1024)
    gemm_tc<2><<<dim3(1024/64, ROWS/128), 256, GEMM_SMEM_BYTES>>>(y, fc1w, fc1b, nullptr, hb, ROWS, 1024, 256);
    // 9) drift_out = drift2 + h @ fc2^T + b2   (in-place on d_out)
    gemm_tc<3><<<dim3(256/64, ROWS/128), 256, GEMM_SMEM_BYTES>>>(hb, fc2w, fc2b, out, out, ROWS, 256, 1024);
    // 10) ocean pass-through
    if (out_size >= 2 * ROWS * DIM) {
        cudaMemcpyAsync(out + (size_t)ROWS*DIM, ocean,
                        (size_t)ROWS*DIM*sizeof(float), cudaMemcpyDeviceToDevice);
    }
}

// round 7
// speedup vs baseline: 5.6478x; 1.4333x over previous
#include <cuda_runtime.h>
#include <cuda_fp16.h>
#include <math.h>
#include <stdint.h>

// Problem constants
#define BB    2
#define NN    2048
#define DIM   256
#define HH    8
#define HD    32
#define HD2   64
#define ROWS  (BB*NN)          // 4096
#define SCALE 0.17677669529663689f  // 32^-0.5
#define LAMBDA_INIT 0.1f
#define EPS   1e-5f

// ---------------- half weight/activation pool (static, no allocation) ------
#define OC_OFF   0u
#define WQ_OFF   1048576u
#define WK_OFF   1179648u
#define WV_OFF   1310720u
#define WO_OFF   1376256u
#define F1_OFF   1441792u
#define F2_OFF   1703936u
#define HW_TOTAL 1966080u
__device__ __half g_hw [HW_TOTAL];     // ocean + all weights (fp16)
__device__ __half g_hx [ROWS*DIM];     // LN1 out
__device__ __half g_hQ [ROWS*2*DIM];   // Q (pre-scaled by SCALE)
__device__ __half g_hK [ROWS*2*DIM];
__device__ __half g_hV [ROWS*DIM];
__device__ __half g_hatt[ROWS*DIM];
__device__ __half g_hy [ROWS*DIM];     // LN2 out
__device__ __half g_hh [ROWS*4*DIM];   // MLP hidden

// ---------------- helpers ---------------------------------------------------
__device__ __forceinline__ void mma_f16(float* d, const uint32_t* a,
                                        uint32_t b0, uint32_t b1) {
    asm volatile("mma.sync.aligned.m16n8k16.row.col.f32.f16.f16.f32 "
                 "{%0,%1,%2,%3},{%4,%5,%6,%7},{%8,%9},{%0,%1,%2,%3};"
                 : "+f"(d[0]), "+f"(d[1]), "+f"(d[2]), "+f"(d[3])
                 : "r"(a[0]), "r"(a[1]), "r"(a[2]), "r"(a[3]),
                   "r"(b0), "r"(b1));
}
__device__ __forceinline__ uint32_t packh2(float x, float y) {
    __half2 h = __floats2half2_rn(x, y);
    return *reinterpret_cast<uint32_t*>(&h);
}
__device__ __forceinline__ void cp16(uint32_t saddr, const void* g) {
    asm volatile("cp.async.cg.shared.global [%0], [%1], 16;\n" :: "r"(saddr), "l"(g));
}
__device__ __forceinline__ void cp_commit() { asm volatile("cp.async.commit_group;\n"); }
template<int N> __device__ __forceinline__ void cp_wait() {
    asm volatile("cp.async.wait_group %0;\n" :: "n"(N));
}

// ---------------- fp32 -> fp16 conversion (ocean + weights) ----------------
__global__ void __launch_bounds__(256) cvt_kernel(const float* __restrict__ oc,
    const float* __restrict__ wq, const float* __restrict__ wk,
    const float* __restrict__ wv, const float* __restrict__ wo,
    const float* __restrict__ f1, const float* __restrict__ f2,
    __half* __restrict__ dst)
{
    uint32_t fi = ((uint32_t)blockIdx.x*256u + threadIdx.x)*4u;
    if (fi >= HW_TOTAL) return;
    const float* src; uint32_t base;
    if      (fi < WQ_OFF) { src = oc; base = OC_OFF; }
    else if (fi < WK_OFF) { src = wq; base = WQ_OFF; }
    else if (fi < WV_OFF) { src = wk; base = WK_OFF; }
    else if (fi < WO_OFF) { src = wv; base = WV_OFF; }
    else if (fi < F1_OFF) { src = wo; base = WO_OFF; }
    else if (fi < F2_OFF) { src = f1; base = F1_OFF; }
    else                  { src = f2; base = F2_OFF; }
    float4 v = *(const float4*)&src[fi - base];
    uint2 u = make_uint2(packh2(v.x, v.y), packh2(v.z, v.w));
    *(uint2*)&dst[fi] = u;
}

// ---------------- LayerNorm: fp32 in, fp16 out ------------------------------
__global__ void __launch_bounds__(256) ln_half(const float* __restrict__ in,
                                               __half* __restrict__ out,
                                               const float* __restrict__ gamma,
                                               const float* __restrict__ beta)
{
    int wid  = threadIdx.x >> 5;
    int lane = threadIdx.x & 31;
    int row  = blockIdx.x * 8 + wid;
    const float4* p = (const float4*)(in + (size_t)row * DIM);
    float4 v0 = p[lane*2], v1 = p[lane*2+1];

    float s = v0.x+v0.y+v0.z+v0.w + v1.x+v1.y+v1.z+v1.w;
    #pragma unroll
    for (int o = 16; o; o >>= 1) s += __shfl_xor_sync(0xffffffffu, s, o);
    float mu = s * (1.0f/DIM);

    float d0x=v0.x-mu,d0y=v0.y-mu,d0z=v0.z-mu,d0w=v0.w-mu;
    float d1x=v1.x-mu,d1y=v1.y-mu,d1z=v1.z-mu,d1w=v1.w-mu;
    float q = d0x*d0x+d0y*d0y+d0z*d0z+d0w*d0w + d1x*d1x+d1y*d1y+d1z*d1z+d1w*d1w;
    #pragma unroll
    for (int o = 16; o; o >>= 1) q += __shfl_xor_sync(0xffffffffu, q, o);
    float rstd = rsqrtf(q * (1.0f/DIM) + EPS);

    const float4* gp = (const float4*)gamma;
    const float4* bp = (const float4*)beta;
    float4 g0 = gp[lane*2], g1 = gp[lane*2+1];
    float4 b0 = bp[lane*2], b1 = bp[lane*2+1];

    uint4 u;
    u.x = packh2(d0x*rstd*g0.x + b0.x, d0y*rstd*g0.y + b0.y);
    u.y = packh2(d0z*rstd*g0.z + b0.z, d0w*rstd*g0.w + b0.w);
    u.z = packh2(d1x*rstd*g1.x + b1.x, d1y*rstd*g1.y + b1.y);
    u.w = packh2(d1z*rstd*g1.z + b1.z, d1w*rstd*g1.w + b1.w);
    *(uint4*)&out[(size_t)row*DIM + lane*8] = u;
}

// ---------------- fp16 GEMM NT with cp.async 3-stage pipeline ---------------
// C[M,N] = A[M,K] * B[N,K]^T. Tile 128x64, K-chunk 32 halves, 256 threads.
// EPI: 0 = *oscale -> half, 1 = +res -> float, 2 = gelu(.+bias) -> half,
//      3 = +bias+res -> float
#define GSTR 20                 // uint32 stride per row chunk (16 used + 4 pad)
#define GSM_A (3*128*GSTR)
#define GSM_B (3*64*GSTR)
#define GEMM_SMEM_BYTES ((GSM_A + GSM_B)*4)
template<int EPI>
__global__ void __launch_bounds__(256) gemm_h(const __half* __restrict__ A,
                                              const __half* __restrict__ Bm,
                                              const float* __restrict__ bias,
                                              const float* __restrict__ res,
                                              void* __restrict__ Cout,
                                              int M, int N, int K, float oscale)
{
    extern __shared__ uint32_t smu[];
    uint32_t* sA = smu;
    uint32_t* sB = smu + GSM_A;
    const uint32_t sA_base = (uint32_t)__cvta_generic_to_shared(sA);
    const uint32_t sB_base = (uint32_t)__cvta_generic_to_shared(sB);

    const int tid  = threadIdx.x;
    const int m0   = blockIdx.y * 128;
    const int n0   = blockIdx.x * 64;
    const int lane = tid & 31;
    const int warp = tid >> 5;
    const int gr   = lane >> 2;
    const int gc   = lane & 3;
    const int wm   = warp >> 1;
    const int wn   = warp & 1;

    const int lrow = tid >> 2, lseg = tid & 3;   // fill coords

    float c[2][4][4];
    #pragma unroll
    for (int mi=0; mi<2; mi++)
        #pragma unroll
        for (int ni=0; ni<4; ni++)
            #pragma unroll
            for (int i=0; i<4; i++) c[mi][ni][i] = 0.f;

    auto fill = [&](int stage, int k0) {
        cp16(sA_base + (((stage*128 + lrow)*GSTR + lseg*4) << 2),
             A + (size_t)(m0 + lrow)*K + k0 + lseg*8);
        cp16(sA_base + (((stage*128 + lrow + 64)*GSTR + lseg*4) << 2),
             A + (size_t)(m0 + lrow + 64)*K + k0 + lseg*8);
        cp16(sB_base + (((stage*64 + lrow)*GSTR + lseg*4) << 2),
             Bm + (size_t)(n0 + lrow)*K + k0 + lseg*8);
    };

    auto compute = [&](int stage) {
        const uint32_t* pA = sA + (stage*128 + wm*32)*GSTR;
        const uint32_t* pB = sB + (stage*64  + wn*32)*GSTR;
        #pragma unroll
        for (int kc = 0; kc < 2; kc++) {
            const int kb = kc*8;
            uint32_t af[2][4], bf[4][2];
            #pragma unroll
            for (int mi = 0; mi < 2; mi++) {
                int r = mi*16 + gr;
                af[mi][0] = pA[ r   *GSTR + kb + gc    ];
                af[mi][1] = pA[(r+8)*GSTR + kb + gc    ];
                af[mi][2] = pA[ r   *GSTR + kb + gc + 4];
                af[mi][3] = pA[(r+8)*GSTR + kb + gc + 4];
            }
            #pragma unroll
            for (int ni = 0; ni < 4; ni++) {
                int r = ni*8 + gr;
                bf[ni][0] = pB[r*GSTR + kb + gc    ];
                bf[ni][1] = pB[r*GSTR + kb + gc + 4];
            }
            #pragma unroll
            for (int mi = 0; mi < 2; mi++)
                #pragma unroll
                for (int ni = 0; ni < 4; ni++)
                    mma_f16(c[mi][ni], af[mi], bf[ni][0], bf[ni][1]);
        }
    };

    const int nIter = K >> 5;
    fill(0, 0);  cp_commit();
    fill(1, 32); cp_commit();
    fill(2, 64); cp_commit();
    for (int it = 0; it < nIter; it++) {
        cp_wait<2>();
        __syncthreads();
        compute(it % 3);
        __syncthreads();
        if (it + 3 < nIter) fill(it % 3, (it+3)*32);
        cp_commit();
    }

    // epilogue (fp32 accumulators)
    #pragma unroll
    for (int ni = 0; ni < 4; ni++) {
        const int col = n0 + wn*32 + ni*8 + 2*gc;
        float2 bi = make_float2(0.f, 0.f);
        if (EPI == 2 || EPI == 3) bi = *(const float2*)&bias[col];
        #pragma unroll
        for (int mi = 0; mi < 2; mi++) {
            const int row0 = m0 + wm*32 + mi*16 + gr;
            #pragma unroll
            for (int hh2 = 0; hh2 < 2; hh2++) {
                const int row = row0 + hh2*8;
                float2 v = make_float2(c[mi][ni][hh2*2], c[mi][ni][hh2*2+1]);
                if (EPI == 0) { v.x *= oscale; v.y *= oscale; }
                if (EPI == 2) {
                    v.x += bi.x; v.y += bi.y;
                    v.x = 0.5f*v.x*(1.0f + erff(v.x*0.7071067811865475f));
                    v.y = 0.5f*v.y*(1.0f + erff(v.y*0.7071067811865475f));
                }
                if (EPI == 3) { v.x += bi.x; v.y += bi.y; }
                if (EPI == 1 || EPI == 3) {
                    float2 r = *(const float2*)&res[(size_t)row*N + col];
                    v.x += r.x; v.y += r.y;
                }
                if (EPI == 0 || EPI == 2) {
                    ((uint32_t*)Cout)[((size_t)row*N + col) >> 1] = packh2(v.x, v.y);
                } else {
                    *(float2*)&((float*)Cout)[(size_t)row*N + col] = v;
                }
            }
        }
    }
}

// ---------------- Differential attention: fp16 m16n8k16 tensor cores -------
// 128 queries/block, 256 threads (8 warps x 16 query rows). Half inputs.
#define KH_STRIDE 36   // uint32 stride per key row (32 used + pad)
#define VT_STRIDE 36   // uint32 stride per hd row
__global__ void __launch_bounds__(256) attn_tc(const __half* __restrict__ Q,
                                               const __half* __restrict__ Kg,
                                               const __half* __restrict__ Vg,
                                               const float* __restrict__ lq1,
                                               const float* __restrict__ lk1,
                                               const float* __restrict__ lq2,
                                               const float* __restrict__ lk2,
                                               __half* __restrict__ O)
{
    __shared__ uint32_t Kh[64*KH_STRIDE];  // 64 keys x 64 halves (both halves)
    __shared__ uint32_t Vt[32*VT_STRIDE];  // 32 hd x 64 keys (transposed)

    const int b    = blockIdx.z;
    const int h    = blockIdx.y;
    const int warp = threadIdx.x >> 5;
    const int lane = threadIdx.x & 31;
    const int gr   = lane >> 2;
    const int gc   = lane & 3;
    const int qw   = blockIdx.x * 128 + warp * 16;

    float d1 = 0.f, d2 = 0.f;
    #pragma unroll
    for (int i = 0; i < HD; i++) {
        d1 = fmaf(lq1[h*HD+i], lk1[h*HD+i], d1);
        d2 = fmaf(lq2[h*HD+i], lk2[h*HD+i], d2);
    }
    const float lam = expf(d1) - expf(d2) + LAMBDA_INIT;

    // Q fragments (already scaled by SCALE in projection). qh[half][kc][4]
    uint32_t qh[2][2][4];
    {
        const uint32_t* q0 = (const uint32_t*)(Q + ((size_t)(b*NN + qw + gr))*(2*DIM)) + h*32;
        const uint32_t* q8 = q0 + 8*(2*DIM/2);
        #pragma unroll
        for (int half = 0; half < 2; half++) {
            #pragma unroll
            for (int kc = 0; kc < 2; kc++) {
                int off = half*16 + kc*8 + gc;
                qh[half][kc][0] = q0[off];
                qh[half][kc][1] = q8[off];
                qh[half][kc][2] = q0[off+4];
                qh[half][kc][3] = q8[off+4];
            }
        }
    }

    float o[2][4][4];
    #pragma unroll
    for (int hf=0; hf<2; hf++)
        #pragma unroll
        for (int n=0; n<4; n++)
            #pragma unroll
            for (int i=0; i<4; i++) o[hf][n][i] = 0.f;
    float lsum[2][2] = {{0.f,0.f},{0.f,0.f}};

    const int t = threadIdx.x;
    for (int k0 = 0; k0 < NN; k0 += 64) {
        __syncthreads();
        // K tile: 64 keys x 64 halves = 512 x 16B chunks -> 2 per thread (FIXED)
        #pragma unroll
        for (int it = 0; it < 2; it++) {
            int i = t + it*256;
            int key = i >> 3, seg = i & 7;
            uint4 v = *(const uint4*)(Kg + ((size_t)(b*NN + k0 + key))*(2*DIM) + h*HD2 + seg*8);
            *(uint4*)&Kh[key*KH_STRIDE + seg*4] = v;
        }
        // V tile: 64 keys x 32 halves = 256 x 16B chunks -> 1 per thread, transposed
        {
            int key = t >> 2, q = t & 3;
            uint4 v = *(const uint4*)(Vg + ((size_t)(b*NN + k0 + key))*DIM + h*HD + q*8);
            __half* Vh = (__half*)Vt;
            uint32_t w[4] = {v.x, v.y, v.z, v.w};
            #pragma unroll
            for (int j = 0; j < 4; j++) {
                __half2 hv = *(__half2*)&w[j];
                Vh[(q*8 + j*2    )*(2*VT_STRIDE) + key] = __low2half(hv);
                Vh[(q*8 + j*2 + 1)*(2*VT_STRIDE) + key] = __high2half(hv);
            }
        }
        __syncthreads();

        uint32_t ph[2][4][4];
        #pragma unroll
        for (int half = 0; half < 2; half++) {
            float s[8][4];
            #pragma unroll
            for (int n=0;n<8;n++)
                #pragma unroll
                for (int i=0;i<4;i++) s[n][i] = 0.f;

            #pragma unroll
            for (int n = 0; n < 8; n++) {
                const uint32_t* krow = &Kh[(n*8 + gr)*KH_STRIDE + half*16];
                #pragma unroll
                for (int kc = 0; kc < 2; kc++) {
                    mma_f16(s[n], qh[half][kc], krow[kc*8 + gc], krow[kc*8 + gc + 4]);
                }
            }
            #pragma unroll
            for (int n = 0; n < 8; n++) {
                float p0 = __expf(s[n][0]);
                float p1 = __expf(s[n][1]);
                float p2 = __expf(s[n][2]);
                float p3 = __expf(s[n][3]);
                lsum[half][0] += p0 + p1;
                lsum[half][1] += p2 + p3;
                int ks = n >> 1, hi = (n & 1) * 2;
                ph[half][ks][hi    ] = packh2(p0, p1);
                ph[half][ks][hi + 1] = packh2(p2, p3);
            }
        }

        #pragma unroll
        for (int ks = 0; ks < 4; ks++) {
            #pragma unroll
            for (int n = 0; n < 4; n++) {
                uint32_t b0 = Vt[(n*8 + gr)*VT_STRIDE + ks*8 + gc    ];
                uint32_t b1 = Vt[(n*8 + gr)*VT_STRIDE + ks*8 + gc + 4];
                mma_f16(o[0][n], ph[0][ks], b0, b1);
                mma_f16(o[1][n], ph[1][ks], b0, b1);
            }
        }
    }

    #pragma unroll
    for (int hf = 0; hf < 2; hf++) {
        #pragma unroll
        for (int r2 = 0; r2 < 2; r2++) {
            float v = lsum[hf][r2];
            v += __shfl_xor_sync(0xffffffffu, v, 1);
            v += __shfl_xor_sync(0xffffffffu, v, 2);
            lsum[hf][r2] = v;
        }
    }
    const float i1A = 1.f / lsum[0][0];
    const float i1B = 1.f / lsum[0][1];
    const float s2A = lam / lsum[1][0];
    const float s2B = lam / lsum[1][1];

    uint32_t* outA = (uint32_t*)(O + ((size_t)(b*NN + qw + gr    ))*DIM + h*HD);
    uint32_t* outB = (uint32_t*)(O + ((size_t)(b*NN + qw + gr + 8))*DIM + h*HD);
    #pragma unroll
    for (int n = 0; n < 4; n++) {
        outA[(n*8 + 2*gc) >> 1] = packh2(o[0][n][0]*i1A - o[1][n][0]*s2A,
                                         o[0][n][1]*i1A - o[1][n][1]*s2A);
        outB[(n*8 + 2*gc) >> 1] = packh2(o[0][n][2]*i1B - o[1][n][2]*s2B,
                                         o[0][n][3]*i1B - o[1][n][3]*s2B);
    }
}

// ---------------- launch ----------------------------------------------------
static void* symp(const void* sym) {
    void* p = nullptr;
    cudaGetSymbolAddress(&p, sym);
    return p;
}

extern "C" void kernel_launch(void* const* d_in, const int* in_sizes, int n_in,
                              void* d_out, int out_size)
{
    const float* drift = (const float*)d_in[0];
    const float* ocean = (const float*)d_in[1];
    const float* Wq    = (const float*)d_in[2];
    const float* Wk    = (const float*)d_in[3];
    const float* Wv    = (const float*)d_in[4];
    const float* Wo    = (const float*)d_in[5];
    const float* lq1   = (const float*)d_in[6];
    const float* lk1   = (const float*)d_in[7];
    const float* lq2   = (const float*)d_in[8];
    const float* lk2   = (const float*)d_in[9];
    const float* gamma = (const float*)d_in[10];
    const float* beta  = (const float*)d_in[11];
    const float* fc1w  = (const float*)d_in[12];
    const float* fc1b  = (const float*)d_in[13];
    const float* fc2w  = (const float*)d_in[14];
    const float* fc2b  = (const float*)d_in[15];
    float* out = (float*)d_out;

    __half* hw   = (__half*)symp(g_hw);
    __half* hx   = (__half*)symp(g_hx);
    __half* hQ   = (__half*)symp(g_hQ);
    __half* hK   = (__half*)symp(g_hK);
    __half* hV   = (__half*)symp(g_hV);
    __half* hatt = (__half*)symp(g_hatt);
    __half* hy   = (__half*)symp(g_hy);
    __half* hh   = (__half*)symp(g_hh);

    cudaFuncSetAttribute(gemm_h<0>, cudaFuncAttributeMaxDynamicSharedMemorySize, GEMM_SMEM_BYTES);
    cudaFuncSetAttribute(gemm_h<1>, cudaFuncAttributeMaxDynamicSharedMemorySize, GEMM_SMEM_BYTES);
    cudaFuncSetAttribute(gemm_h<2>, cudaFuncAttributeMaxDynamicSharedMemorySize, GEMM_SMEM_BYTES);
    cudaFuncSetAttribute(gemm_h<3>, cudaFuncAttributeMaxDynamicSharedMemorySize, GEMM_SMEM_BYTES);

    // 0) convert ocean + weights to fp16
    cvt_kernel<<<(HW_TOTAL/4 + 255)/256, 256>>>(ocean, Wq, Wk, Wv, Wo, fc1w, fc2w, hw);
    // 1) x = LN(drift) -> half
    ln_half<<<ROWS/8, 256>>>(drift, hx, gamma, beta);
    // 2) Q = (x @ Wq^T) * SCALE
    gemm_h<0><<<dim3(512/64, ROWS/128), 256, GEMM_SMEM_BYTES>>>(hx, hw+WQ_OFF, nullptr, nullptr, hQ, ROWS, 512, 256, SCALE);
    // 3) K = ocean @ Wk^T
    gemm_h<0><<<dim3(512/64, ROWS/128), 256, GEMM_SMEM_BYTES>>>(hw+OC_OFF, hw+WK_OFF, nullptr, nullptr, hK, ROWS, 512, 256, 1.0f);
    // 4) V = ocean @ Wv^T
    gemm_h<0><<<dim3(256/64, ROWS/128), 256, GEMM_SMEM_BYTES>>>(hw+OC_OFF, hw+WV_OFF, nullptr, nullptr, hV, ROWS, 256, 256, 1.0f);
    // 5) differential attention
    attn_tc<<<dim3(NN/128, HH, BB), 256>>>(hQ, hK, hV, lq1, lk1, lq2, lk2, hatt);
    // 6) drift2 = drift + att @ Wo^T -> out (fp32)
    gemm_h<1><<<dim3(256/64, ROWS/128), 256, GEMM_SMEM_BYTES>>>(hatt, hw+WO_OFF, nullptr, drift, out, ROWS, 256, 256, 1.0f);
    // 7) y = LN(drift2) -> half
    ln_half<<<ROWS/8, 256>>>(out, hy, gamma, beta);
    // 8) h = gelu(y @ fc1^T + b1)
    gemm_h<2><<<dim3(1024/64, ROWS/128), 256, GEMM_SMEM_BYTES>>>(hy, hw+F1_OFF, fc1b, nullptr, hh, ROWS, 1024, 256, 1.0f);
    // 9) drift_out = drift2 + h @ fc2^T + b2 (in-place on out)
    gemm_h<3><<<dim3(256/64, ROWS/128), 256, GEMM_SMEM_BYTES>>>(hh, hw+F2_OFF, fc2b, out, out, ROWS, 256, 1024, 1.0f);
    // 10) ocean pass-through
    if (out_size >= 2 * ROWS * DIM) {
        cudaMemcpyAsync(out + (size_t)ROWS*DIM, ocean,
                        (size_t)ROWS*DIM*sizeof(float), cudaMemcpyDeviceToDevice);
    }
}

// round 8
// speedup vs baseline: 6.0903x; 1.0783x over previous
#include <cuda_runtime.h>
#include <cuda_fp16.h>
#include <math.h>
#include <stdint.h>

// Problem constants
#define BB    2
#define NN    2048
#define DIM   256
#define HH    8
#define HD    32
#define HD2   64
#define ROWS  (BB*NN)          // 4096
#define SCALE 0.17677669529663689f  // 32^-0.5
#define LAMBDA_INIT 0.1f
#define EPS   1e-5f

// ---------------- half weight/activation pool (static, no allocation) ------
#define OC_OFF   0u
#define WQ_OFF   1048576u
#define WK_OFF   1179648u      // Wk (512x256) then Wv (256x256) contiguous
#define WV_OFF   1310720u
#define WO_OFF   1376256u
#define F1_OFF   1441792u
#define F2_OFF   1703936u
#define HW_TOTAL 1966080u
__device__ __half g_hw [HW_TOTAL];     // ocean + all weights (fp16)
__device__ __half g_hx [ROWS*DIM];     // LN1 out
__device__ __half g_hQ [ROWS*2*DIM];   // Q (pre-scaled by SCALE)
__device__ __half g_hKV[ROWS*768];     // fused K(512) | V(256) per row
__device__ __half g_hatt[ROWS*DIM];
__device__ __half g_hy [ROWS*DIM];     // LN2 out
__device__ __half g_hh [ROWS*4*DIM];   // MLP hidden

// ---------------- helpers ---------------------------------------------------
__device__ __forceinline__ void mma_f16(float* d, const uint32_t* a,
                                        uint32_t b0, uint32_t b1) {
    asm volatile("mma.sync.aligned.m16n8k16.row.col.f32.f16.f16.f32 "
                 "{%0,%1,%2,%3},{%4,%5,%6,%7},{%8,%9},{%0,%1,%2,%3};"
                 : "+f"(d[0]), "+f"(d[1]), "+f"(d[2]), "+f"(d[3])
                 : "r"(a[0]), "r"(a[1]), "r"(a[2]), "r"(a[3]),
                   "r"(b0), "r"(b1));
}
__device__ __forceinline__ void ldsm4(uint32_t* r, uint32_t addr) {
    asm volatile("ldmatrix.sync.aligned.m8n8.x4.shared.b16 {%0,%1,%2,%3}, [%4];"
                 : "=r"(r[0]), "=r"(r[1]), "=r"(r[2]), "=r"(r[3]) : "r"(addr));
}
__device__ __forceinline__ uint32_t packh2(float x, float y) {
    __half2 h = __floats2half2_rn(x, y);
    return *reinterpret_cast<uint32_t*>(&h);
}
__device__ __forceinline__ void cp16(uint32_t saddr, const void* g) {
    asm volatile("cp.async.cg.shared.global [%0], [%1], 16;\n" :: "r"(saddr), "l"(g));
}
__device__ __forceinline__ void cp_commit() { asm volatile("cp.async.commit_group;\n"); }
template<int N> __device__ __forceinline__ void cp_wait() {
    asm volatile("cp.async.wait_group %0;\n" :: "n"(N));
}

// ---------------- fp32 -> fp16 conversion + ocean passthrough --------------
__global__ void __launch_bounds__(256) cvt_kernel(const float* __restrict__ oc,
    const float* __restrict__ wq, const float* __restrict__ wk,
    const float* __restrict__ wv, const float* __restrict__ wo,
    const float* __restrict__ f1, const float* __restrict__ f2,
    __half* __restrict__ dst, float* __restrict__ oout)
{
    uint32_t fi = ((uint32_t)blockIdx.x*256u + threadIdx.x)*4u;
    if (fi >= HW_TOTAL) return;
    const float* src; uint32_t base;
    if      (fi < WQ_OFF) { src = oc; base = OC_OFF; }
    else if (fi < WK_OFF) { src = wq; base = WQ_OFF; }
    else if (fi < WV_OFF) { src = wk; base = WK_OFF; }
    else if (fi < WO_OFF) { src = wv; base = WV_OFF; }
    else if (fi < F1_OFF) { src = wo; base = WO_OFF; }
    else if (fi < F2_OFF) { src = f1; base = F1_OFF; }
    else                  { src = f2; base = F2_OFF; }
    float4 v = *(const float4*)&src[fi - base];
    if (fi < WQ_OFF) *(float4*)&oout[fi] = v;   // ocean passthrough (fp32)
    uint2 u = make_uint2(packh2(v.x, v.y), packh2(v.z, v.w));
    *(uint2*)&dst[fi] = u;
}

// ---------------- LayerNorm: fp32 in, fp16 out ------------------------------
__global__ void __launch_bounds__(256) ln_half(const float* __restrict__ in,
                                               __half* __restrict__ out,
                                               const float* __restrict__ gamma,
                                               const float* __restrict__ beta)
{
    int wid  = threadIdx.x >> 5;
    int lane = threadIdx.x & 31;
    int row  = blockIdx.x * 8 + wid;
    const float4* p = (const float4*)(in + (size_t)row * DIM);
    float4 v0 = p[lane*2], v1 = p[lane*2+1];

    float s = v0.x+v0.y+v0.z+v0.w + v1.x+v1.y+v1.z+v1.w;
    #pragma unroll
    for (int o = 16; o; o >>= 1) s += __shfl_xor_sync(0xffffffffu, s, o);
    float mu = s * (1.0f/DIM);

    float d0x=v0.x-mu,d0y=v0.y-mu,d0z=v0.z-mu,d0w=v0.w-mu;
    float d1x=v1.x-mu,d1y=v1.y-mu,d1z=v1.z-mu,d1w=v1.w-mu;
    float q = d0x*d0x+d0y*d0y+d0z*d0z+d0w*d0w + d1x*d1x+d1y*d1y+d1z*d1z+d1w*d1w;
    #pragma unroll
    for (int o = 16; o; o >>= 1) q += __shfl_xor_sync(0xffffffffu, q, o);
    float rstd = rsqrtf(q * (1.0f/DIM) + EPS);

    const float4* gp = (const float4*)gamma;
    const float4* bp = (const float4*)beta;
    float4 g0 = gp[lane*2], g1 = gp[lane*2+1];
    float4 b0 = bp[lane*2], b1 = bp[lane*2+1];

    uint4 u;
    u.x = packh2(d0x*rstd*g0.x + b0.x, d0y*rstd*g0.y + b0.y);
    u.y = packh2(d0z*rstd*g0.z + b0.z, d0w*rstd*g0.w + b0.w);
    u.z = packh2(d1x*rstd*g1.x + b1.x, d1y*rstd*g1.y + b1.y);
    u.w = packh2(d1z*rstd*g1.z + b1.z, d1w*rstd*g1.w + b1.w);
    *(uint4*)&out[(size_t)row*DIM + lane*8] = u;
}

// ---------------- fp16 GEMM NT: cp.async 4-stage, ldmatrix, 1 sync/iter -----
// C[M,N] = A[M,K] * B[N,K]^T. Tile 128x64, K-chunk 32 halves, 256 threads.
// EPI: 0 = *oscale -> half, 1 = +res -> float, 2 = gelu(.+bias) -> half,
//      3 = +bias+res -> float
#define GSTR 20                 // uint32 stride per row chunk (16 used + 4 pad)
#define NSTAGE 4
#define GSM_A (NSTAGE*128*GSTR)
#define GSM_B (NSTAGE*64*GSTR)
#define GEMM_SMEM_BYTES ((GSM_A + GSM_B)*4)
template<int EPI>
__global__ void __launch_bounds__(256) gemm_h(const __half* __restrict__ A,
                                              const __half* __restrict__ Bm,
                                              const float* __restrict__ bias,
                                              const float* __restrict__ res,
                                              void* __restrict__ Cout,
                                              int M, int N, int K, float oscale)
{
    extern __shared__ uint32_t smu[];
    uint32_t* sA = smu;
    uint32_t* sB = smu + GSM_A;
    const uint32_t sA_base = (uint32_t)__cvta_generic_to_shared(sA);
    const uint32_t sB_base = (uint32_t)__cvta_generic_to_shared(sB);

    const int tid  = threadIdx.x;
    const int m0   = blockIdx.y * 128;
    const int n0   = blockIdx.x * 64;
    const int lane = tid & 31;
    const int warp = tid >> 5;
    const int gr   = lane >> 2;
    const int gc   = lane & 3;
    const int wm   = warp >> 1;
    const int wn   = warp & 1;

    const int lrow = tid >> 2, lseg = tid & 3;   // fill coords

    // ldmatrix lane addressing
    const int la = lane & 15,                 sa = lane >> 4;        // A
    const int lb = (lane & 7) + ((lane >> 4) << 3), sb = (lane >> 3) & 1;  // B

    float c[2][4][4];
    #pragma unroll
    for (int mi=0; mi<2; mi++)
        #pragma unroll
        for (int ni=0; ni<4; ni++)
            #pragma unroll
            for (int i=0; i<4; i++) c[mi][ni][i] = 0.f;

    auto fill = [&](int stage, int k0) {
        cp16(sA_base + (((stage*128 + lrow)*GSTR + lseg*4) << 2),
             A + (size_t)(m0 + lrow)*K + k0 + lseg*8);
        cp16(sA_base + (((stage*128 + lrow + 64)*GSTR + lseg*4) << 2),
             A + (size_t)(m0 + lrow + 64)*K + k0 + lseg*8);
        cp16(sB_base + (((stage*64 + lrow)*GSTR + lseg*4) << 2),
             Bm + (size_t)(n0 + lrow)*K + k0 + lseg*8);
    };

    auto compute = [&](int stage) {
        const uint32_t aBase = sA_base + (((stage*128 + wm*32)*GSTR) << 2);
        const uint32_t bBase = sB_base + (((stage*64  + wn*32)*GSTR) << 2);
        #pragma unroll
        for (int kc = 0; kc < 2; kc++) {
            const int kb = kc*8;
            uint32_t af[2][4], bf[2][4];
            #pragma unroll
            for (int mi = 0; mi < 2; mi++)
                ldsm4(af[mi], aBase + (((mi*16 + la)*GSTR + kb + sa*4) << 2));
            #pragma unroll
            for (int nj = 0; nj < 2; nj++)
                ldsm4(bf[nj], bBase + (((nj*16 + lb)*GSTR + kb + sb*4) << 2));
            #pragma unroll
            for (int mi = 0; mi < 2; mi++)
                #pragma unroll
                for (int ni = 0; ni < 4; ni++)
                    mma_f16(c[mi][ni], af[mi],
                            bf[ni>>1][(ni&1)*2], bf[ni>>1][(ni&1)*2+1]);
        }
    };

    const int nIter = K >> 5;
    fill(0, 0);  cp_commit();
    fill(1, 32); cp_commit();
    fill(2, 64); cp_commit();
    for (int it = 0; it < nIter; it++) {
        cp_wait<2>();
        __syncthreads();
        if (it + 3 < nIter) fill((it+3) & 3, (it+3)*32);
        cp_commit();
        compute(it & 3);
    }

    // epilogue (fp32 accumulators)
    #pragma unroll
    for (int ni = 0; ni < 4; ni++) {
        const int col = n0 + wn*32 + ni*8 + 2*gc;
        float2 bi = make_float2(0.f, 0.f);
        if (EPI == 2 || EPI == 3) bi = *(const float2*)&bias[col];
        #pragma unroll
        for (int mi = 0; mi < 2; mi++) {
            const int row0 = m0 + wm*32 + mi*16 + gr;
            #pragma unroll
            for (int hh2 = 0; hh2 < 2; hh2++) {
                const int row = row0 + hh2*8;
                float2 v = make_float2(c[mi][ni][hh2*2], c[mi][ni][hh2*2+1]);
                if (EPI == 0) { v.x *= oscale; v.y *= oscale; }
                if (EPI == 2) {
                    v.x += bi.x; v.y += bi.y;
                    v.x = 0.5f*v.x*(1.0f + erff(v.x*0.7071067811865475f));
                    v.y = 0.5f*v.y*(1.0f + erff(v.y*0.7071067811865475f));
                }
                if (EPI == 3) { v.x += bi.x; v.y += bi.y; }
                if (EPI == 1 || EPI == 3) {
                    float2 r = *(const float2*)&res[(size_t)row*N + col];
                    v.x += r.x; v.y += r.y;
                }
                if (EPI == 0 || EPI == 2) {
                    ((uint32_t*)Cout)[((size_t)row*N + col) >> 1] = packh2(v.x, v.y);
                } else {
                    *(float2*)&((float*)Cout)[(size_t)row*N + col] = v;
                }
            }
        }
    }
}

// ---------------- Differential attention: fp16 m16n8k16 tensor cores -------
// 128 queries/block, 256 threads. KV fused layout: row stride 768,
// K at cols [0,512), V at cols [512,768).
#define KH_STRIDE 36   // uint32 stride per key row (32 used + pad)
#define VT_STRIDE 36   // uint32 stride per hd row
#define KVS 768
__global__ void __launch_bounds__(256) attn_tc(const __half* __restrict__ Q,
                                               const __half* __restrict__ KV,
                                               const float* __restrict__ lq1,
                                               const float* __restrict__ lk1,
                                               const float* __restrict__ lq2,
                                               const float* __restrict__ lk2,
                                               __half* __restrict__ O)
{
    __shared__ uint32_t Kh[64*KH_STRIDE];  // 64 keys x 64 halves (both halves)
    __shared__ uint32_t Vt[32*VT_STRIDE];  // 32 hd x 64 keys (transposed)

    const int b    = blockIdx.z;
    const int h    = blockIdx.y;
    const int warp = threadIdx.x >> 5;
    const int lane = threadIdx.x & 31;
    const int gr   = lane >> 2;
    const int gc   = lane & 3;
    const int qw   = blockIdx.x * 128 + warp * 16;

    float d1 = 0.f, d2 = 0.f;
    #pragma unroll
    for (int i = 0; i < HD; i++) {
        d1 = fmaf(lq1[h*HD+i], lk1[h*HD+i], d1);
        d2 = fmaf(lq2[h*HD+i], lk2[h*HD+i], d2);
    }
    const float lam = expf(d1) - expf(d2) + LAMBDA_INIT;

    // Q fragments (already scaled by SCALE in projection). qh[half][kc][4]
    uint32_t qh[2][2][4];
    {
        const uint32_t* q0 = (const uint32_t*)(Q + ((size_t)(b*NN + qw + gr))*(2*DIM)) + h*32;
        const uint32_t* q8 = q0 + 8*(2*DIM/2);
        #pragma unroll
        for (int half = 0; half < 2; half++) {
            #pragma unroll
            for (int kc = 0; kc < 2; kc++) {
                int off = half*16 + kc*8 + gc;
                qh[half][kc][0] = q0[off];
                qh[half][kc][1] = q8[off];
                qh[half][kc][2] = q0[off+4];
                qh[half][kc][3] = q8[off+4];
            }
        }
    }

    float o[2][4][4];
    #pragma unroll
    for (int hf=0; hf<2; hf++)
        #pragma unroll
        for (int n=0; n<4; n++)
            #pragma unroll
            for (int i=0; i<4; i++) o[hf][n][i] = 0.f;
    float lsum[2][2] = {{0.f,0.f},{0.f,0.f}};

    const int t = threadIdx.x;
    for (int k0 = 0; k0 < NN; k0 += 64) {
        __syncthreads();
        // K tile: 64 keys x 64 halves = 512 x 16B chunks -> 2 per thread
        #pragma unroll
        for (int it = 0; it < 2; it++) {
            int i = t + it*256;
            int key = i >> 3, seg = i & 7;
            uint4 v = *(const uint4*)(KV + ((size_t)(b*NN + k0 + key))*KVS + h*HD2 + seg*8);
            *(uint4*)&Kh[key*KH_STRIDE + seg*4] = v;
        }
        // V tile: 64 keys x 32 halves -> 1 chunk per thread, transposed
        {
            int key = t >> 2, q = t & 3;
            uint4 v = *(const uint4*)(KV + ((size_t)(b*NN + k0 + key))*KVS + 512 + h*HD + q*8);
            __half* Vh = (__half*)Vt;
            uint32_t w[4] = {v.x, v.y, v.z, v.w};
            #pragma unroll
            for (int j = 0; j < 4; j++) {
                __half2 hv = *(__half2*)&w[j];
                Vh[(q*8 + j*2    )*(2*VT_STRIDE) + key] = __low2half(hv);
                Vh[(q*8 + j*2 + 1)*(2*VT_STRIDE) + key] = __high2half(hv);
            }
        }
        __syncthreads();

        uint32_t ph[2][4][4];
        #pragma unroll
        for (int half = 0; half < 2; half++) {
            float s[8][4];
            #pragma unroll
            for (int n=0;n<8;n++)
                #pragma unroll
                for (int i=0;i<4;i++) s[n][i] = 0.f;

            #pragma unroll
            for (int n = 0; n < 8; n++) {
                const uint32_t* krow = &Kh[(n*8 + gr)*KH_STRIDE + half*16];
                #pragma unroll
                for (int kc = 0; kc < 2; kc++) {
                    mma_f16(s[n], qh[half][kc], krow[kc*8 + gc], krow[kc*8 + gc + 4]);
                }
            }
            #pragma unroll
            for (int n = 0; n < 8; n++) {
                float p0 = __expf(s[n][0]);
                float p1 = __expf(s[n][1]);
                float p2 = __expf(s[n][2]);
                float p3 = __expf(s[n][3]);
                lsum[half][0] += p0 + p1;
                lsum[half][1] += p2 + p3;
                int ks = n >> 1, hi = (n & 1) * 2;
                ph[half][ks][hi    ] = packh2(p0, p1);
                ph[half][ks][hi + 1] = packh2(p2, p3);
            }
        }

        #pragma unroll
        for (int ks = 0; ks < 4; ks++) {
            #pragma unroll
            for (int n = 0; n < 4; n++) {
                uint32_t b0 = Vt[(n*8 + gr)*VT_STRIDE + ks*8 + gc    ];
                uint32_t b1 = Vt[(n*8 + gr)*VT_STRIDE + ks*8 + gc + 4];
                mma_f16(o[0][n], ph[0][ks], b0, b1);
                mma_f16(o[1][n], ph[1][ks], b0, b1);
            }
        }
    }

    #pragma unroll
    for (int hf = 0; hf < 2; hf++) {
        #pragma unroll
        for (int r2 = 0; r2 < 2; r2++) {
            float v = lsum[hf][r2];
            v += __shfl_xor_sync(0xffffffffu, v, 1);
            v += __shfl_xor_sync(0xffffffffu, v, 2);
            lsum[hf][r2] = v;
        }
    }
    const float i1A = 1.f / lsum[0][0];
    const float i1B = 1.f / lsum[0][1];
    const float s2A = lam / lsum[1][0];
    const float s2B = lam / lsum[1][1];

    uint32_t* outA = (uint32_t*)(O + ((size_t)(b*NN + qw + gr    ))*DIM + h*HD);
    uint32_t* outB = (uint32_t*)(O + ((size_t)(b*NN + qw + gr + 8))*DIM + h*HD);
    #pragma unroll
    for (int n = 0; n < 4; n++) {
        outA[(n*8 + 2*gc) >> 1] = packh2(o[0][n][0]*i1A - o[1][n][0]*s2A,
                                         o[0][n][1]*i1A - o[1][n][1]*s2A);
        outB[(n*8 + 2*gc) >> 1] = packh2(o[0][n][2]*i1B - o[1][n][2]*s2B,
                                         o[0][n][3]*i1B - o[1][n][3]*s2B);
    }
}

// ---------------- launch ----------------------------------------------------
static void* symp(const void* sym) {
    void* p = nullptr;
    cudaGetSymbolAddress(&p, sym);
    return p;
}

extern "C" void kernel_launch(void* const* d_in, const int* in_sizes, int n_in,
                              void* d_out, int out_size)
{
    const float* drift = (const float*)d_in[0];
    const float* ocean = (const float*)d_in[1];
    const float* Wq    = (const float*)d_in[2];
    const float* Wk    = (const float*)d_in[3];
    const float* Wv    = (const float*)d_in[4];
    const float* Wo    = (const float*)d_in[5];
    const float* lq1   = (const float*)d_in[6];
    const float* lk1   = (const float*)d_in[7];
    const float* lq2   = (const float*)d_in[8];
    const float* lk2   = (const float*)d_in[9];
    const float* gamma = (const float*)d_in[10];
    const float* beta  = (const float*)d_in[11];
    const float* fc1w  = (const float*)d_in[12];
    const float* fc1b  = (const float*)d_in[13];
    const float* fc2w  = (const float*)d_in[14];
    const float* fc2b  = (const float*)d_in[15];
    float* out = (float*)d_out;

    __half* hw   = (__half*)symp(g_hw);
    __half* hx   = (__half*)symp(g_hx);
    __half* hQ   = (__half*)symp(g_hQ);
    __half* hKV  = (__half*)symp(g_hKV);
    __half* hatt = (__half*)symp(g_hatt);
    __half* hy   = (__half*)symp(g_hy);
    __half* hh   = (__half*)symp(g_hh);

    cudaFuncSetAttribute(gemm_h<0>, cudaFuncAttributeMaxDynamicSharedMemorySize, GEMM_SMEM_BYTES);
    cudaFuncSetAttribute(gemm_h<1>, cudaFuncAttributeMaxDynamicSharedMemorySize, GEMM_SMEM_BYTES);
    cudaFuncSetAttribute(gemm_h<2>, cudaFuncAttributeMaxDynamicSharedMemorySize, GEMM_SMEM_BYTES);
    cudaFuncSetAttribute(gemm_h<3>, cudaFuncAttributeMaxDynamicSharedMemorySize, GEMM_SMEM_BYTES);

    // 0) convert ocean + weights to fp16; write ocean passthrough to out
    cvt_kernel<<<(HW_TOTAL/4 + 255)/256, 256>>>(ocean, Wq, Wk, Wv, Wo, fc1w, fc2w,
                                                hw, out + (size_t)ROWS*DIM);
    // 1) x = LN(drift) -> half
    ln_half<<<ROWS/8, 256>>>(drift, hx, gamma, beta);
    // 2) Q = (x @ Wq^T) * SCALE
    gemm_h<0><<<dim3(512/64, ROWS/128), 256, GEMM_SMEM_BYTES>>>(hx, hw+WQ_OFF, nullptr, nullptr, hQ, ROWS, 512, 256, SCALE);
    // 3) KV = ocean @ [Wk;Wv]^T   (fused, N=768)
    gemm_h<0><<<dim3(768/64, ROWS/128), 256, GEMM_SMEM_BYTES>>>(hw+OC_OFF, hw+WK_OFF, nullptr, nullptr, hKV, ROWS, 768, 256, 1.0f);
    // 4) differential attention
    attn_tc<<<dim3(NN/128, HH, BB), 256>>>(hQ, hKV, lq1, lk1, lq2, lk2, hatt);
    // 5) drift2 = drift + att @ Wo^T -> out (fp32)
    gemm_h<1><<<dim3(256/64, ROWS/128), 256, GEMM_SMEM_BYTES>>>(hatt, hw+WO_OFF, nullptr, drift, out, ROWS, 256, 256, 1.0f);
    // 6) y = LN(drift2) -> half
    ln_half<<<ROWS/8, 256>>>(out, hy, gamma, beta);
    // 7) h = gelu(y @ fc1^T + b1)
    gemm_h<2><<<dim3(1024/64, ROWS/128), 256, GEMM_SMEM_BYTES>>>(hy, hw+F1_OFF, fc1b, nullptr, hh, ROWS, 1024, 256, 1.0f);
    // 8) drift_out = drift2 + h @ fc2^T + b2 (in-place on out)
    gemm_h<3><<<dim3(256/64, ROWS/128), 256, GEMM_SMEM_BYTES>>>(hh, hw+F2_OFF, fc2b, out, out, ROWS, 256, 1024, 1.0f);
}

// round 9
// speedup vs baseline: 6.1679x; 1.0127x over previous
#include <cuda_runtime.h>
#include <cuda_fp16.h>
#include <math.h>
#include <stdint.h>

// Problem constants
#define BB    2
#define NN    2048
#define DIM   256
#define HH    8
#define HD    32
#define HD2   64
#define ROWS  (BB*NN)          // 4096
#define SCALE 0.17677669529663689f  // 32^-0.5
#define LOG2E 1.4426950408889634f
#define LAMBDA_INIT 0.1f
#define EPS   1e-5f

// ---------------- half weight/activation pool (static, no allocation) ------
#define OC_OFF   0u
#define WQ_OFF   1048576u
#define WK_OFF   1179648u      // Wk (512x256) then Wv (256x256) contiguous
#define WV_OFF   1310720u
#define WO_OFF   1376256u
#define F1_OFF   1441792u
#define F2_OFF   1703936u
#define HW_TOTAL 1966080u
__device__ __half g_hw [HW_TOTAL];     // ocean + all weights (fp16)
__device__ __half g_hx [ROWS*DIM];     // LN1 out
__device__ __half g_hQ [ROWS*2*DIM];   // Q (pre-scaled by SCALE*LOG2E)
__device__ __half g_hKV[ROWS*768];     // fused K(512) | V(256) per row
__device__ __half g_hatt[ROWS*DIM];
__device__ __half g_hy [ROWS*DIM];     // LN2 out
__device__ __half g_hh [ROWS*4*DIM];   // MLP hidden

// ---------------- helpers ---------------------------------------------------
__device__ __forceinline__ void mma_f16(float* d, const uint32_t* a,
                                        uint32_t b0, uint32_t b1) {
    asm volatile("mma.sync.aligned.m16n8k16.row.col.f32.f16.f16.f32 "
                 "{%0,%1,%2,%3},{%4,%5,%6,%7},{%8,%9},{%0,%1,%2,%3};"
                 : "+f"(d[0]), "+f"(d[1]), "+f"(d[2]), "+f"(d[3])
                 : "r"(a[0]), "r"(a[1]), "r"(a[2]), "r"(a[3]),
                   "r"(b0), "r"(b1));
}
__device__ __forceinline__ void ldsm4(uint32_t* r, uint32_t addr) {
    asm volatile("ldmatrix.sync.aligned.m8n8.x4.shared.b16 {%0,%1,%2,%3}, [%4];"
                 : "=r"(r[0]), "=r"(r[1]), "=r"(r[2]), "=r"(r[3]) : "r"(addr));
}
__device__ __forceinline__ uint32_t packh2(float x, float y) {
    __half2 h = __floats2half2_rn(x, y);
    return *reinterpret_cast<uint32_t*>(&h);
}
__device__ __forceinline__ float ex2f(float x) {
    float y;
    asm("ex2.approx.f32 %0, %1;" : "=f"(y) : "f"(x));
    return y;
}
__device__ __forceinline__ void cp16(uint32_t saddr, const void* g) {
    asm volatile("cp.async.cg.shared.global [%0], [%1], 16;\n" :: "r"(saddr), "l"(g));
}
__device__ __forceinline__ void cp_commit() { asm volatile("cp.async.commit_group;\n"); }
template<int N> __device__ __forceinline__ void cp_wait() {
    asm volatile("cp.async.wait_group %0;\n" :: "n"(N));
}

// ---------------- fp32 -> fp16 conversion + ocean passthrough --------------
__global__ void __launch_bounds__(256) cvt_kernel(const float* __restrict__ oc,
    const float* __restrict__ wq, const float* __restrict__ wk,
    const float* __restrict__ wv, const float* __restrict__ wo,
    const float* __restrict__ f1, const float* __restrict__ f2,
    __half* __restrict__ dst, float* __restrict__ oout)
{
    uint32_t fi = ((uint32_t)blockIdx.x*256u + threadIdx.x)*4u;
    if (fi >= HW_TOTAL) return;
    const float* src; uint32_t base;
    if      (fi < WQ_OFF) { src = oc; base = OC_OFF; }
    else if (fi < WK_OFF) { src = wq; base = WQ_OFF; }
    else if (fi < WV_OFF) { src = wk; base = WK_OFF; }
    else if (fi < WO_OFF) { src = wv; base = WV_OFF; }
    else if (fi < F1_OFF) { src = wo; base = WO_OFF; }
    else if (fi < F2_OFF) { src = f1; base = F1_OFF; }
    else                  { src = f2; base = F2_OFF; }
    float4 v = *(const float4*)&src[fi - base];
    if (fi < WQ_OFF) *(float4*)&oout[fi] = v;   // ocean passthrough (fp32)
    uint2 u = make_uint2(packh2(v.x, v.y), packh2(v.z, v.w));
    *(uint2*)&dst[fi] = u;
}

// ---------------- LayerNorm: fp32 in, fp16 out ------------------------------
__global__ void __launch_bounds__(256) ln_half(const float* __restrict__ in,
                                               __half* __restrict__ out,
                                               const float* __restrict__ gamma,
                                               const float* __restrict__ beta)
{
    int wid  = threadIdx.x >> 5;
    int lane = threadIdx.x & 31;
    int row  = blockIdx.x * 8 + wid;
    const float4* p = (const float4*)(in + (size_t)row * DIM);
    float4 v0 = p[lane*2], v1 = p[lane*2+1];

    float s = v0.x+v0.y+v0.z+v0.w + v1.x+v1.y+v1.z+v1.w;
    #pragma unroll
    for (int o = 16; o; o >>= 1) s += __shfl_xor_sync(0xffffffffu, s, o);
    float mu = s * (1.0f/DIM);

    float d0x=v0.x-mu,d0y=v0.y-mu,d0z=v0.z-mu,d0w=v0.w-mu;
    float d1x=v1.x-mu,d1y=v1.y-mu,d1z=v1.z-mu,d1w=v1.w-mu;
    float q = d0x*d0x+d0y*d0y+d0z*d0z+d0w*d0w + d1x*d1x+d1y*d1y+d1z*d1z+d1w*d1w;
    #pragma unroll
    for (int o = 16; o; o >>= 1) q += __shfl_xor_sync(0xffffffffu, q, o);
    float rstd = rsqrtf(q * (1.0f/DIM) + EPS);

    const float4* gp = (const float4*)gamma;
    const float4* bp = (const float4*)beta;
    float4 g0 = gp[lane*2], g1 = gp[lane*2+1];
    float4 b0 = bp[lane*2], b1 = bp[lane*2+1];

    uint4 u;
    u.x = packh2(d0x*rstd*g0.x + b0.x, d0y*rstd*g0.y + b0.y);
    u.y = packh2(d0z*rstd*g0.z + b0.z, d0w*rstd*g0.w + b0.w);
    u.z = packh2(d1x*rstd*g1.x + b1.x, d1y*rstd*g1.y + b1.y);
    u.w = packh2(d1z*rstd*g1.z + b1.z, d1w*rstd*g1.w + b1.w);
    *(uint4*)&out[(size_t)row*DIM + lane*8] = u;
}

// ---------------- fp16 GEMM NT: cp.async 4-stage, ldmatrix, 1 sync/iter -----
// C[M,N] = A[M,K] * B[N,K]^T. Tile 128xBN (BN=64 or 128), K-chunk 32 halves,
// 256 threads = 8 warps as 4(M) x 2(N); warp tile 32 x BN/2.
// EPI: 0 = *oscale -> half, 1 = +res -> float, 2 = gelu(.+bias) -> half,
//      3 = +bias+res -> float
#define GSTR 20                 // uint32 stride per row chunk (16 used + 4 pad)
#define NSTAGE 4
template<int EPI, int BN>
__global__ void __launch_bounds__(256) gemm_h(const __half* __restrict__ A,
                                              const __half* __restrict__ Bm,
                                              const float* __restrict__ bias,
                                              const float* __restrict__ res,
                                              void* __restrict__ Cout,
                                              int M, int N, int K, float oscale)
{
    constexpr int NI = BN/16;       // n8 tiles per warp
    constexpr int NJ = BN/32;       // n16 ldsm tiles per warp
    constexpr int GSM_A = NSTAGE*128*GSTR;

    extern __shared__ uint32_t smu[];
    uint32_t* sA = smu;
    uint32_t* sB = smu + GSM_A;
    const uint32_t sA_base = (uint32_t)__cvta_generic_to_shared(sA);
    const uint32_t sB_base = (uint32_t)__cvta_generic_to_shared(sB);

    const int tid  = threadIdx.x;
    const int m0   = blockIdx.y * 128;
    const int n0   = blockIdx.x * BN;
    const int lane = tid & 31;
    const int warp = tid >> 5;
    const int gr   = lane >> 2;
    const int gc   = lane & 3;
    const int wm   = warp >> 1;
    const int wn   = warp & 1;

    const int lrow = tid >> 2, lseg = tid & 3;   // fill coords

    // ldmatrix lane addressing
    const int la = lane & 15,                 sa = lane >> 4;        // A
    const int lb = (lane & 7) + ((lane >> 4) << 3), sb = (lane >> 3) & 1;  // B

    float c[2][NI][4];
    #pragma unroll
    for (int mi=0; mi<2; mi++)
        #pragma unroll
        for (int ni=0; ni<NI; ni++)
            #pragma unroll
            for (int i=0; i<4; i++) c[mi][ni][i] = 0.f;

    auto fill = [&](int stage, int k0) {
        cp16(sA_base + (((stage*128 + lrow)*GSTR + lseg*4) << 2),
             A + (size_t)(m0 + lrow)*K + k0 + lseg*8);
        cp16(sA_base + (((stage*128 + lrow + 64)*GSTR + lseg*4) << 2),
             A + (size_t)(m0 + lrow + 64)*K + k0 + lseg*8);
        cp16(sB_base + (((stage*BN + lrow)*GSTR + lseg*4) << 2),
             Bm + (size_t)(n0 + lrow)*K + k0 + lseg*8);
        if (BN == 128)
            cp16(sB_base + (((stage*BN + lrow + 64)*GSTR + lseg*4) << 2),
                 Bm + (size_t)(n0 + lrow + 64)*K + k0 + lseg*8);
    };

    auto compute = [&](int stage) {
        const uint32_t aBase = sA_base + (((stage*128 + wm*32)*GSTR) << 2);
        const uint32_t bBase = sB_base + (((stage*BN + wn*(BN/2))*GSTR) << 2);
        #pragma unroll
        for (int kc = 0; kc < 2; kc++) {
            const int kb = kc*8;
            uint32_t af[2][4], bf[NJ][4];
            #pragma unroll
            for (int mi = 0; mi < 2; mi++)
                ldsm4(af[mi], aBase + (((mi*16 + la)*GSTR + kb + sa*4) << 2));
            #pragma unroll
            for (int nj = 0; nj < NJ; nj++)
                ldsm4(bf[nj], bBase + (((nj*16 + lb)*GSTR + kb + sb*4) << 2));
            #pragma unroll
            for (int mi = 0; mi < 2; mi++)
                #pragma unroll
                for (int ni = 0; ni < NI; ni++)
                    mma_f16(c[mi][ni], af[mi],
                            bf[ni>>1][(ni&1)*2], bf[ni>>1][(ni&1)*2+1]);
        }
    };

    const int nIter = K >> 5;
    fill(0, 0);  cp_commit();
    fill(1, 32); cp_commit();
    fill(2, 64); cp_commit();
    for (int it = 0; it < nIter; it++) {
        cp_wait<2>();
        __syncthreads();
        if (it + 3 < nIter) fill((it+3) & 3, (it+3)*32);
        cp_commit();
        compute(it & 3);
    }

    // epilogue (fp32 accumulators)
    #pragma unroll
    for (int ni = 0; ni < NI; ni++) {
        const int col = n0 + wn*(BN/2) + ni*8 + 2*gc;
        float2 bi = make_float2(0.f, 0.f);
        if (EPI == 2 || EPI == 3) bi = *(const float2*)&bias[col];
        #pragma unroll
        for (int mi = 0; mi < 2; mi++) {
            const int row0 = m0 + wm*32 + mi*16 + gr;
            #pragma unroll
            for (int hh2 = 0; hh2 < 2; hh2++) {
                const int row = row0 + hh2*8;
                float2 v = make_float2(c[mi][ni][hh2*2], c[mi][ni][hh2*2+1]);
                if (EPI == 0) { v.x *= oscale; v.y *= oscale; }
                if (EPI == 2) {
                    v.x += bi.x; v.y += bi.y;
                    v.x = 0.5f*v.x*(1.0f + erff(v.x*0.7071067811865475f));
                    v.y = 0.5f*v.y*(1.0f + erff(v.y*0.7071067811865475f));
                }
                if (EPI == 3) { v.x += bi.x; v.y += bi.y; }
                if (EPI == 1 || EPI == 3) {
                    float2 r = *(const float2*)&res[(size_t)row*N + col];
                    v.x += r.x; v.y += r.y;
                }
                if (EPI == 0 || EPI == 2) {
                    ((uint32_t*)Cout)[((size_t)row*N + col) >> 1] = packh2(v.x, v.y);
                } else {
                    *(float2*)&((float*)Cout)[(size_t)row*N + col] = v;
                }
            }
        }
    }
}
#define GEMM_SMEM(BN) ((NSTAGE*128*GSTR + NSTAGE*(BN)*GSTR)*4)

// ---------------- Differential attention: fp16 m16n8k16 tensor cores -------
// 128 queries/block, 256 threads. KV fused layout: row stride 768,
// K at cols [0,512), V at cols [512,768).
// Q pre-scaled by SCALE*LOG2E so P = ex2(S) directly.
#define KH_STRIDE 36   // uint32 stride per key row (32 used + pad)
#define VT_STRIDE 36   // uint32 stride per hd row
#define KVS 768
__global__ void __launch_bounds__(256) attn_tc(const __half* __restrict__ Q,
                                               const __half* __restrict__ KV,
                                               const float* __restrict__ lq1,
                                               const float* __restrict__ lk1,
                                               const float* __restrict__ lq2,
                                               const float* __restrict__ lk2,
                                               __half* __restrict__ O)
{
    __shared__ uint32_t Kh[64*KH_STRIDE];  // 64 keys x 64 halves (both halves)
    __shared__ uint32_t Vt[32*VT_STRIDE];  // 32 hd x 64 keys (transposed)

    const int b    = blockIdx.z;
    const int h    = blockIdx.y;
    const int warp = threadIdx.x >> 5;
    const int lane = threadIdx.x & 31;
    const int gr   = lane >> 2;
    const int gc   = lane & 3;
    const int qw   = blockIdx.x * 128 + warp * 16;

    float d1 = 0.f, d2 = 0.f;
    #pragma unroll
    for (int i = 0; i < HD; i++) {
        d1 = fmaf(lq1[h*HD+i], lk1[h*HD+i], d1);
        d2 = fmaf(lq2[h*HD+i], lk2[h*HD+i], d2);
    }
    const float lam = expf(d1) - expf(d2) + LAMBDA_INIT;

    // Q fragments (pre-scaled). qh[half][kc][4]
    uint32_t qh[2][2][4];
    {
        const uint32_t* q0 = (const uint32_t*)(Q + ((size_t)(b*NN + qw + gr))*(2*DIM)) + h*32;
        const uint32_t* q8 = q0 + 8*(2*DIM/2);
        #pragma unroll
        for (int half = 0; half < 2; half++) {
            #pragma unroll
            for (int kc = 0; kc < 2; kc++) {
                int off = half*16 + kc*8 + gc;
                qh[half][kc][0] = q0[off];
                qh[half][kc][1] = q8[off];
                qh[half][kc][2] = q0[off+4];
                qh[half][kc][3] = q8[off+4];
            }
        }
    }

    float o[2][4][4];
    #pragma unroll
    for (int hf=0; hf<2; hf++)
        #pragma unroll
        for (int n=0; n<4; n++)
            #pragma unroll
            for (int i=0; i<4; i++) o[hf][n][i] = 0.f;
    float lsum[2][2] = {{0.f,0.f},{0.f,0.f}};

    const int t = threadIdx.x;
    for (int k0 = 0; k0 < NN; k0 += 64) {
        __syncthreads();
        // K tile: 64 keys x 64 halves = 512 x 16B chunks -> 2 per thread
        #pragma unroll
        for (int it = 0; it < 2; it++) {
            int i = t + it*256;
            int key = i >> 3, seg = i & 7;
            uint4 v = *(const uint4*)(KV + ((size_t)(b*NN + k0 + key))*KVS + h*HD2 + seg*8);
            *(uint4*)&Kh[key*KH_STRIDE + seg*4] = v;
        }
        // V tile: 64 keys x 32 halves -> 1 chunk per thread, transposed
        {
            int key = t >> 2, q = t & 3;
            uint4 v = *(const uint4*)(KV + ((size_t)(b*NN + k0 + key))*KVS + 512 + h*HD + q*8);
            __half* Vh = (__half*)Vt;
            uint32_t w[4] = {v.x, v.y, v.z, v.w};
            #pragma unroll
            for (int j = 0; j < 4; j++) {
                __half2 hv = *(__half2*)&w[j];
                Vh[(q*8 + j*2    )*(2*VT_STRIDE) + key] = __low2half(hv);
                Vh[(q*8 + j*2 + 1)*(2*VT_STRIDE) + key] = __high2half(hv);
            }
        }
        __syncthreads();

        uint32_t ph[2][4][4];
        #pragma unroll
        for (int half = 0; half < 2; half++) {
            float s[8][4];
            #pragma unroll
            for (int n=0;n<8;n++)
                #pragma unroll
                for (int i=0;i<4;i++) s[n][i] = 0.f;

            #pragma unroll
            for (int n = 0; n < 8; n++) {
                const uint32_t* krow = &Kh[(n*8 + gr)*KH_STRIDE + half*16];
                #pragma unroll
                for (int kc = 0; kc < 2; kc++) {
                    mma_f16(s[n], qh[half][kc], krow[kc*8 + gc], krow[kc*8 + gc + 4]);
                }
            }
            #pragma unroll
            for (int n = 0; n < 8; n++) {
                float p0 = ex2f(s[n][0]);
                float p1 = ex2f(s[n][1]);
                float p2 = ex2f(s[n][2]);
                float p3 = ex2f(s[n][3]);
                lsum[half][0] += p0 + p1;
                lsum[half][1] += p2 + p3;
                int ks = n >> 1, hi = (n & 1) * 2;
                ph[half][ks][hi    ] = packh2(p0, p1);
                ph[half][ks][hi + 1] = packh2(p2, p3);
            }
        }

        #pragma unroll
        for (int ks = 0; ks < 4; ks++) {
            #pragma unroll
            for (int n = 0; n < 4; n++) {
                uint32_t b0 = Vt[(n*8 + gr)*VT_STRIDE + ks*8 + gc    ];
                uint32_t b1 = Vt[(n*8 + gr)*VT_STRIDE + ks*8 + gc + 4];
                mma_f16(o[0][n], ph[0][ks], b0, b1);
                mma_f16(o[1][n], ph[1][ks], b0, b1);
            }
        }
    }

    #pragma unroll
    for (int hf = 0; hf < 2; hf++) {
        #pragma unroll
        for (int r2 = 0; r2 < 2; r2++) {
            float v = lsum[hf][r2];
            v += __shfl_xor_sync(0xffffffffu, v, 1);
            v += __shfl_xor_sync(0xffffffffu, v, 2);
            lsum[hf][r2] = v;
        }
    }
    const float i1A = 1.f / lsum[0][0];
    const float i1B = 1.f / lsum[0][1];
    const float s2A = lam / lsum[1][0];
    const float s2B = lam / lsum[1][1];

    uint32_t* outA = (uint32_t*)(O + ((size_t)(b*NN + qw + gr    ))*DIM + h*HD);
    uint32_t* outB = (uint32_t*)(O + ((size_t)(b*NN + qw + gr + 8))*DIM + h*HD);
    #pragma unroll
    for (int n = 0; n < 4; n++) {
        outA[(n*8 + 2*gc) >> 1] = packh2(o[0][n][0]*i1A - o[1][n][0]*s2A,
                                         o[0][n][1]*i1A - o[1][n][1]*s2A);
        outB[(n*8 + 2*gc) >> 1] = packh2(o[0][n][2]*i1B - o[1][n][2]*s2B,
                                         o[0][n][3]*i1B - o[1][n][3]*s2B);
    }
}

// ---------------- launch ----------------------------------------------------
static void* symp(const void* sym) {
    void* p = nullptr;
    cudaGetSymbolAddress(&p, sym);
    return p;
}

extern "C" void kernel_launch(void* const* d_in, const int* in_sizes, int n_in,
                              void* d_out, int out_size)
{
    const float* drift = (const float*)d_in[0];
    const float* ocean = (const float*)d_in[1];
    const float* Wq    = (const float*)d_in[2];
    const float* Wk    = (const float*)d_in[3];
    const float* Wv    = (const float*)d_in[4];
    const float* Wo    = (const float*)d_in[5];
    const float* lq1   = (const float*)d_in[6];
    const float* lk1   = (const float*)d_in[7];
    const float* lq2   = (const float*)d_in[8];
    const float* lk2   = (const float*)d_in[9];
    const float* gamma = (const float*)d_in[10];
    const float* beta  = (const float*)d_in[11];
    const float* fc1w  = (const float*)d_in[12];
    const float* fc1b  = (const float*)d_in[13];
    const float* fc2w  = (const float*)d_in[14];
    const float* fc2b  = (const float*)d_in[15];
    float* out = (float*)d_out;

    __half* hw   = (__half*)symp(g_hw);
    __half* hx   = (__half*)symp(g_hx);
    __half* hQ   = (__half*)symp(g_hQ);
    __half* hKV  = (__half*)symp(g_hKV);
    __half* hatt = (__half*)symp(g_hatt);
    __half* hy   = (__half*)symp(g_hy);
    __half* hh   = (__half*)symp(g_hh);

    cudaFuncSetAttribute((const void*)gemm_h<0,128>, cudaFuncAttributeMaxDynamicSharedMemorySize, GEMM_SMEM(128));
    cudaFuncSetAttribute((const void*)gemm_h<1,64>,  cudaFuncAttributeMaxDynamicSharedMemorySize, GEMM_SMEM(64));
    cudaFuncSetAttribute((const void*)gemm_h<2,128>, cudaFuncAttributeMaxDynamicSharedMemorySize, GEMM_SMEM(128));
    cudaFuncSetAttribute((const void*)gemm_h<3,64>,  cudaFuncAttributeMaxDynamicSharedMemorySize, GEMM_SMEM(64));

    // 0) convert ocean + weights to fp16; write ocean passthrough to out
    cvt_kernel<<<(HW_TOTAL/4 + 255)/256, 256>>>(ocean, Wq, Wk, Wv, Wo, fc1w, fc2w,
                                                hw, out + (size_t)ROWS*DIM);
    // 1) x = LN(drift) -> half
    ln_half<<<ROWS/8, 256>>>(drift, hx, gamma, beta);
    // 2) Q = (x @ Wq^T) * SCALE*LOG2E
    gemm_h<0,128><<<dim3(512/128, ROWS/128), 256, GEMM_SMEM(128)>>>(hx, hw+WQ_OFF, nullptr, nullptr, hQ, ROWS, 512, 256, SCALE*LOG2E);
    // 3) KV = ocean @ [Wk;Wv]^T   (fused, N=768)
    gemm_h<0,128><<<dim3(768/128, ROWS/128), 256, GEMM_SMEM(128)>>>(hw+OC_OFF, hw+WK_OFF, nullptr, nullptr, hKV, ROWS, 768, 256, 1.0f);
    // 4) differential attention
    attn_tc<<<dim3(NN/128, HH, BB), 256>>>(hQ, hKV, lq1, lk1, lq2, lk2, hatt);
    // 5) drift2 = drift + att @ Wo^T -> out (fp32)
    gemm_h<1,64><<<dim3(256/64, ROWS/128), 256, GEMM_SMEM(64)>>>(hatt, hw+WO_OFF, nullptr, drift, out, ROWS, 256, 256, 1.0f);
    // 6) y = LN(drift2) -> half
    ln_half<<<ROWS/8, 256>>>(out, hy, gamma, beta);
    // 7) h = gelu(y @ fc1^T + b1)
    gemm_h<2,128><<<dim3(1024/128, ROWS/128), 256, GEMM_SMEM(128)>>>(hy, hw+F1_OFF, fc1b, nullptr, hh, ROWS, 1024, 256, 1.0f);
    // 8) drift_out = drift2 + h @ fc2^T + b2 (in-place on out)
    gemm_h<3,64><<<dim3(256/64, ROWS/128), 256, GEMM_SMEM(64)>>>(hh, hw+F2_OFF, fc2b, out, out, ROWS, 256, 1024, 1.0f);
}

// round 11
// speedup vs baseline: 6.6431x; 1.0770x over previous
#include <cuda_runtime.h>
#include <cuda_fp16.h>
#include <math.h>
#include <stdint.h>

// Problem constants
#define BB    2
#define NN    2048
#define DIM   256
#define HH    8
#define HD    32
#define HD2   64
#define ROWS  (BB*NN)          // 4096
#define SCALE 0.17677669529663689f  // 32^-0.5
#define LOG2E 1.4426950408889634f
#define LAMBDA_INIT 0.1f
#define EPS   1e-5f

// ---------------- half weight/activation pool (static, no allocation) ------
#define OC_OFF   0u
#define WQ_OFF   1048576u
#define WK_OFF   1179648u      // Wk (512x256) then Wv (256x256) contiguous
#define WV_OFF   1310720u
#define WO_OFF   1376256u
#define F1_OFF   1441792u
#define F2_OFF   1703936u
#define HW_TOTAL 1966080u
__device__ __half g_hw [HW_TOTAL];     // ocean + all weights (fp16)
__device__ __half g_hx [ROWS*DIM];     // LN1 out
__device__ __half g_hQ [ROWS*2*DIM];   // Q (pre-scaled by SCALE*LOG2E)
__device__ __half g_hKV[ROWS*768];     // fused K(512) | V(256) per row
__device__ __half g_hatt[ROWS*DIM];
__device__ __half g_hy [ROWS*DIM];     // LN2 out
__device__ __half g_hh [ROWS*4*DIM];   // MLP hidden

// ---------------- helpers ---------------------------------------------------
__device__ __forceinline__ void mma_f16(float* d, const uint32_t* a,
                                        uint32_t b0, uint32_t b1) {
    asm volatile("mma.sync.aligned.m16n8k16.row.col.f32.f16.f16.f32 "
                 "{%0,%1,%2,%3},{%4,%5,%6,%7},{%8,%9},{%0,%1,%2,%3};"
                 : "+f"(d[0]), "+f"(d[1]), "+f"(d[2]), "+f"(d[3])
                 : "r"(a[0]), "r"(a[1]), "r"(a[2]), "r"(a[3]),
                   "r"(b0), "r"(b1));
}
__device__ __forceinline__ void ldsm4(uint32_t* r, uint32_t addr) {
    asm volatile("ldmatrix.sync.aligned.m8n8.x4.shared.b16 {%0,%1,%2,%3}, [%4];"
                 : "=r"(r[0]), "=r"(r[1]), "=r"(r[2]), "=r"(r[3]) : "r"(addr));
}
__device__ __forceinline__ uint32_t packh2(float x, float y) {
    __half2 h = __floats2half2_rn(x, y);
    return *reinterpret_cast<uint32_t*>(&h);
}
__device__ __forceinline__ float ex2f(float x) {
    float y;
    asm("ex2.approx.f32 %0, %1;" : "=f"(y) : "f"(x));
    return y;
}
__device__ __forceinline__ void cp16(uint32_t saddr, const void* g) {
    asm volatile("cp.async.cg.shared.global [%0], [%1], 16;\n" :: "r"(saddr), "l"(g));
}
__device__ __forceinline__ void cp_commit() { asm volatile("cp.async.commit_group;\n"); }
template<int N> __device__ __forceinline__ void cp_wait() {
    asm volatile("cp.async.wait_group %0;\n" :: "n"(N));
}

// ---------------- fp32 -> fp16 conversion + ocean passthrough --------------
__global__ void __launch_bounds__(256) cvt_kernel(const float* __restrict__ oc,
    const float* __restrict__ wq, const float* __restrict__ wk,
    const float* __restrict__ wv, const float* __restrict__ wo,
    const float* __restrict__ f1, const float* __restrict__ f2,
    __half* __restrict__ dst, float* __restrict__ oout)
{
    uint32_t fi = ((uint32_t)blockIdx.x*256u + threadIdx.x)*4u;
    if (fi >= HW_TOTAL) return;
    const float* src; uint32_t base;
    if      (fi < WQ_OFF) { src = oc; base = OC_OFF; }
    else if (fi < WK_OFF) { src = wq; base = WQ_OFF; }
    else if (fi < WV_OFF) { src = wk; base = WK_OFF; }
    else if (fi < WO_OFF) { src = wv; base = WV_OFF; }
    else if (fi < F1_OFF) { src = wo; base = WO_OFF; }
    else if (fi < F2_OFF) { src = f1; base = F1_OFF; }
    else                  { src = f2; base = F2_OFF; }
    float4 v = *(const float4*)&src[fi - base];
    if (fi < WQ_OFF) *(float4*)&oout[fi] = v;   // ocean passthrough (fp32)
    uint2 u = make_uint2(packh2(v.x, v.y), packh2(v.z, v.w));
    *(uint2*)&dst[fi] = u;
}

// ---------------- LayerNorm: fp32 in, fp16 out ------------------------------
__global__ void __launch_bounds__(256) ln_half(const float* __restrict__ in,
                                               __half* __restrict__ out,
                                               const float* __restrict__ gamma,
                                               const float* __restrict__ beta)
{
    int wid  = threadIdx.x >> 5;
    int lane = threadIdx.x & 31;
    int row  = blockIdx.x * 8 + wid;
    const float4* p = (const float4*)(in + (size_t)row * DIM);
    float4 v0 = p[lane*2], v1 = p[lane*2+1];

    float s = v0.x+v0.y+v0.z+v0.w + v1.x+v1.y+v1.z+v1.w;
    #pragma unroll
    for (int o = 16; o; o >>= 1) s += __shfl_xor_sync(0xffffffffu, s, o);
    float mu = s * (1.0f/DIM);

    float d0x=v0.x-mu,d0y=v0.y-mu,d0z=v0.z-mu,d0w=v0.w-mu;
    float d1x=v1.x-mu,d1y=v1.y-mu,d1z=v1.z-mu,d1w=v1.w-mu;
    float q = d0x*d0x+d0y*d0y+d0z*d0z+d0w*d0w + d1x*d1x+d1y*d1y+d1z*d1z+d1w*d1w;
    #pragma unroll
    for (int o = 16; o; o >>= 1) q += __shfl_xor_sync(0xffffffffu, q, o);
    float rstd = rsqrtf(q * (1.0f/DIM) + EPS);

    const float4* gp = (const float4*)gamma;
    const float4* bp = (const float4*)beta;
    float4 g0 = gp[lane*2], g1 = gp[lane*2+1];
    float4 b0 = bp[lane*2], b1 = bp[lane*2+1];

    uint4 u;
    u.x = packh2(d0x*rstd*g0.x + b0.x, d0y*rstd*g0.y + b0.y);
    u.y = packh2(d0z*rstd*g0.z + b0.z, d0w*rstd*g0.w + b0.w);
    u.z = packh2(d1x*rstd*g1.x + b1.x, d1y*rstd*g1.y + b1.y);
    u.w = packh2(d1z*rstd*g1.z + b1.z, d1w*rstd*g1.w + b1.w);
    *(uint4*)&out[(size_t)row*DIM + lane*8] = u;
}

// ---------------- fp16 GEMM NT: cp.async 4-stage, ldmatrix, 1 sync/iter -----
// C[M,N] = A[M,K] * B[N,K]^T. Tile 128xBN (BN=64 or 128), K-chunk 32 halves,
// 256 threads = 8 warps as 4(M) x 2(N); warp tile 32 x BN/2.
// EPI: 0 = *oscale -> half, 1 = +res -> float, 2 = gelu(.+bias) -> half,
//      3 = +bias+res -> float
#define GSTR 20                 // uint32 stride per row chunk (16 used + 4 pad)
#define NSTAGE 4
template<int EPI, int BN>
__global__ void __launch_bounds__(256) gemm_h(const __half* __restrict__ A,
                                              const __half* __restrict__ Bm,
                                              const float* __restrict__ bias,
                                              const float* __restrict__ res,
                                              void* __restrict__ Cout,
                                              int M, int N, int K, float oscale)
{
    constexpr int NI = BN/16;       // n8 tiles per warp
    constexpr int NJ = BN/32;       // n16 ldsm tiles per warp
    constexpr int GSM_A = NSTAGE*128*GSTR;

    extern __shared__ uint32_t smu[];
    uint32_t* sA = smu;
    uint32_t* sB = smu + GSM_A;
    const uint32_t sA_base = (uint32_t)__cvta_generic_to_shared(sA);
    const uint32_t sB_base = (uint32_t)__cvta_generic_to_shared(sB);

    const int tid  = threadIdx.x;
    const int m0   = blockIdx.y * 128;
    const int n0   = blockIdx.x * BN;
    const int lane = tid & 31;
    const int warp = tid >> 5;
    const int gr   = lane >> 2;
    const int gc   = lane & 3;
    const int wm   = warp >> 1;
    const int wn   = warp & 1;

    const int lrow = tid >> 2, lseg = tid & 3;   // fill coords

    // ldmatrix lane addressing
    const int la = lane & 15,                 sa = lane >> 4;        // A
    const int lb = (lane & 7) + ((lane >> 4) << 3), sb = (lane >> 3) & 1;  // B

    float c[2][NI][4];
    #pragma unroll
    for (int mi=0; mi<2; mi++)
        #pragma unroll
        for (int ni=0; ni<NI; ni++)
            #pragma unroll
            for (int i=0; i<4; i++) c[mi][ni][i] = 0.f;

    auto fill = [&](int stage, int k0) {
        cp16(sA_base + (((stage*128 + lrow)*GSTR + lseg*4) << 2),
             A + (size_t)(m0 + lrow)*K + k0 + lseg*8);
        cp16(sA_base + (((stage*128 + lrow + 64)*GSTR + lseg*4) << 2),
             A + (size_t)(m0 + lrow + 64)*K + k0 + lseg*8);
        cp16(sB_base + (((stage*BN + lrow)*GSTR + lseg*4) << 2),
             Bm + (size_t)(n0 + lrow)*K + k0 + lseg*8);
        if (BN == 128)
            cp16(sB_base + (((stage*BN + lrow + 64)*GSTR + lseg*4) << 2),
                 Bm + (size_t)(n0 + lrow + 64)*K + k0 + lseg*8);
    };

    auto compute = [&](int stage) {
        const uint32_t aBase = sA_base + (((stage*128 + wm*32)*GSTR) << 2);
        const uint32_t bBase = sB_base + (((stage*BN + wn*(BN/2))*GSTR) << 2);
        #pragma unroll
        for (int kc = 0; kc < 2; kc++) {
            const int kb = kc*8;
            uint32_t af[2][4], bf[NJ][4];
            #pragma unroll
            for (int mi = 0; mi < 2; mi++)
                ldsm4(af[mi], aBase + (((mi*16 + la)*GSTR + kb + sa*4) << 2));
            #pragma unroll
            for (int nj = 0; nj < NJ; nj++)
                ldsm4(bf[nj], bBase + (((nj*16 + lb)*GSTR + kb + sb*4) << 2));
            #pragma unroll
            for (int mi = 0; mi < 2; mi++)
                #pragma unroll
                for (int ni = 0; ni < NI; ni++)
                    mma_f16(c[mi][ni], af[mi],
                            bf[ni>>1][(ni&1)*2], bf[ni>>1][(ni&1)*2+1]);
        }
    };

    const int nIter = K >> 5;
    fill(0, 0);  cp_commit();
    fill(1, 32); cp_commit();
    fill(2, 64); cp_commit();
    for (int it = 0; it < nIter; it++) {
        cp_wait<2>();
        __syncthreads();
        if (it + 3 < nIter) fill((it+3) & 3, (it+3)*32);
        cp_commit();
        compute(it & 3);
    }

    // epilogue (fp32 accumulators)
    #pragma unroll
    for (int ni = 0; ni < NI; ni++) {
        const int col = n0 + wn*(BN/2) + ni*8 + 2*gc;
        float2 bi = make_float2(0.f, 0.f);
        if (EPI == 2 || EPI == 3) bi = *(const float2*)&bias[col];
        #pragma unroll
        for (int mi = 0; mi < 2; mi++) {
            const int row0 = m0 + wm*32 + mi*16 + gr;
            #pragma unroll
            for (int hh2 = 0; hh2 < 2; hh2++) {
                const int row = row0 + hh2*8;
                float2 v = make_float2(c[mi][ni][hh2*2], c[mi][ni][hh2*2+1]);
                if (EPI == 0) { v.x *= oscale; v.y *= oscale; }
                if (EPI == 2) {
                    v.x += bi.x; v.y += bi.y;
                    v.x = 0.5f*v.x*(1.0f + erff(v.x*0.7071067811865475f));
                    v.y = 0.5f*v.y*(1.0f + erff(v.y*0.7071067811865475f));
                }
                if (EPI == 3) { v.x += bi.x; v.y += bi.y; }
                if (EPI == 1 || EPI == 3) {
                    float2 r = *(const float2*)&res[(size_t)row*N + col];
                    v.x += r.x; v.y += r.y;
                }
                if (EPI == 0 || EPI == 2) {
                    ((uint32_t*)Cout)[((size_t)row*N + col) >> 1] = packh2(v.x, v.y);
                } else {
                    *(float2*)&((float*)Cout)[(size_t)row*N + col] = v;
                }
            }
        }
    }
}
#define GEMM_SMEM(BN) ((NSTAGE*128*GSTR + NSTAGE*(BN)*GSTR)*4)

// ---------------- Differential attention: fp16 + ldmatrix fragments --------
// 128 queries/block, 256 threads. KV fused layout: row stride 768,
// K at cols [0,512), V at cols [512,768).
// Q pre-scaled by SCALE*LOG2E so P = ex2(S) directly.
#define KH_STRIDE 36   // uint32 stride per key row (32 used + pad)
#define VT_STRIDE 36   // uint32 stride per hd row
#define KVS 768
__global__ void __launch_bounds__(256) attn_tc(const __half* __restrict__ Q,
                                               const __half* __restrict__ KV,
                                               const float* __restrict__ lq1,
                                               const float* __restrict__ lk1,
                                               const float* __restrict__ lq2,
                                               const float* __restrict__ lk2,
                                               __half* __restrict__ O)
{
    __shared__ uint32_t Kh[64*KH_STRIDE];  // 64 keys x 64 halves (both halves)
    __shared__ uint32_t Vt[32*VT_STRIDE];  // 32 hd x 64 keys (transposed)

    const int b    = blockIdx.z;
    const int h    = blockIdx.y;
    const int warp = threadIdx.x >> 5;
    const int lane = threadIdx.x & 31;
    const int gr   = lane >> 2;
    const int gc   = lane & 3;
    const int qw   = blockIdx.x * 128 + warp * 16;

    const uint32_t khB = (uint32_t)__cvta_generic_to_shared(Kh);
    const uint32_t vtB = (uint32_t)__cvta_generic_to_shared(Vt);
    const int lb = (lane & 7) + ((lane >> 4) << 3), sb = (lane >> 3) & 1;

    float d1 = 0.f, d2 = 0.f;
    #pragma unroll
    for (int i = 0; i < HD; i++) {
        d1 = fmaf(lq1[h*HD+i], lk1[h*HD+i], d1);
        d2 = fmaf(lq2[h*HD+i], lk2[h*HD+i], d2);
    }
    const float lam = expf(d1) - expf(d2) + LAMBDA_INIT;

    // Q fragments (pre-scaled). qh[half][kc][4]
    uint32_t qh[2][2][4];
    {
        const uint32_t* q0 = (const uint32_t*)(Q + ((size_t)(b*NN + qw + gr))*(2*DIM)) + h*32;
        const uint32_t* q8 = q0 + 8*(2*DIM/2);
        #pragma unroll
        for (int half = 0; half < 2; half++) {
            #pragma unroll
            for (int kc = 0; kc < 2; kc++) {
                int off = half*16 + kc*8 + gc;
                qh[half][kc][0] = q0[off];
                qh[half][kc][1] = q8[off];
                qh[half][kc][2] = q0[off+4];
                qh[half][kc][3] = q8[off+4];
            }
        }
    }

    float o[2][4][4];
    #pragma unroll
    for (int hf=0; hf<2; hf++)
        #pragma unroll
        for (int n=0; n<4; n++)
            #pragma unroll
            for (int i=0; i<4; i++) o[hf][n][i] = 0.f;
    float lsum[2][2] = {{0.f,0.f},{0.f,0.f}};

    const int t = threadIdx.x;
    for (int k0 = 0; k0 < NN; k0 += 64) {
        __syncthreads();
        // K tile: 64 keys x 64 halves = 512 x 16B chunks -> 2 per thread
        #pragma unroll
        for (int it = 0; it < 2; it++) {
            int i = t + it*256;
            int key = i >> 3, seg = i & 7;
            uint4 v = *(const uint4*)(KV + ((size_t)(b*NN + k0 + key))*KVS + h*HD2 + seg*8);
            *(uint4*)&Kh[key*KH_STRIDE + seg*4] = v;
        }
        // V tile: 64 keys x 32 halves -> 1 chunk per thread, transposed
        {
            int key = t >> 2, q = t & 3;
            uint4 v = *(const uint4*)(KV + ((size_t)(b*NN + k0 + key))*KVS + 512 + h*HD + q*8);
            __half* Vh = (__half*)Vt;
            uint32_t w[4] = {v.x, v.y, v.z, v.w};
            #pragma unroll
            for (int j = 0; j < 4; j++) {
                __half2 hv = *(__half2*)&w[j];
                Vh[(q*8 + j*2    )*(2*VT_STRIDE) + key] = __low2half(hv);
                Vh[(q*8 + j*2 + 1)*(2*VT_STRIDE) + key] = __high2half(hv);
            }
        }
        __syncthreads();

        uint32_t ph[2][4][4];
        #pragma unroll
        for (int half = 0; half < 2; half++) {
            float s[8][4];
            #pragma unroll
            for (int n=0;n<8;n++)
                #pragma unroll
                for (int i=0;i<4;i++) s[n][i] = 0.f;

            // S = Q_half @ K_half^T via ldmatrix B fragments
            #pragma unroll
            for (int kc = 0; kc < 2; kc++) {
                const int kb = half*16 + kc*8;
                uint32_t bf[4][4];
                #pragma unroll
                for (int nj = 0; nj < 4; nj++)
                    ldsm4(bf[nj], khB + (((nj*16 + lb)*KH_STRIDE + kb + sb*4) << 2));
                #pragma unroll
                for (int n = 0; n < 8; n++)
                    mma_f16(s[n], qh[half][kc],
                            bf[n>>1][(n&1)*2], bf[n>>1][(n&1)*2+1]);
            }
            #pragma unroll
            for (int n = 0; n < 8; n++) {
                float p0 = ex2f(s[n][0]);
                float p1 = ex2f(s[n][1]);
                float p2 = ex2f(s[n][2]);
                float p3 = ex2f(s[n][3]);
                lsum[half][0] += p0 + p1;
                lsum[half][1] += p2 + p3;
                int ks = n >> 1, hi = (n & 1) * 2;
                ph[half][ks][hi    ] = packh2(p0, p1);
                ph[half][ks][hi + 1] = packh2(p2, p3);
            }
        }

        // PV via ldmatrix V^T fragments (shared across both halves)
        #pragma unroll
        for (int ks = 0; ks < 4; ks++) {
            uint32_t vf[2][4];
            #pragma unroll
            for (int nj = 0; nj < 2; nj++)
                ldsm4(vf[nj], vtB + (((nj*16 + lb)*VT_STRIDE + ks*8 + sb*4) << 2));
            #pragma unroll
            for (int n = 0; n < 4; n++) {
                uint32_t b0 = vf[n>>1][(n&1)*2], b1 = vf[n>>1][(n&1)*2+1];
                mma_f16(o[0][n], ph[0][ks], b0, b1);
                mma_f16(o[1][n], ph[1][ks], b0, b1);
            }
        }
    }

    #pragma unroll
    for (int hf = 0; hf < 2; hf++) {
        #pragma unroll
        for (int r2 = 0; r2 < 2; r2++) {
            float v = lsum[hf][r2];
            v += __shfl_xor_sync(0xffffffffu, v, 1);
            v += __shfl_xor_sync(0xffffffffu, v, 2);
            lsum[hf][r2] = v;
        }
    }
    const float i1A = 1.f / lsum[0][0];
    const float i1B = 1.f / lsum[0][1];
    const float s2A = lam / lsum[1][0];
    const float s2B = lam / lsum[1][1];

    uint32_t* outA = (uint32_t*)(O + ((size_t)(b*NN + qw + gr    ))*DIM + h*HD);
    uint32_t* outB = (uint32_t*)(O + ((size_t)(b*NN + qw + gr + 8))*DIM + h*HD);
    #pragma unroll
    for (int n = 0; n < 4; n++) {
        outA[(n*8 + 2*gc) >> 1] = packh2(o[0][n][0]*i1A - o[1][n][0]*s2A,
                                         o[0][n][1]*i1A - o[1][n][1]*s2A);
        outB[(n*8 + 2*gc) >> 1] = packh2(o[0][n][2]*i1B - o[1][n][2]*s2B,
                                         o[0][n][3]*i1B - o[1][n][3]*s2B);
    }
}

// ---------------- launch ----------------------------------------------------
static void* symp(const void* sym) {
    void* p = nullptr;
    cudaGetSymbolAddress(&p, sym);
    return p;
}

extern "C" void kernel_launch(void* const* d_in, const int* in_sizes, int n_in,
                              void* d_out, int out_size)
{
    const float* drift = (const float*)d_in[0];
    const float* ocean = (const float*)d_in[1];
    const float* Wq    = (const float*)d_in[2];
    const float* Wk    = (const float*)d_in[3];
    const float* Wv    = (const float*)d_in[4];
    const float* Wo    = (const float*)d_in[5];
    const float* lq1   = (const float*)d_in[6];
    const float* lk1   = (const float*)d_in[7];
    const float* lq2   = (const float*)d_in[8];
    const float* lk2   = (const float*)d_in[9];
    const float* gamma = (const float*)d_in[10];
    const float* beta  = (const float*)d_in[11];
    const float* fc1w  = (const float*)d_in[12];
    const float* fc1b  = (const float*)d_in[13];
    const float* fc2w  = (const float*)d_in[14];
    const float* fc2b  = (const float*)d_in[15];
    float* out = (float*)d_out;

    __half* hw   = (__half*)symp(g_hw);
    __half* hx   = (__half*)symp(g_hx);
    __half* hQ   = (__half*)symp(g_hQ);
    __half* hKV  = (__half*)symp(g_hKV);
    __half* hatt = (__half*)symp(g_hatt);
    __half* hy   = (__half*)symp(g_hy);
    __half* hh   = (__half*)symp(g_hh);

    cudaFuncSetAttribute((const void*)gemm_h<0,64>,  cudaFuncAttributeMaxDynamicSharedMemorySize, GEMM_SMEM(64));
    cudaFuncSetAttribute((const void*)gemm_h<1,64>,  cudaFuncAttributeMaxDynamicSharedMemorySize, GEMM_SMEM(64));
    cudaFuncSetAttribute((const void*)gemm_h<2,128>, cudaFuncAttributeMaxDynamicSharedMemorySize, GEMM_SMEM(128));
    cudaFuncSetAttribute((const void*)gemm_h<3,64>,  cudaFuncAttributeMaxDynamicSharedMemorySize, GEMM_SMEM(64));

    // 0) convert ocean + weights to fp16; write ocean passthrough to out
    cvt_kernel<<<(HW_TOTAL/4 + 255)/256, 256>>>(ocean, Wq, Wk, Wv, Wo, fc1w, fc2w,
                                                hw, out + (size_t)ROWS*DIM);
    // 1) x = LN(drift) -> half
    ln_half<<<ROWS/8, 256>>>(drift, hx, gamma, beta);
    // 2) Q = (x @ Wq^T) * SCALE*LOG2E
    gemm_h<0,64><<<dim3(512/64, ROWS/128), 256, GEMM_SMEM(64)>>>(hx, hw+WQ_OFF, nullptr, nullptr, hQ, ROWS, 512, 256, SCALE*LOG2E);
    // 3) KV = ocean @ [Wk;Wv]^T   (fused, N=768)
    gemm_h<0,64><<<dim3(768/64, ROWS/128), 256, GEMM_SMEM(64)>>>(hw+OC_OFF, hw+WK_OFF, nullptr, nullptr, hKV, ROWS, 768, 256, 1.0f);
    // 4) differential attention
    attn_tc<<<dim3(NN/128, HH, BB), 256>>>(hQ, hKV, lq1, lk1, lq2, lk2, hatt);
    // 5) drift2 = drift + att @ Wo^T -> out (fp32)
    gemm_h<1,64><<<dim3(256/64, ROWS/128), 256, GEMM_SMEM(64)>>>(hatt, hw+WO_OFF, nullptr, drift, out, ROWS, 256, 256, 1.0f);
    // 6) y = LN(drift2) -> half
    ln_half<<<ROWS/8, 256>>>(out, hy, gamma, beta);
    // 7) h = gelu(y @ fc1^T + b1)
    gemm_h<2,128><<<dim3(1024/128, ROWS/128), 256, GEMM_SMEM(128)>>>(hy, hw+F1_OFF, fc1b, nullptr, hh, ROWS, 1024, 256, 1.0f);
    // 8) drift_out = drift2 + h @ fc2^T + b2 (in-place on out)
    gemm_h<3,64><<<dim3(256/64, ROWS/128), 256, GEMM_SMEM(64)>>>(hh, hw+F2_OFF, fc2b, out, out, ROWS, 256, 1024, 1.0f);
}

// round 12
// speedup vs baseline: 6.7935x; 1.0226x over previous
#include <cuda_runtime.h>
#include <cuda_fp16.h>
#include <math.h>
#include <stdint.h>

// Problem constants
#define BB    2
#define NN    2048
#define DIM   256
#define HH    8
#define HD    32
#define HD2   64
#define ROWS  (BB*NN)          // 4096
#define SCALE 0.17677669529663689f  // 32^-0.5
#define LOG2E 1.4426950408889634f
#define LAMBDA_INIT 0.1f
#define EPS   1e-5f

// ---------------- half weight/activation pool (static, no allocation) ------
#define OC_OFF   0u
#define WQ_OFF   1048576u
#define WK_OFF   1179648u      // Wk (512x256) then Wv (256x256) contiguous
#define WV_OFF   1310720u
#define WO_OFF   1376256u
#define F1_OFF   1441792u
#define F2_OFF   1703936u
#define HW_TOTAL 1966080u
__device__ __half g_hw [HW_TOTAL];     // ocean + all weights (fp16)
__device__ __half g_hx [ROWS*DIM];     // LN1 out
__device__ __half g_hQ [ROWS*2*DIM];   // Q (pre-scaled by SCALE*LOG2E)
__device__ __half g_hKV[ROWS*768];     // fused K(512) | V(256) per row
__device__ __half g_hatt[ROWS*DIM];
__device__ __half g_hy [ROWS*DIM];     // LN2 out
__device__ __half g_hh [ROWS*4*DIM];   // MLP hidden

// ---------------- helpers ---------------------------------------------------
__device__ __forceinline__ void mma_f16(float* d, const uint32_t* a,
                                        uint32_t b0, uint32_t b1) {
    asm volatile("mma.sync.aligned.m16n8k16.row.col.f32.f16.f16.f32 "
                 "{%0,%1,%2,%3},{%4,%5,%6,%7},{%8,%9},{%0,%1,%2,%3};"
                 : "+f"(d[0]), "+f"(d[1]), "+f"(d[2]), "+f"(d[3])
                 : "r"(a[0]), "r"(a[1]), "r"(a[2]), "r"(a[3]),
                   "r"(b0), "r"(b1));
}
__device__ __forceinline__ void ldsm4(uint32_t* r, uint32_t addr) {
    asm volatile("ldmatrix.sync.aligned.m8n8.x4.shared.b16 {%0,%1,%2,%3}, [%4];"
                 : "=r"(r[0]), "=r"(r[1]), "=r"(r[2]), "=r"(r[3]) : "r"(addr));
}
__device__ __forceinline__ uint32_t packh2(float x, float y) {
    __half2 h = __floats2half2_rn(x, y);
    return *reinterpret_cast<uint32_t*>(&h);
}
__device__ __forceinline__ float ex2f(float x) {
    float y;
    asm("ex2.approx.f32 %0, %1;" : "=f"(y) : "f"(x));
    return y;
}
__device__ __forceinline__ void cp16(uint32_t saddr, const void* g) {
    asm volatile("cp.async.cg.shared.global [%0], [%1], 16;\n" :: "r"(saddr), "l"(g));
}
__device__ __forceinline__ void cp_commit() { asm volatile("cp.async.commit_group;\n"); }
template<int N> __device__ __forceinline__ void cp_wait() {
    asm volatile("cp.async.wait_group %0;\n" :: "n"(N));
}

// ---------------- fused LN1 + fp32->fp16 conversion -------------------------
// blocks [0,512): ln rows; blocks [512, 512+1920): weight/ocean conversion
__global__ void __launch_bounds__(256) ln_cvt_kernel(
    const float* __restrict__ drift, __half* __restrict__ hx,
    const float* __restrict__ gamma, const float* __restrict__ beta,
    const float* __restrict__ oc,
    const float* __restrict__ wq, const float* __restrict__ wk,
    const float* __restrict__ wv, const float* __restrict__ wo,
    const float* __restrict__ f1, const float* __restrict__ f2,
    __half* __restrict__ dst, float* __restrict__ oout)
{
    if (blockIdx.x < 512) {
        int wid  = threadIdx.x >> 5;
        int lane = threadIdx.x & 31;
        int row  = blockIdx.x * 8 + wid;
        const float4* p = (const float4*)(drift + (size_t)row * DIM);
        float4 v0 = p[lane*2], v1 = p[lane*2+1];

        float s = v0.x+v0.y+v0.z+v0.w + v1.x+v1.y+v1.z+v1.w;
        #pragma unroll
        for (int o = 16; o; o >>= 1) s += __shfl_xor_sync(0xffffffffu, s, o);
        float mu = s * (1.0f/DIM);

        float d0x=v0.x-mu,d0y=v0.y-mu,d0z=v0.z-mu,d0w=v0.w-mu;
        float d1x=v1.x-mu,d1y=v1.y-mu,d1z=v1.z-mu,d1w=v1.w-mu;
        float q = d0x*d0x+d0y*d0y+d0z*d0z+d0w*d0w + d1x*d1x+d1y*d1y+d1z*d1z+d1w*d1w;
        #pragma unroll
        for (int o = 16; o; o >>= 1) q += __shfl_xor_sync(0xffffffffu, q, o);
        float rstd = rsqrtf(q * (1.0f/DIM) + EPS);

        const float4* gp = (const float4*)gamma;
        const float4* bp = (const float4*)beta;
        float4 g0 = gp[lane*2], g1 = gp[lane*2+1];
        float4 b0 = bp[lane*2], b1 = bp[lane*2+1];

        uint4 u;
        u.x = packh2(d0x*rstd*g0.x + b0.x, d0y*rstd*g0.y + b0.y);
        u.y = packh2(d0z*rstd*g0.z + b0.z, d0w*rstd*g0.w + b0.w);
        u.z = packh2(d1x*rstd*g1.x + b1.x, d1y*rstd*g1.y + b1.y);
        u.w = packh2(d1z*rstd*g1.z + b1.z, d1w*rstd*g1.w + b1.w);
        *(uint4*)&hx[(size_t)row*DIM + lane*8] = u;
    } else {
        uint32_t fi = ((uint32_t)(blockIdx.x - 512)*256u + threadIdx.x)*4u;
        if (fi >= HW_TOTAL) return;
        const float* src; uint32_t base;
        if      (fi < WQ_OFF) { src = oc; base = OC_OFF; }
        else if (fi < WK_OFF) { src = wq; base = WQ_OFF; }
        else if (fi < WV_OFF) { src = wk; base = WK_OFF; }
        else if (fi < WO_OFF) { src = wv; base = WV_OFF; }
        else if (fi < F1_OFF) { src = wo; base = WO_OFF; }
        else if (fi < F2_OFF) { src = f1; base = F1_OFF; }
        else                  { src = f2; base = F2_OFF; }
        float4 v = *(const float4*)&src[fi - base];
        if (fi < WQ_OFF) *(float4*)&oout[fi] = v;   // ocean passthrough (fp32)
        uint2 u = make_uint2(packh2(v.x, v.y), packh2(v.z, v.w));
        *(uint2*)&dst[fi] = u;
    }
}

// ---------------- LayerNorm standalone (for ln2) ----------------------------
__global__ void __launch_bounds__(256) ln_half(const float* __restrict__ in,
                                               __half* __restrict__ out,
                                               const float* __restrict__ gamma,
                                               const float* __restrict__ beta)
{
    int wid  = threadIdx.x >> 5;
    int lane = threadIdx.x & 31;
    int row  = blockIdx.x * 8 + wid;
    const float4* p = (const float4*)(in + (size_t)row * DIM);
    float4 v0 = p[lane*2], v1 = p[lane*2+1];

    float s = v0.x+v0.y+v0.z+v0.w + v1.x+v1.y+v1.z+v1.w;
    #pragma unroll
    for (int o = 16; o; o >>= 1) s += __shfl_xor_sync(0xffffffffu, s, o);
    float mu = s * (1.0f/DIM);

    float d0x=v0.x-mu,d0y=v0.y-mu,d0z=v0.z-mu,d0w=v0.w-mu;
    float d1x=v1.x-mu,d1y=v1.y-mu,d1z=v1.z-mu,d1w=v1.w-mu;
    float q = d0x*d0x+d0y*d0y+d0z*d0z+d0w*d0w + d1x*d1x+d1y*d1y+d1z*d1z+d1w*d1w;
    #pragma unroll
    for (int o = 16; o; o >>= 1) q += __shfl_xor_sync(0xffffffffu, q, o);
    float rstd = rsqrtf(q * (1.0f/DIM) + EPS);

    const float4* gp = (const float4*)gamma;
    const float4* bp = (const float4*)beta;
    float4 g0 = gp[lane*2], g1 = gp[lane*2+1];
    float4 b0 = bp[lane*2], b1 = bp[lane*2+1];

    uint4 u;
    u.x = packh2(d0x*rstd*g0.x + b0.x, d0y*rstd*g0.y + b0.y);
    u.y = packh2(d0z*rstd*g0.z + b0.z, d0w*rstd*g0.w + b0.w);
    u.z = packh2(d1x*rstd*g1.x + b1.x, d1y*rstd*g1.y + b1.y);
    u.w = packh2(d1z*rstd*g1.z + b1.z, d1w*rstd*g1.w + b1.w);
    *(uint4*)&out[(size_t)row*DIM + lane*8] = u;
}

// ---------------- fp16 GEMM core: cp.async 3-stage, ldmatrix ----------------
// C[M,N] = A[M,K] * B[N,K]^T. Tile 128xBN, K-chunk 32 halves, 256 threads.
// EPI: 0 = *oscale -> half, 1 = +res -> float, 2 = gelu(.+bias) -> half,
//      3 = +bias+res -> float
#define GSTR 20                 // uint32 stride per row chunk (16 used + 4 pad)
#define NSTAGE 3
#define GEMM_SMEM(BN) ((NSTAGE*128*GSTR + NSTAGE*(BN)*GSTR)*4)
template<int EPI, int BN>
__device__ __forceinline__ void gemm_core(const __half* __restrict__ A,
                                          const __half* __restrict__ Bm,
                                          const float* __restrict__ bias,
                                          const float* __restrict__ res,
                                          void* __restrict__ Cout,
                                          int N, int K, float oscale,
                                          int m0, int n0)
{
    constexpr int NI = BN/16;
    constexpr int NJ = BN/32;
    constexpr int GSM_A = NSTAGE*128*GSTR;

    extern __shared__ uint32_t smu[];
    uint32_t* sA = smu;
    uint32_t* sB = smu + GSM_A;
    const uint32_t sA_base = (uint32_t)__cvta_generic_to_shared(sA);
    const uint32_t sB_base = (uint32_t)__cvta_generic_to_shared(sB);

    const int tid  = threadIdx.x;
    const int lane = tid & 31;
    const int warp = tid >> 5;
    const int gr   = lane >> 2;
    const int gc   = lane & 3;
    const int wm   = warp >> 1;
    const int wn   = warp & 1;

    const int lrow = tid >> 2, lseg = tid & 3;

    const int la = lane & 15,                 sa = lane >> 4;
    const int lb = (lane & 7) + ((lane >> 4) << 3), sb = (lane >> 3) & 1;

    float c[2][NI][4];
    #pragma unroll
    for (int mi=0; mi<2; mi++)
        #pragma unroll
        for (int ni=0; ni<NI; ni++)
            #pragma unroll
            for (int i=0; i<4; i++) c[mi][ni][i] = 0.f;

    auto fill = [&](int stage, int k0) {
        cp16(sA_base + (((stage*128 + lrow)*GSTR + lseg*4) << 2),
             A + (size_t)(m0 + lrow)*K + k0 + lseg*8);
        cp16(sA_base + (((stage*128 + lrow + 64)*GSTR + lseg*4) << 2),
             A + (size_t)(m0 + lrow + 64)*K + k0 + lseg*8);
        cp16(sB_base + (((stage*BN + lrow)*GSTR + lseg*4) << 2),
             Bm + (size_t)(n0 + lrow)*K + k0 + lseg*8);
        if (BN == 128)
            cp16(sB_base + (((stage*BN + lrow + 64)*GSTR + lseg*4) << 2),
                 Bm + (size_t)(n0 + lrow + 64)*K + k0 + lseg*8);
    };

    auto compute = [&](int stage) {
        const uint32_t aBase = sA_base + (((stage*128 + wm*32)*GSTR) << 2);
        const uint32_t bBase = sB_base + (((stage*BN + wn*(BN/2))*GSTR) << 2);
        #pragma unroll
        for (int kc = 0; kc < 2; kc++) {
            const int kb = kc*8;
            uint32_t af[2][4], bf[NJ][4];
            #pragma unroll
            for (int mi = 0; mi < 2; mi++)
                ldsm4(af[mi], aBase + (((mi*16 + la)*GSTR + kb + sa*4) << 2));
            #pragma unroll
            for (int nj = 0; nj < NJ; nj++)
                ldsm4(bf[nj], bBase + (((nj*16 + lb)*GSTR + kb + sb*4) << 2));
            #pragma unroll
            for (int mi = 0; mi < 2; mi++)
                #pragma unroll
                for (int ni = 0; ni < NI; ni++)
                    mma_f16(c[mi][ni], af[mi],
                            bf[ni>>1][(ni&1)*2], bf[ni>>1][(ni&1)*2+1]);
        }
    };

    const int nIter = K >> 5;
    fill(0, 0);  cp_commit();
    fill(1, 32); cp_commit();
    for (int it = 0; it < nIter; it++) {
        cp_wait<1>();
        __syncthreads();
        if (it + 2 < nIter) fill((it+2) % 3, (it+2)*32);
        cp_commit();
        compute(it % 3);
    }

    #pragma unroll
    for (int ni = 0; ni < NI; ni++) {
        const int col = n0 + wn*(BN/2) + ni*8 + 2*gc;
        float2 bi = make_float2(0.f, 0.f);
        if (EPI == 2 || EPI == 3) bi = *(const float2*)&bias[col];
        #pragma unroll
        for (int mi = 0; mi < 2; mi++) {
            const int row0 = m0 + wm*32 + mi*16 + gr;
            #pragma unroll
            for (int hh2 = 0; hh2 < 2; hh2++) {
                const int row = row0 + hh2*8;
                float2 v = make_float2(c[mi][ni][hh2*2], c[mi][ni][hh2*2+1]);
                if (EPI == 0) { v.x *= oscale; v.y *= oscale; }
                if (EPI == 2) {
                    v.x += bi.x; v.y += bi.y;
                    v.x = 0.5f*v.x*(1.0f + erff(v.x*0.7071067811865475f));
                    v.y = 0.5f*v.y*(1.0f + erff(v.y*0.7071067811865475f));
                }
                if (EPI == 3) { v.x += bi.x; v.y += bi.y; }
                if (EPI == 1 || EPI == 3) {
                    float2 r = *(const float2*)&res[(size_t)row*N + col];
                    v.x += r.x; v.y += r.y;
                }
                if (EPI == 0 || EPI == 2) {
                    ((uint32_t*)Cout)[((size_t)row*N + col) >> 1] = packh2(v.x, v.y);
                } else {
                    *(float2*)&((float*)Cout)[(size_t)row*N + col] = v;
                }
            }
        }
    }
}

template<int EPI, int BN>
__global__ void __launch_bounds__(256) gemm_h(const __half* __restrict__ A,
                                              const __half* __restrict__ Bm,
                                              const float* __restrict__ bias,
                                              const float* __restrict__ res,
                                              void* __restrict__ Cout,
                                              int N, int K, float oscale)
{
    gemm_core<EPI,BN>(A, Bm, bias, res, Cout, N, K, oscale,
                      blockIdx.y*128, blockIdx.x*BN);
}

// fused Q + KV projection: blocks x<8 -> Q (N=512), x>=8 -> KV (N=768)
__global__ void __launch_bounds__(256) gemm_qkv(const __half* __restrict__ x,
                                                const __half* __restrict__ wq,
                                                __half* __restrict__ Qout,
                                                const __half* __restrict__ oc,
                                                const __half* __restrict__ wkv,
                                                __half* __restrict__ KVout)
{
    if (blockIdx.x < 8)
        gemm_core<0,64>(x, wq, nullptr, nullptr, Qout, 512, 256, SCALE*LOG2E,
                        blockIdx.y*128, blockIdx.x*64);
    else
        gemm_core<0,64>(oc, wkv, nullptr, nullptr, KVout, 768, 256, 1.0f,
                        blockIdx.y*128, (blockIdx.x-8)*64);
}

// ---------------- Differential attention: fp16 + ldmatrix fragments --------
#define KH_STRIDE 36
#define VT_STRIDE 36
#define KVS 768
__global__ void __launch_bounds__(256) attn_tc(const __half* __restrict__ Q,
                                               const __half* __restrict__ KV,
                                               const float* __restrict__ lq1,
                                               const float* __restrict__ lk1,
                                               const float* __restrict__ lq2,
                                               const float* __restrict__ lk2,
                                               __half* __restrict__ O)
{
    __shared__ uint32_t Kh[64*KH_STRIDE];
    __shared__ uint32_t Vt[32*VT_STRIDE];

    const int b    = blockIdx.z;
    const int h    = blockIdx.y;
    const int warp = threadIdx.x >> 5;
    const int lane = threadIdx.x & 31;
    const int gr   = lane >> 2;
    const int gc   = lane & 3;
    const int qw   = blockIdx.x * 128 + warp * 16;

    const uint32_t khB = (uint32_t)__cvta_generic_to_shared(Kh);
    const uint32_t vtB = (uint32_t)__cvta_generic_to_shared(Vt);
    const int lb = (lane & 7) + ((lane >> 4) << 3), sb = (lane >> 3) & 1;

    float d1 = 0.f, d2 = 0.f;
    #pragma unroll
    for (int i = 0; i < HD; i++) {
        d1 = fmaf(lq1[h*HD+i], lk1[h*HD+i], d1);
        d2 = fmaf(lq2[h*HD+i], lk2[h*HD+i], d2);
    }
    const float lam = expf(d1) - expf(d2) + LAMBDA_INIT;

    uint32_t qh[2][2][4];
    {
        const uint32_t* q0 = (const uint32_t*)(Q + ((size_t)(b*NN + qw + gr))*(2*DIM)) + h*32;
        const uint32_t* q8 = q0 + 8*(2*DIM/2);
        #pragma unroll
        for (int half = 0; half < 2; half++) {
            #pragma unroll
            for (int kc = 0; kc < 2; kc++) {
                int off = half*16 + kc*8 + gc;
                qh[half][kc][0] = q0[off];
                qh[half][kc][1] = q8[off];
                qh[half][kc][2] = q0[off+4];
                qh[half][kc][3] = q8[off+4];
            }
        }
    }

    float o[2][4][4];
    #pragma unroll
    for (int hf=0; hf<2; hf++)
        #pragma unroll
        for (int n=0; n<4; n++)
            #pragma unroll
            for (int i=0; i<4; i++) o[hf][n][i] = 0.f;
    float lsum[2][2] = {{0.f,0.f},{0.f,0.f}};

    const int t = threadIdx.x;
    for (int k0 = 0; k0 < NN; k0 += 64) {
        __syncthreads();
        #pragma unroll
        for (int it = 0; it < 2; it++) {
            int i = t + it*256;
            int key = i >> 3, seg = i & 7;
            uint4 v = *(const uint4*)(KV + ((size_t)(b*NN + k0 + key))*KVS + h*HD2 + seg*8);
            *(uint4*)&Kh[key*KH_STRIDE + seg*4] = v;
        }
        {
            int key = t >> 2, q = t & 3;
            uint4 v = *(const uint4*)(KV + ((size_t)(b*NN + k0 + key))*KVS + 512 + h*HD + q*8);
            __half* Vh = (__half*)Vt;
            uint32_t w[4] = {v.x, v.y, v.z, v.w};
            #pragma unroll
            for (int j = 0; j < 4; j++) {
                __half2 hv = *(__half2*)&w[j];
                Vh[(q*8 + j*2    )*(2*VT_STRIDE) + key] = __low2half(hv);
                Vh[(q*8 + j*2 + 1)*(2*VT_STRIDE) + key] = __high2half(hv);
            }
        }
        __syncthreads();

        uint32_t ph[2][4][4];
        #pragma unroll
        for (int half = 0; half < 2; half++) {
            float s[8][4];
            #pragma unroll
            for (int n=0;n<8;n++)
                #pragma unroll
                for (int i=0;i<4;i++) s[n][i] = 0.f;

            #pragma unroll
            for (int kc = 0; kc < 2; kc++) {
                const int kb = half*16 + kc*8;
                uint32_t bf[4][4];
                #pragma unroll
                for (int nj = 0; nj < 4; nj++)
                    ldsm4(bf[nj], khB + (((nj*16 + lb)*KH_STRIDE + kb + sb*4) << 2));
                #pragma unroll
                for (int n = 0; n < 8; n++)
                    mma_f16(s[n], qh[half][kc],
                            bf[n>>1][(n&1)*2], bf[n>>1][(n&1)*2+1]);
            }
            #pragma unroll
            for (int n = 0; n < 8; n++) {
                float p0 = ex2f(s[n][0]);
                float p1 = ex2f(s[n][1]);
                float p2 = ex2f(s[n][2]);
                float p3 = ex2f(s[n][3]);
                lsum[half][0] += p0 + p1;
                lsum[half][1] += p2 + p3;
                int ks = n >> 1, hi = (n & 1) * 2;
                ph[half][ks][hi    ] = packh2(p0, p1);
                ph[half][ks][hi + 1] = packh2(p2, p3);
            }
        }

        #pragma unroll
        for (int ks = 0; ks < 4; ks++) {
            uint32_t vf[2][4];
            #pragma unroll
            for (int nj = 0; nj < 2; nj++)
                ldsm4(vf[nj], vtB + (((nj*16 + lb)*VT_STRIDE + ks*8 + sb*4) << 2));
            #pragma unroll
            for (int n = 0; n < 4; n++) {
                uint32_t b0 = vf[n>>1][(n&1)*2], b1 = vf[n>>1][(n&1)*2+1];
                mma_f16(o[0][n], ph[0][ks], b0, b1);
                mma_f16(o[1][n], ph[1][ks], b0, b1);
            }
        }
    }

    #pragma unroll
    for (int hf = 0; hf < 2; hf++) {
        #pragma unroll
        for (int r2 = 0; r2 < 2; r2++) {
            float v = lsum[hf][r2];
            v += __shfl_xor_sync(0xffffffffu, v, 1);
            v += __shfl_xor_sync(0xffffffffu, v, 2);
            lsum[hf][r2] = v;
        }
    }
    const float i1A = 1.f / lsum[0][0];
    const float i1B = 1.f / lsum[0][1];
    const float s2A = lam / lsum[1][0];
    const float s2B = lam / lsum[1][1];

    uint32_t* outA = (uint32_t*)(O + ((size_t)(b*NN + qw + gr    ))*DIM + h*HD);
    uint32_t* outB = (uint32_t*)(O + ((size_t)(b*NN + qw + gr + 8))*DIM + h*HD);
    #pragma unroll
    for (int n = 0; n < 4; n++) {
        outA[(n*8 + 2*gc) >> 1] = packh2(o[0][n][0]*i1A - o[1][n][0]*s2A,
                                         o[0][n][1]*i1A - o[1][n][1]*s2A);
        outB[(n*8 + 2*gc) >> 1] = packh2(o[0][n][2]*i1B - o[1][n][2]*s2B,
                                         o[0][n][3]*i1B - o[1][n][3]*s2B);
    }
}

// ---------------- launch ----------------------------------------------------
static void* symp(const void* sym) {
    void* p = nullptr;
    cudaGetSymbolAddress(&p, sym);
    return p;
}

extern "C" void kernel_launch(void* const* d_in, const int* in_sizes, int n_in,
                              void* d_out, int out_size)
{
    const float* drift = (const float*)d_in[0];
    const float* ocean = (const float*)d_in[1];
    const float* Wq    = (const float*)d_in[2];
    const float* Wk    = (const float*)d_in[3];
    const float* Wv    = (const float*)d_in[4];
    const float* Wo    = (const float*)d_in[5];
    const float* lq1   = (const float*)d_in[6];
    const float* lk1   = (const float*)d_in[7];
    const float* lq2   = (const float*)d_in[8];
    const float* lk2   = (const float*)d_in[9];
    const float* gamma = (const float*)d_in[10];
    const float* beta  = (const float*)d_in[11];
    const float* fc1w  = (const float*)d_in[12];
    const float* fc1b  = (const float*)d_in[13];
    const float* fc2w  = (const float*)d_in[14];
    const float* fc2b  = (const float*)d_in[15];
    float* out = (float*)d_out;

    __half* hw   = (__half*)symp(g_hw);
    __half* hx   = (__half*)symp(g_hx);
    __half* hQ   = (__half*)symp(g_hQ);
    __half* hKV  = (__half*)symp(g_hKV);
    __half* hatt = (__half*)symp(g_hatt);
    __half* hy   = (__half*)symp(g_hy);
    __half* hh   = (__half*)symp(g_hh);

    cudaFuncSetAttribute((const void*)gemm_qkv,      cudaFuncAttributeMaxDynamicSharedMemorySize, GEMM_SMEM(64));
    cudaFuncSetAttribute((const void*)gemm_h<1,64>,  cudaFuncAttributeMaxDynamicSharedMemorySize, GEMM_SMEM(64));
    cudaFuncSetAttribute((const void*)gemm_h<2,128>, cudaFuncAttributeMaxDynamicSharedMemorySize, GEMM_SMEM(128));
    cudaFuncSetAttribute((const void*)gemm_h<3,64>,  cudaFuncAttributeMaxDynamicSharedMemorySize, GEMM_SMEM(64));

    // 0) fused: LN1 + weight/ocean conversion (+ ocean passthrough)
    ln_cvt_kernel<<<512 + (HW_TOTAL/4 + 255)/256, 256>>>(
        drift, hx, gamma, beta,
        ocean, Wq, Wk, Wv, Wo, fc1w, fc2w, hw, out + (size_t)ROWS*DIM);
    // 1) fused Q + KV projections (one launch)
    gemm_qkv<<<dim3(20, ROWS/128), 256, GEMM_SMEM(64)>>>(hx, hw+WQ_OFF, hQ,
                                                         hw+OC_OFF, hw+WK_OFF, hKV);
    // 2) differential attention
    attn_tc<<<dim3(NN/128, HH, BB), 256>>>(hQ, hKV, lq1, lk1, lq2, lk2, hatt);
    // 3) drift2 = drift + att @ Wo^T -> out (fp32)
    gemm_h<1,64><<<dim3(256/64, ROWS/128), 256, GEMM_SMEM(64)>>>(hatt, hw+WO_OFF, nullptr, drift, out, 256, 256, 1.0f);
    // 4) y = LN(drift2) -> half
    ln_half<<<ROWS/8, 256>>>(out, hy, gamma, beta);
    // 5) h = gelu(y @ fc1^T + b1)
    gemm_h<2,128><<<dim3(1024/128, ROWS/128), 256, GEMM_SMEM(128)>>>(hy, hw+F1_OFF, fc1b, nullptr, hh, 1024, 256, 1.0f);
    // 6) drift_out = drift2 + h @ fc2^T + b2 (in-place on out)
    gemm_h<3,64><<<dim3(256/64, ROWS/128), 256, GEMM_SMEM(64)>>>(hh, hw+F2_OFF, fc2b, out, out, 256, 1024, 1.0f);
}